// round 13
// baseline (speedup 1.0000x reference)
#include <cuda_runtime.h>
#include <cuda_bf16.h>
#include <math.h>
#include <stdint.h>

// Problem dims
#define BB 8
#define SS 128
#define EE 512
#define DD 1024
#define HH 16
#define LL 4
#define VV 32000
#define DHH 64
#define FF_ 4096
#define TT (SS*BB)
#define TE (EE*BB)
#define NTILE (VV/128)
#define SCALE_ 0.125f
#define NEG_ (-1e30f)

typedef __nv_bfloat16 bf16;

// ---------------- scratch ----------------
__device__ float g_r[SS*DD];
__device__ float g_core[TT*DD];
__device__ float g_x[TT*DD];
__device__ float g_y[TT*DD];
__device__ float g_tmpk[4*TT*DD];
__device__ float g_enct[TE*DD];
__device__ float g_IL[TT*EE];
__device__ float g_pm[TT*256];
__device__ float g_ps[TT*256];
__device__ float g_tgtlog[TT];
__device__ float g_rmax[TT];
__device__ float g_rsum[TT];
__device__ float g_msig[TT];
__device__ float g_lossacc[2];

// bf16 activations
__device__ bf16 b_core[TT*DD];
__device__ bf16 b_r[SS*DD];
__device__ bf16 b_rkall[SS*LL*DD];
__device__ bf16 b_x[TT*DD];
__device__ bf16 b_y[TT*DD];
__device__ bf16 b_vec[TT*DD];
__device__ bf16 b_enct[TE*DD];
__device__ bf16 b_h[TT*FF_];
__device__ bf16 b_outb[TT*DD];
__device__ bf16 b_copyhb[TT*DD];
__device__ bf16 b_heads[TT*3*DD];
__device__ bf16 b_kvall[(size_t)TE*LL*2*DD];
__device__ bf16 b_q2[TT*DD];

// bf16 weights
__device__ bf16 w_qkv[LL*3*DD*DD];
__device__ bf16 w_r[LL*DD*DD];
__device__ bf16 w_o[LL*DD*DD];
__device__ bf16 w_kv[LL*2*DD*DD];
__device__ bf16 w_q[LL*DD*DD];
__device__ bf16 w_io[LL*DD*DD];
__device__ bf16 w_f1[LL*FF_*DD];
__device__ bf16 w_f2[LL*DD*FF_];
__device__ bf16 w_emb[(size_t)VV*DD];
__device__ bf16 w_out[DD*DD];
__device__ bf16 w_copy[DD*DD];

__device__ __forceinline__ uint32_t smem_u32(const void* p)
{
    return (uint32_t)__cvta_generic_to_shared(p);
}

// FFMA-only exp (no MUFU)
__device__ __forceinline__ float fexp(float x)
{
    x = fmaxf(x, -87.0f);
    float y = x * 1.4426950408889634f;
    float z = y + 12582912.0f;
    int   ki = __float_as_int(z) - 0x4B400000;
    float kf = z - 12582912.0f;
    float f = y - kf;
    float p = 0.00133336f;
    p = fmaf(p, f, 0.00961813f);
    p = fmaf(p, f, 0.05550411f);
    p = fmaf(p, f, 0.24022651f);
    p = fmaf(p, f, 0.69314718f);
    p = fmaf(p, f, 1.0f);
    return p * __int_as_float((ki + 127) << 23);
}

// ---------------- f32 -> bf16 conversion ----------------
__global__ void cvt_bf16(const float* __restrict__ src, bf16* __restrict__ dst, int n)
{
    int i = (blockIdx.x * 256 + threadIdx.x) * 4;
    if (i >= n) return;
    float4 v = *reinterpret_cast<const float4*>(src + i);
    uint32_t lo = ((uint32_t)__bfloat16_as_ushort(__float2bfloat16_rn(v.y)) << 16)
                | (uint32_t)__bfloat16_as_ushort(__float2bfloat16_rn(v.x));
    uint32_t hi = ((uint32_t)__bfloat16_as_ushort(__float2bfloat16_rn(v.w)) << 16)
                | (uint32_t)__bfloat16_as_ushort(__float2bfloat16_rn(v.z));
    *reinterpret_cast<uint2*>(dst + i) = make_uint2(lo, hi);
}

// 4-stage cp.async pipeline, 128x128 block
#define SMEMSZ (4*2*128*40*2)

__global__ __launch_bounds__(256, 2)
void sgemm_bf(const bf16* __restrict__ A, const bf16* __restrict__ Bw,
              float* __restrict__ Cf, bf16* __restrict__ Cb,
              const float* __restrict__ bias,
              int K, int lda, int ldb, int ldc, int act, int ksplit,
              long long partStride,
              long long aBS, long long bBS, long long cBS)
{
    extern __shared__ bf16 ds[];
    bf16* AsB = ds;                 // [4][128][40]
    bf16* BsB = ds + 4*128*40;

    int tid = threadIdx.x;
    int warp = tid >> 5, lane = tid & 31;
    int warp_m = warp >> 1;
    int warp_n = warp & 1;
    int rowA0 = blockIdx.y * 128;
    int colB0 = blockIdx.x * 128;

    long long zb = (ksplit == 1) ? (long long)blockIdx.z : 0;
    const bf16* Az = A + zb * aBS;
    const bf16* Bz = Bw + zb * bBS;

    int Kloc = K / ksplit;
    int kgbase = (ksplit > 1) ? blockIdx.z * Kloc : 0;

    int ldrow = tid >> 1;
    int ldkoff = (tid & 1) * 16;

    float c[2][8][4];
#pragma unroll
    for (int mi = 0; mi < 2; mi++)
#pragma unroll
        for (int ni = 0; ni < 8; ni++)
#pragma unroll
            for (int r = 0; r < 4; r++) c[mi][ni][r] = 0.f;

    const bf16* Agp = &Az[(size_t)(rowA0 + ldrow) * lda + kgbase + ldkoff];
    const bf16* Bgp = &Bz[(size_t)(colB0 + ldrow) * ldb + kgbase + ldkoff];

    int nk = Kloc >> 5;
    // prologue: stages 0..2
#pragma unroll
    for (int s = 0; s < 3; s++) {
        bf16* as = AsB + s * (128*40);
        bf16* bs = BsB + s * (128*40);
        uint32_t sa = smem_u32(as + ldrow * 40 + ldkoff);
        uint32_t sb = smem_u32(bs + ldrow * 40 + ldkoff);
        const bf16* ag = Agp + s * 32;
        const bf16* bg = Bgp + s * 32;
        asm volatile("cp.async.ca.shared.global [%0], [%1], 16;\n"
                     "cp.async.ca.shared.global [%2], [%3], 16;\n"
                     "cp.async.ca.shared.global [%4], [%5], 16;\n"
                     "cp.async.ca.shared.global [%6], [%7], 16;\n"
                     :: "r"(sa), "l"(ag), "r"(sa + 16), "l"(ag + 8),
                        "r"(sb), "l"(bg), "r"(sb + 16), "l"(bg + 8));
        asm volatile("cp.async.commit_group;");
    }

    for (int kt = 0; kt < nk; kt++) {
        asm volatile("cp.async.wait_group 2;");
        __syncthreads();
        int pf = kt + 3;
        if (pf < nk) {
            int sbuf = pf & 3;
            bf16* as = AsB + sbuf * (128*40);
            bf16* bs = BsB + sbuf * (128*40);
            uint32_t sa = smem_u32(as + ldrow * 40 + ldkoff);
            uint32_t sb = smem_u32(bs + ldrow * 40 + ldkoff);
            const bf16* ag = Agp + pf * 32;
            const bf16* bg = Bgp + pf * 32;
            asm volatile("cp.async.ca.shared.global [%0], [%1], 16;\n"
                         "cp.async.ca.shared.global [%2], [%3], 16;\n"
                         "cp.async.ca.shared.global [%4], [%5], 16;\n"
                         "cp.async.ca.shared.global [%6], [%7], 16;\n"
                         :: "r"(sa), "l"(ag), "r"(sa + 16), "l"(ag + 8),
                            "r"(sb), "l"(bg), "r"(sb + 16), "l"(bg + 8));
        }
        asm volatile("cp.async.commit_group;");

        int cbuf = kt & 3;
        bf16* as = AsB + cbuf * (128*40);
        bf16* bs = BsB + cbuf * (128*40);
#pragma unroll
        for (int ks = 0; ks < 2; ks++) {
            int k0 = ks * 16;
            uint32_t a[2][4];
#pragma unroll
            for (int mi = 0; mi < 2; mi++) {
                int m = warp_m * 32 + mi * 16 + (lane & 15);
                int kc = k0 + ((lane >> 4) << 3);
                uint32_t addr = smem_u32(as + m * 40 + kc);
                asm volatile("ldmatrix.sync.aligned.m8n8.x4.shared.b16 {%0,%1,%2,%3}, [%4];"
                             : "=r"(a[mi][0]), "=r"(a[mi][1]), "=r"(a[mi][2]), "=r"(a[mi][3])
                             : "r"(addr));
            }
            uint32_t b[8][2];
#pragma unroll
            for (int nt = 0; nt < 4; nt++) {
                int n = warp_n * 64 + nt * 16 + (lane & 7) + ((lane >> 4) << 3);
                int kc = k0 + (((lane >> 3) & 1) << 3);
                uint32_t addr = smem_u32(bs + n * 40 + kc);
                asm volatile("ldmatrix.sync.aligned.m8n8.x4.shared.b16 {%0,%1,%2,%3}, [%4];"
                             : "=r"(b[nt*2][0]), "=r"(b[nt*2][1]),
                               "=r"(b[nt*2+1][0]), "=r"(b[nt*2+1][1])
                             : "r"(addr));
            }
#pragma unroll
            for (int mi = 0; mi < 2; mi++)
#pragma unroll
                for (int ni = 0; ni < 8; ni++) {
                    asm volatile(
                        "mma.sync.aligned.m16n8k16.row.col.f32.bf16.bf16.f32 "
                        "{%0,%1,%2,%3}, {%4,%5,%6,%7}, {%8,%9}, {%0,%1,%2,%3};\n"
                        : "+f"(c[mi][ni][0]), "+f"(c[mi][ni][1]),
                          "+f"(c[mi][ni][2]), "+f"(c[mi][ni][3])
                        : "r"(a[mi][0]), "r"(a[mi][1]), "r"(a[mi][2]), "r"(a[mi][3]),
                          "r"(b[ni][0]), "r"(b[ni][1]));
                }
        }
    }

    bool addbias = (bias != nullptr) && (ksplit == 1 || blockIdx.z == 0);
    float* Cfz = Cf ? (Cf + (ksplit > 1 ? (size_t)blockIdx.z * partStride : (size_t)zb * cBS)) : nullptr;
    bf16*  Cbz = Cb ? (Cb + (size_t)zb * cBS) : nullptr;
#pragma unroll
    for (int mi = 0; mi < 2; mi++) {
        int row0 = rowA0 + warp_m * 32 + mi * 16 + (lane >> 2);
#pragma unroll
        for (int ni = 0; ni < 8; ni++) {
            int col = colB0 + warp_n * 64 + ni * 8 + (lane & 3) * 2;
            float bv0 = 0.f, bv1 = 0.f;
            if (addbias) { bv0 = bias[col]; bv1 = bias[col + 1]; }
#pragma unroll
            for (int half = 0; half < 2; half++) {
                int gm = row0 + half * 8;
                float v0 = c[mi][ni][half * 2 + 0] + bv0;
                float v1 = c[mi][ni][half * 2 + 1] + bv1;
                if (ksplit > 1) {
                    Cfz[(size_t)gm * ldc + col]     = v0;
                    Cfz[(size_t)gm * ldc + col + 1] = v1;
                } else {
                    if (act == 1) {
                        v0 = 0.5f * v0 * (1.0f + erff(v0 * 0.70710678118654752f));
                        v1 = 0.5f * v1 * (1.0f + erff(v1 * 0.70710678118654752f));
                    }
                    if (Cfz) {
                        Cfz[(size_t)gm * ldc + col]     = v0;
                        Cfz[(size_t)gm * ldc + col + 1] = v1;
                    }
                    if (Cbz) {
                        uint32_t pk = ((uint32_t)__bfloat16_as_ushort(__float2bfloat16_rn(v1)) << 16)
                                    | (uint32_t)__bfloat16_as_ushort(__float2bfloat16_rn(v0));
                        *reinterpret_cast<uint32_t*>(&Cbz[(size_t)gm * ldc + col]) = pk;
                    }
                }
            }
        }
    }
}

// ======== fully fused self-attention ========
#define SMEM_ATT (5*128*72*2)
__global__ __launch_bounds__(256, 1)
void fused_self_attn(const bf16* __restrict__ heads, const bf16* __restrict__ rkall,
                     bf16* __restrict__ vecOut,
                     const float* __restrict__ rwb, const float* __restrict__ rrb,
                     int layer)
{
    extern __shared__ bf16 dsA[];
    bf16* vS   = dsA;
    bf16* regA = dsA + 128*72;
    bf16* qrw  = regA;
    bf16* qrr  = regA + 128*72;
    bf16* kS   = regA + 2*128*72;
    bf16* rkS  = regA + 3*128*72;
    float* bdS = (float*)regA;
    bf16*  PS  = regA;

    __shared__ float rowm[128][2];
    __shared__ float rowsum[128][2];

    int z = blockIdx.x;
    int h = z % HH, b = z / HH;
    int tid = threadIdx.x;
    int warp = tid >> 5, lane = tid & 31;
    int warp_m = warp >> 1, warp_n = warp & 1;
    int gid = lane >> 2, tig = lane & 3;

    {
        int row = tid >> 1;
        int koff = (tid & 1) * 32;
        const bf16* qg  = heads + (size_t)b*3*DD + (size_t)h*DHH + (size_t)row*(BB*3*DD) + koff;
        const bf16* kg  = qg + DD;
        const bf16* vg  = qg + 2*DD;
        const bf16* rkg = rkall + (size_t)layer*DD + (size_t)h*DHH + (size_t)row*(LL*DD) + koff;
        const float* rwh = rwb + h*DHH + koff;
        const float* rrh = rrb + h*DHH + koff;
#pragma unroll
        for (int j = 0; j < 4; j++) {
            bf16 tq[8], trw[8], trr[8];
            *reinterpret_cast<uint4*>(tq) = *reinterpret_cast<const uint4*>(qg + j*8);
#pragma unroll
            for (int e = 0; e < 8; e++) {
                float qv = __bfloat162float(tq[e]);
                trw[e] = __float2bfloat16_rn(qv + rwh[j*8+e]);
                trr[e] = __float2bfloat16_rn(qv + rrh[j*8+e]);
            }
            *reinterpret_cast<uint4*>(&qrw[row*72 + koff + j*8]) = *reinterpret_cast<uint4*>(trw);
            *reinterpret_cast<uint4*>(&qrr[row*72 + koff + j*8]) = *reinterpret_cast<uint4*>(trr);
            *reinterpret_cast<uint4*>(&kS [row*72 + koff + j*8]) =
                *reinterpret_cast<const uint4*>(kg + j*8);
            *reinterpret_cast<uint4*>(&rkS[row*72 + koff + j*8]) =
                *reinterpret_cast<const uint4*>(rkg + j*8);
            *reinterpret_cast<uint4*>(&vS [row*72 + koff + j*8]) =
                *reinterpret_cast<const uint4*>(vg + j*8);
        }
    }
    __syncthreads();

    float cac[2][8][4], cbd[2][8][4];
#pragma unroll
    for (int mi = 0; mi < 2; mi++)
#pragma unroll
        for (int ni = 0; ni < 8; ni++)
#pragma unroll
            for (int r = 0; r < 4; r++) { cac[mi][ni][r] = 0.f; cbd[mi][ni][r] = 0.f; }

#pragma unroll
    for (int ks = 0; ks < 4; ks++) {
        int k0 = ks * 16;
        int m0 = warp_m * 32 + (lane & 15);
        int kcA = k0 + ((lane >> 4) << 3);
        int nI  = warp_n * 64 + (lane & 7) + ((lane >> 4) << 3);
        int kcB = k0 + (((lane >> 3) & 1) << 3);
        uint32_t a1[2][4], a2[2][4];
#pragma unroll
        for (int mi = 0; mi < 2; mi++) {
            uint32_t ad1 = smem_u32(qrw + (m0 + mi*16)*72 + kcA);
            uint32_t ad2 = smem_u32(qrr + (m0 + mi*16)*72 + kcA);
            asm volatile("ldmatrix.sync.aligned.m8n8.x4.shared.b16 {%0,%1,%2,%3}, [%4];"
                         : "=r"(a1[mi][0]), "=r"(a1[mi][1]), "=r"(a1[mi][2]), "=r"(a1[mi][3])
                         : "r"(ad1));
            asm volatile("ldmatrix.sync.aligned.m8n8.x4.shared.b16 {%0,%1,%2,%3}, [%4];"
                         : "=r"(a2[mi][0]), "=r"(a2[mi][1]), "=r"(a2[mi][2]), "=r"(a2[mi][3])
                         : "r"(ad2));
        }
        uint32_t b1[8][2], b2[8][2];
#pragma unroll
        for (int nt = 0; nt < 4; nt++) {
            uint32_t bd1 = smem_u32(kS  + (nI + nt*16)*72 + kcB);
            uint32_t bd2 = smem_u32(rkS + (nI + nt*16)*72 + kcB);
            asm volatile("ldmatrix.sync.aligned.m8n8.x4.shared.b16 {%0,%1,%2,%3}, [%4];"
                         : "=r"(b1[nt*2][0]), "=r"(b1[nt*2][1]),
                           "=r"(b1[nt*2+1][0]), "=r"(b1[nt*2+1][1])
                         : "r"(bd1));
            asm volatile("ldmatrix.sync.aligned.m8n8.x4.shared.b16 {%0,%1,%2,%3}, [%4];"
                         : "=r"(b2[nt*2][0]), "=r"(b2[nt*2][1]),
                           "=r"(b2[nt*2+1][0]), "=r"(b2[nt*2+1][1])
                         : "r"(bd2));
        }
#pragma unroll
        for (int mi = 0; mi < 2; mi++)
#pragma unroll
            for (int ni = 0; ni < 8; ni++) {
                asm volatile("mma.sync.aligned.m16n8k16.row.col.f32.bf16.bf16.f32 "
                             "{%0,%1,%2,%3}, {%4,%5,%6,%7}, {%8,%9}, {%0,%1,%2,%3};\n"
                             : "+f"(cac[mi][ni][0]), "+f"(cac[mi][ni][1]),
                               "+f"(cac[mi][ni][2]), "+f"(cac[mi][ni][3])
                             : "r"(a1[mi][0]), "r"(a1[mi][1]), "r"(a1[mi][2]), "r"(a1[mi][3]),
                               "r"(b1[ni][0]), "r"(b1[ni][1]));
                asm volatile("mma.sync.aligned.m16n8k16.row.col.f32.bf16.bf16.f32 "
                             "{%0,%1,%2,%3}, {%4,%5,%6,%7}, {%8,%9}, {%0,%1,%2,%3};\n"
                             : "+f"(cbd[mi][ni][0]), "+f"(cbd[mi][ni][1]),
                               "+f"(cbd[mi][ni][2]), "+f"(cbd[mi][ni][3])
                             : "r"(a2[mi][0]), "r"(a2[mi][1]), "r"(a2[mi][2]), "r"(a2[mi][3]),
                               "r"(b2[ni][0]), "r"(b2[ni][1]));
            }
    }
    __syncthreads();

#pragma unroll
    for (int mi = 0; mi < 2; mi++) {
        int row0 = warp_m * 32 + mi * 16 + gid;
#pragma unroll
        for (int ni = 0; ni < 8; ni++) {
            int col = warp_n * 64 + ni * 8 + tig * 2;
#pragma unroll
            for (int half = 0; half < 2; half++) {
                int gm = row0 + half * 8;
                bdS[gm * 132 + col]     = cbd[mi][ni][half*2 + 0];
                bdS[gm * 132 + col + 1] = cbd[mi][ni][half*2 + 1];
            }
        }
    }
    __syncthreads();

#pragma unroll
    for (int mi = 0; mi < 2; mi++) {
#pragma unroll
        for (int half = 0; half < 2; half++) {
            int r = warp_m * 32 + mi * 16 + half * 8 + gid;
            float m = -1e30f;
#pragma unroll
            for (int ni = 0; ni < 8; ni++) {
#pragma unroll
                for (int e = 0; e < 2; e++) {
                    int j = warp_n * 64 + ni * 8 + tig * 2 + e;
                    float sc;
                    if (j > r) sc = NEG_;
                    else {
                        int f = r * SS + j + SS;
                        int qi = f / (SS + 1);
                        int cc = f - qi * (SS + 1);
                        float bdv = (cc > 0) ? bdS[qi * 132 + (cc - 1)] : 0.f;
                        sc = (cac[mi][ni][half*2 + e] + bdv) * SCALE_;
                    }
                    cac[mi][ni][half*2 + e] = sc;
                    m = fmaxf(m, sc);
                }
            }
#pragma unroll
            for (int o = 1; o <= 2; o <<= 1) m = fmaxf(m, __shfl_xor_sync(0xffffffffu, m, o));
            if (tig == 0) rowm[r][warp_n] = m;
        }
    }
    __syncthreads();

#pragma unroll
    for (int mi = 0; mi < 2; mi++) {
#pragma unroll
        for (int half = 0; half < 2; half++) {
            int r = warp_m * 32 + mi * 16 + half * 8 + gid;
            float m = fmaxf(rowm[r][0], rowm[r][1]);
            float s = 0.f;
#pragma unroll
            for (int ni = 0; ni < 8; ni++) {
#pragma unroll
                for (int e = 0; e < 2; e++) {
                    float ev = fexp(cac[mi][ni][half*2 + e] - m);
                    cac[mi][ni][half*2 + e] = ev;
                    s += ev;
                }
            }
#pragma unroll
            for (int o = 1; o <= 2; o <<= 1) s += __shfl_xor_sync(0xffffffffu, s, o);
            if (tig == 0) rowsum[r][warp_n] = s;
        }
    }
    __syncthreads();

#pragma unroll
    for (int mi = 0; mi < 2; mi++) {
#pragma unroll
        for (int half = 0; half < 2; half++) {
            int r = warp_m * 32 + mi * 16 + half * 8 + gid;
            float inv = 1.0f / (rowsum[r][0] + rowsum[r][1]);
#pragma unroll
            for (int ni = 0; ni < 8; ni++) {
                int col = warp_n * 64 + ni * 8 + tig * 2;
                uint32_t pk = ((uint32_t)__bfloat16_as_ushort(
                                  __float2bfloat16_rn(cac[mi][ni][half*2+1] * inv)) << 16)
                            | (uint32_t)__bfloat16_as_ushort(
                                  __float2bfloat16_rn(cac[mi][ni][half*2+0] * inv));
                *reinterpret_cast<uint32_t*>(&PS[r * 136 + col]) = pk;
            }
        }
    }
    __syncthreads();

    float c2[2][4][4];
#pragma unroll
    for (int mi = 0; mi < 2; mi++)
#pragma unroll
        for (int ni = 0; ni < 4; ni++)
#pragma unroll
            for (int r = 0; r < 4; r++) c2[mi][ni][r] = 0.f;

#pragma unroll
    for (int ks = 0; ks < 8; ks++) {
        int k0 = ks * 16;
        uint32_t a[2][4];
#pragma unroll
        for (int mi = 0; mi < 2; mi++) {
            int m = warp_m * 32 + mi * 16 + (lane & 15);
            int kc = k0 + ((lane >> 4) << 3);
            uint32_t addr = smem_u32(PS + m * 136 + kc);
            asm volatile("ldmatrix.sync.aligned.m8n8.x4.shared.b16 {%0,%1,%2,%3}, [%4];"
                         : "=r"(a[mi][0]), "=r"(a[mi][1]), "=r"(a[mi][2]), "=r"(a[mi][3])
                         : "r"(addr));
        }
        uint32_t bb[4][2];
#pragma unroll
        for (int nt = 0; nt < 2; nt++) {
            int kr = k0 + (lane & 15);
            int n = warp_n * 32 + nt * 16 + ((lane >> 4) << 3);
            uint32_t addr = smem_u32(vS + kr * 72 + n);
            asm volatile("ldmatrix.sync.aligned.m8n8.x4.trans.shared.b16 {%0,%1,%2,%3}, [%4];"
                         : "=r"(bb[nt*2][0]), "=r"(bb[nt*2][1]),
                           "=r"(bb[nt*2+1][0]), "=r"(bb[nt*2+1][1])
                         : "r"(addr));
        }
#pragma unroll
        for (int mi = 0; mi < 2; mi++)
#pragma unroll
            for (int ni = 0; ni < 4; ni++) {
                asm volatile("mma.sync.aligned.m16n8k16.row.col.f32.bf16.bf16.f32 "
                             "{%0,%1,%2,%3}, {%4,%5,%6,%7}, {%8,%9}, {%0,%1,%2,%3};\n"
                             : "+f"(c2[mi][ni][0]), "+f"(c2[mi][ni][1]),
                               "+f"(c2[mi][ni][2]), "+f"(c2[mi][ni][3])
                             : "r"(a[mi][0]), "r"(a[mi][1]), "r"(a[mi][2]), "r"(a[mi][3]),
                               "r"(bb[ni][0]), "r"(bb[ni][1]));
            }
    }

    bf16* outBase = vecOut + (size_t)b * DD + (size_t)h * DHH;
#pragma unroll
    for (int mi = 0; mi < 2; mi++) {
        int row0 = warp_m * 32 + mi * 16 + gid;
#pragma unroll
        for (int ni = 0; ni < 4; ni++) {
            int col = warp_n * 32 + ni * 8 + tig * 2;
#pragma unroll
            for (int half = 0; half < 2; half++) {
                int gm = row0 + half * 8;
                uint32_t pk = ((uint32_t)__bfloat16_as_ushort(__float2bfloat16_rn(c2[mi][ni][half*2+1])) << 16)
                            | (uint32_t)__bfloat16_as_ushort(__float2bfloat16_rn(c2[mi][ni][half*2+0]));
                *reinterpret_cast<uint32_t*>(&outBase[(size_t)gm * (BB*DD) + col]) = pk;
            }
        }
    }
}

// ======== fused cross-attention: flash-style over E=512 in 4 chunks of 128 ========
#define SMEM_XATT ((3*128*72 + 128*136)*2)
__global__ __launch_bounds__(256, 1)
void fused_cross_attn(const bf16* __restrict__ q2, const bf16* __restrict__ kvall,
                      const float* __restrict__ mask,
                      bf16* __restrict__ vecOut, int layer)
{
    extern __shared__ bf16 dsX[];
    bf16* qS = dsX;
    bf16* kS = dsX + 128*72;
    bf16* vS = dsX + 2*128*72;
    bf16* PS = dsX + 3*128*72;

    __shared__ float rowm[128][2];
    __shared__ float rowsum[128][2];
    __shared__ float maskS[128];

    int z = blockIdx.x;
    int h = z % HH, b = z / HH;
    int tid = threadIdx.x;
    int warp = tid >> 5, lane = tid & 31;
    int warp_m = warp >> 1, warp_n = warp & 1;
    int gid = lane >> 2, tig = lane & 3;
    int row = tid >> 1, koff = (tid & 1) * 32;

    {
        const bf16* qg = q2 + (size_t)b*DD + (size_t)h*DHH + (size_t)row*(BB*DD) + koff;
#pragma unroll
        for (int j = 0; j < 4; j++)
            *reinterpret_cast<uint4*>(&qS[row*72 + koff + j*8]) =
                *reinterpret_cast<const uint4*>(qg + j*8);
    }

    const bf16* kBase = kvall + (size_t)layer*2*DD + (size_t)b*(LL*2*DD) + (size_t)h*DHH;
    const bf16* vBase = kBase + DD;
    const long long kvRow = (long long)BB*LL*2*DD;

    float mstate[2][2], lstate[2][2];
#pragma unroll
    for (int mi = 0; mi < 2; mi++)
#pragma unroll
        for (int half = 0; half < 2; half++) { mstate[mi][half] = -1e30f; lstate[mi][half] = 0.f; }

    float c2[2][4][4];
#pragma unroll
    for (int mi = 0; mi < 2; mi++)
#pragma unroll
        for (int ni = 0; ni < 4; ni++)
#pragma unroll
            for (int r = 0; r < 4; r++) c2[mi][ni][r] = 0.f;

    for (int kc = 0; kc < 4; kc++) {
        {
            const bf16* kg = kBase + (size_t)(kc*128 + row) * kvRow + koff;
            const bf16* vg = vBase + (size_t)(kc*128 + row) * kvRow + koff;
#pragma unroll
            for (int j = 0; j < 4; j++) {
                *reinterpret_cast<uint4*>(&kS[row*72 + koff + j*8]) =
                    *reinterpret_cast<const uint4*>(kg + j*8);
                *reinterpret_cast<uint4*>(&vS[row*72 + koff + j*8]) =
                    *reinterpret_cast<const uint4*>(vg + j*8);
            }
            if (tid < 128) maskS[tid] = mask[b*EE + kc*128 + tid];
        }
        __syncthreads();

        float cs[2][8][4];
#pragma unroll
        for (int mi = 0; mi < 2; mi++)
#pragma unroll
            for (int ni = 0; ni < 8; ni++)
#pragma unroll
                for (int r = 0; r < 4; r++) cs[mi][ni][r] = 0.f;

#pragma unroll
        for (int ks = 0; ks < 4; ks++) {
            int k0 = ks * 16;
            uint32_t a[2][4];
#pragma unroll
            for (int mi = 0; mi < 2; mi++) {
                int m = warp_m * 32 + mi * 16 + (lane & 15);
                int kcc = k0 + ((lane >> 4) << 3);
                uint32_t addr = smem_u32(qS + m*72 + kcc);
                asm volatile("ldmatrix.sync.aligned.m8n8.x4.shared.b16 {%0,%1,%2,%3}, [%4];"
                             : "=r"(a[mi][0]), "=r"(a[mi][1]), "=r"(a[mi][2]), "=r"(a[mi][3])
                             : "r"(addr));
            }
            uint32_t bb[8][2];
#pragma unroll
            for (int nt = 0; nt < 4; nt++) {
                int n = warp_n * 64 + nt * 16 + (lane & 7) + ((lane >> 4) << 3);
                int kcc = k0 + (((lane >> 3) & 1) << 3);
                uint32_t addr = smem_u32(kS + n*72 + kcc);
                asm volatile("ldmatrix.sync.aligned.m8n8.x4.shared.b16 {%0,%1,%2,%3}, [%4];"
                             : "=r"(bb[nt*2][0]), "=r"(bb[nt*2][1]),
                               "=r"(bb[nt*2+1][0]), "=r"(bb[nt*2+1][1])
                             : "r"(addr));
            }
#pragma unroll
            for (int mi = 0; mi < 2; mi++)
#pragma unroll
                for (int ni = 0; ni < 8; ni++) {
                    asm volatile("mma.sync.aligned.m16n8k16.row.col.f32.bf16.bf16.f32 "
                                 "{%0,%1,%2,%3}, {%4,%5,%6,%7}, {%8,%9}, {%0,%1,%2,%3};\n"
                                 : "+f"(cs[mi][ni][0]), "+f"(cs[mi][ni][1]),
                                   "+f"(cs[mi][ni][2]), "+f"(cs[mi][ni][3])
                                 : "r"(a[mi][0]), "r"(a[mi][1]), "r"(a[mi][2]), "r"(a[mi][3]),
                                   "r"(bb[ni][0]), "r"(bb[ni][1]));
                }
        }

#pragma unroll
        for (int mi = 0; mi < 2; mi++) {
#pragma unroll
            for (int half = 0; half < 2; half++) {
                int r = warp_m * 32 + mi * 16 + half * 8 + gid;
                float m = -1e30f;
#pragma unroll
                for (int ni = 0; ni < 8; ni++) {
#pragma unroll
                    for (int e = 0; e < 2; e++) {
                        int j = warp_n * 64 + ni * 8 + tig * 2 + e;
                        float sc = cs[mi][ni][half*2 + e] * SCALE_
                                 + (1.0f - maskS[j]) * NEG_;
                        cs[mi][ni][half*2 + e] = sc;
                        m = fmaxf(m, sc);
                    }
                }
#pragma unroll
                for (int o = 1; o <= 2; o <<= 1) m = fmaxf(m, __shfl_xor_sync(0xffffffffu, m, o));
                if (tig == 0) rowm[r][warp_n] = m;
            }
        }
        __syncthreads();

        float scaleF[2][2], mnew[2][2];
#pragma unroll
        for (int mi = 0; mi < 2; mi++) {
#pragma unroll
            for (int half = 0; half < 2; half++) {
                int r = warp_m * 32 + mi * 16 + half * 8 + gid;
                float mc = fmaxf(rowm[r][0], rowm[r][1]);
                float mn = fmaxf(mstate[mi][half], mc);
                scaleF[mi][half] = fexp(mstate[mi][half] - mn);
                mnew[mi][half] = mn;
                float s = 0.f;
#pragma unroll
                for (int ni = 0; ni < 8; ni++) {
#pragma unroll
                    for (int e = 0; e < 2; e++) {
                        float ev = fexp(cs[mi][ni][half*2 + e] - mn);
                        cs[mi][ni][half*2 + e] = ev;
                        s += ev;
                    }
                }
#pragma unroll
                for (int o = 1; o <= 2; o <<= 1) s += __shfl_xor_sync(0xffffffffu, s, o);
                if (tig == 0) rowsum[r][warp_n] = s;
            }
        }
        __syncthreads();

#pragma unroll
        for (int mi = 0; mi < 2; mi++) {
#pragma unroll
            for (int half = 0; half < 2; half++) {
                int r = warp_m * 32 + mi * 16 + half * 8 + gid;
                float sc = scaleF[mi][half];
                lstate[mi][half] = lstate[mi][half] * sc + rowsum[r][0] + rowsum[r][1];
                mstate[mi][half] = mnew[mi][half];
#pragma unroll
                for (int ni = 0; ni < 4; ni++) {
                    c2[mi][ni][half*2 + 0] *= sc;
                    c2[mi][ni][half*2 + 1] *= sc;
                }
#pragma unroll
                for (int ni = 0; ni < 8; ni++) {
                    int col = warp_n * 64 + ni * 8 + tig * 2;
                    uint32_t pk = ((uint32_t)__bfloat16_as_ushort(
                                      __float2bfloat16_rn(cs[mi][ni][half*2+1])) << 16)
                                | (uint32_t)__bfloat16_as_ushort(
                                      __float2bfloat16_rn(cs[mi][ni][half*2+0]));
                    *reinterpret_cast<uint32_t*>(&PS[r * 136 + col]) = pk;
                }
            }
        }
        __syncthreads();

#pragma unroll
        for (int ks = 0; ks < 8; ks++) {
            int k0 = ks * 16;
            uint32_t a[2][4];
#pragma unroll
            for (int mi = 0; mi < 2; mi++) {
                int m = warp_m * 32 + mi * 16 + (lane & 15);
                int kcc = k0 + ((lane >> 4) << 3);
                uint32_t addr = smem_u32(PS + m * 136 + kcc);
                asm volatile("ldmatrix.sync.aligned.m8n8.x4.shared.b16 {%0,%1,%2,%3}, [%4];"
                             : "=r"(a[mi][0]), "=r"(a[mi][1]), "=r"(a[mi][2]), "=r"(a[mi][3])
                             : "r"(addr));
            }
            uint32_t bb[4][2];
#pragma unroll
            for (int nt = 0; nt < 2; nt++) {
                int kr = k0 + (lane & 15);
                int n = warp_n * 32 + nt * 16 + ((lane >> 4) << 3);
                uint32_t addr = smem_u32(vS + kr * 72 + n);
                asm volatile("ldmatrix.sync.aligned.m8n8.x4.trans.shared.b16 {%0,%1,%2,%3}, [%4];"
                             : "=r"(bb[nt*2][0]), "=r"(bb[nt*2][1]),
                               "=r"(bb[nt*2+1][0]), "=r"(bb[nt*2+1][1])
                             : "r"(addr));
            }
#pragma unroll
            for (int mi = 0; mi < 2; mi++)
#pragma unroll
                for (int ni = 0; ni < 4; ni++) {
                    asm volatile("mma.sync.aligned.m16n8k16.row.col.f32.bf16.bf16.f32 "
                                 "{%0,%1,%2,%3}, {%4,%5,%6,%7}, {%8,%9}, {%0,%1,%2,%3};\n"
                                 : "+f"(c2[mi][ni][0]), "+f"(c2[mi][ni][1]),
                                   "+f"(c2[mi][ni][2]), "+f"(c2[mi][ni][3])
                                 : "r"(a[mi][0]), "r"(a[mi][1]), "r"(a[mi][2]), "r"(a[mi][3]),
                                   "r"(bb[ni][0]), "r"(bb[ni][1]));
                }
        }
        __syncthreads();
    }

    bf16* outBase = vecOut + (size_t)b * DD + (size_t)h * DHH;
#pragma unroll
    for (int mi = 0; mi < 2; mi++) {
        int row0 = warp_m * 32 + mi * 16 + gid;
#pragma unroll
        for (int ni = 0; ni < 4; ni++) {
            int col = warp_n * 32 + ni * 8 + tig * 2;
#pragma unroll
            for (int half = 0; half < 2; half++) {
                int gm = row0 + half * 8;
                float inv = 1.0f / lstate[mi][half];
                uint32_t pk = ((uint32_t)__bfloat16_as_ushort(
                                  __float2bfloat16_rn(c2[mi][ni][half*2+1] * inv)) << 16)
                            | (uint32_t)__bfloat16_as_ushort(
                                  __float2bfloat16_rn(c2[mi][ni][half*2+0] * inv));
                *reinterpret_cast<uint32_t*>(&outBase[(size_t)gm * (BB*DD) + col]) = pk;
            }
        }
    }
}

// ======== vocab-logits GEMM with fused stats + tgt extract (4-stage) ========
__global__ __launch_bounds__(256, 2)
void sgemm_vocab(const bf16* __restrict__ A, const bf16* __restrict__ Bw,
                 const int* __restrict__ decode_target,
                 float* __restrict__ pm, float* __restrict__ ps,
                 float* __restrict__ tgtlog,
                 int K, int lda, int ldb)
{
    extern __shared__ bf16 ds[];
    bf16* AsB = ds;
    bf16* BsB = ds + 4*128*40;

    int tid = threadIdx.x;
    int warp = tid >> 5, lane = tid & 31;
    int warp_m = warp >> 1;
    int warp_n = warp & 1;
    int rowA0 = blockIdx.y * 128;
    int colB0 = blockIdx.x * 128;

    int ldrow = tid >> 1;
    int ldkoff = (tid & 1) * 16;

    float c[2][8][4];
#pragma unroll
    for (int mi = 0; mi < 2; mi++)
#pragma unroll
        for (int ni = 0; ni < 8; ni++)
#pragma unroll
            for (int r = 0; r < 4; r++) c[mi][ni][r] = 0.f;

    const bf16* Agp = &A[(size_t)(rowA0 + ldrow) * lda + ldkoff];
    const bf16* Bgp = &Bw[(size_t)(colB0 + ldrow) * ldb + ldkoff];

    int nk = K >> 5;
#pragma unroll
    for (int s = 0; s < 3; s++) {
        bf16* as = AsB + s * (128*40);
        bf16* bs = BsB + s * (128*40);
        uint32_t sa = smem_u32(as + ldrow * 40 + ldkoff);
        uint32_t sb = smem_u32(bs + ldrow * 40 + ldkoff);
        const bf16* ag = Agp + s * 32;
        const bf16* bg = Bgp + s * 32;
        asm volatile("cp.async.ca.shared.global [%0], [%1], 16;\n"
                     "cp.async.ca.shared.global [%2], [%3], 16;\n"
                     "cp.async.ca.shared.global [%4], [%5], 16;\n"
                     "cp.async.ca.shared.global [%6], [%7], 16;\n"
                     :: "r"(sa), "l"(ag), "r"(sa + 16), "l"(ag + 8),
                        "r"(sb), "l"(bg), "r"(sb + 16), "l"(bg + 8));
        asm volatile("cp.async.commit_group;");
    }

    for (int kt = 0; kt < nk; kt++) {
        asm volatile("cp.async.wait_group 2;");
        __syncthreads();
        int pf = kt + 3;
        if (pf < nk) {
            int sbuf = pf & 3;
            bf16* as = AsB + sbuf * (128*40);
            bf16* bs = BsB + sbuf * (128*40);
            uint32_t sa = smem_u32(as + ldrow * 40 + ldkoff);
            uint32_t sb = smem_u32(bs + ldrow * 40 + ldkoff);
            const bf16* ag = Agp + pf * 32;
            const bf16* bg = Bgp + pf * 32;
            asm volatile("cp.async.ca.shared.global [%0], [%1], 16;\n"
                         "cp.async.ca.shared.global [%2], [%3], 16;\n"
                         "cp.async.ca.shared.global [%4], [%5], 16;\n"
                         "cp.async.ca.shared.global [%6], [%7], 16;\n"
                         :: "r"(sa), "l"(ag), "r"(sa + 16), "l"(ag + 8),
                            "r"(sb), "l"(bg), "r"(sb + 16), "l"(bg + 8));
        }
        asm volatile("cp.async.commit_group;");

        int cbuf = kt & 3;
        bf16* as = AsB + cbuf * (128*40);
        bf16* bs = BsB + cbuf * (128*40);
#pragma unroll
        for (int ks = 0; ks < 2; ks++) {
            int k0 = ks * 16;
            uint32_t a[2][4];
#pragma unroll
            for (int mi = 0; mi < 2; mi++) {
                int m = warp_m * 32 + mi * 16 + (lane & 15);
                int kc = k0 + ((lane >> 4) << 3);
                uint32_t addr = smem_u32(as + m * 40 + kc);
                asm volatile("ldmatrix.sync.aligned.m8n8.x4.shared.b16 {%0,%1,%2,%3}, [%4];"
                             : "=r"(a[mi][0]), "=r"(a[mi][1]), "=r"(a[mi][2]), "=r"(a[mi][3])
                             : "r"(addr));
            }
            uint32_t b[8][2];
#pragma unroll
            for (int nt = 0; nt < 4; nt++) {
                int n = warp_n * 64 + nt * 16 + (lane & 7) + ((lane >> 4) << 3);
                int kc = k0 + (((lane >> 3) & 1) << 3);
                uint32_t addr = smem_u32(bs + n * 40 + kc);
                asm volatile("ldmatrix.sync.aligned.m8n8.x4.shared.b16 {%0,%1,%2,%3}, [%4];"
                             : "=r"(b[nt*2][0]), "=r"(b[nt*2][1]),
                               "=r"(b[nt*2+1][0]), "=r"(b[nt*2+1][1])
                             : "r"(addr));
            }
#pragma unroll
            for (int mi = 0; mi < 2; mi++)
#pragma unroll
                for (int ni = 0; ni < 8; ni++) {
                    asm volatile(
                        "mma.sync.aligned.m16n8k16.row.col.f32.bf16.bf16.f32 "
                        "{%0,%1,%2,%3}, {%4,%5,%6,%7}, {%8,%9}, {%0,%1,%2,%3};\n"
                        : "+f"(c[mi][ni][0]), "+f"(c[mi][ni][1]),
                          "+f"(c[mi][ni][2]), "+f"(c[mi][ni][3])
                        : "r"(a[mi][0]), "r"(a[mi][1]), "r"(a[mi][2]), "r"(a[mi][3]),
                          "r"(b[ni][0]), "r"(b[ni][1]));
                }
        }
    }

    __shared__ int   stgt[128];
    __shared__ float smx[128][2];
    __shared__ float ssx[128][2];
    if (tid < 128) {
        int grow = rowA0 + tid;
        stgt[tid] = decode_target[(grow & (BB-1)) * SS + (grow >> 3)];
    }
    __syncthreads();

    int gid = lane >> 2, tig = lane & 3;
#pragma unroll
    for (int mi = 0; mi < 2; mi++) {
#pragma unroll
        for (int half = 0; half < 2; half++) {
            int rl = warp_m * 32 + mi * 16 + half * 8 + gid;
            int tgt_c = stgt[rl] - colB0;
            float m = -1e30f, s = 0.f;
#pragma unroll
            for (int ni = 0; ni < 8; ni++) {
#pragma unroll
                for (int e = 0; e < 2; e++) {
                    float v = c[mi][ni][half * 2 + e];
                    int coll = warp_n * 64 + ni * 8 + tig * 2 + e;
                    if (coll == tgt_c) tgtlog[rowA0 + rl] = v;
                    if (v <= m) s += fexp(v - m);
                    else { s = s * fexp(m - v) + 1.0f; m = v; }
                }
            }
#pragma unroll
            for (int o = 1; o <= 2; o <<= 1) {
                float mo = __shfl_xor_sync(0xffffffffu, m, o);
                float so = __shfl_xor_sync(0xffffffffu, s, o);
                float M = fmaxf(m, mo);
                s = s * fexp(m - M) + so * fexp(mo - M);
                m = M;
            }
            if (tig == 0) { smx[rl][warp_n] = m; ssx[rl][warp_n] = s; }
        }
    }
    __syncthreads();
    if (tid < 128) {
        float m0 = smx[tid][0], s0 = ssx[tid][0];
        float m1 = smx[tid][1], s1 = ssx[tid][1];
        float M = fmaxf(m0, m1);
        float S = s0 * fexp(m0 - M) + s1 * fexp(m1 - M);
        pm[(size_t)(rowA0 + tid) * 256 + blockIdx.x] = M;
        ps[(size_t)(rowA0 + tid) * 256 + blockIdx.x] = S;
    }
}

__global__ void stats_final(const float* __restrict__ pm, const float* __restrict__ ps,
                            float* __restrict__ rmax, float* __restrict__ rsum)
{
    int t = blockIdx.x;
    int lane = threadIdx.x;
    float m = -1e30f, s = 0.f;
    for (int i = lane; i < NTILE; i += 32) {
        float mi = pm[(size_t)t * 256 + i];
        float si = ps[(size_t)t * 256 + i];
        float M = fmaxf(m, mi);
        s = s * fexp(m - M) + si * fexp(mi - M);
        m = M;
    }
#pragma unroll
    for (int o = 16; o > 0; o >>= 1) {
        float mo = __shfl_xor_sync(0xffffffffu, m, o);
        float so = __shfl_xor_sync(0xffffffffu, s, o);
        float M = fmaxf(m, mo);
        s = s * fexp(m - M) + so * fexp(mo - M);
        m = M;
    }
    if (lane == 0) { rmax[t] = m; rsum[t] = s; }
}

// ---------------- misc small kernels --------------------------------------------------
__global__ void pos_emb_kernel(float* __restrict__ r, bf16* __restrict__ rb)
{
    int i = blockIdx.x;
    float pos = (float)(SS - 1 - i);
    const float LOG1E4 = 9.210340371976184f;
    for (int d = threadIdx.x; d < DD; d += 256) {
        int j = (d < DD/2) ? d : d - DD/2;
        float invf = expf(-((float)j / (DD/2)) * LOG1E4);
        float a = pos * invf;
        float v = (d < DD/2) ? sinf(a) : cosf(a);
        r[i * DD + d] = v;
        rb[i * DD + d] = __float2bfloat16_rn(v);
    }
}

__global__ void embed_kernel(const int* __restrict__ dec, const float* __restrict__ emb,
                             float* __restrict__ core, bf16* __restrict__ coreb)
{
    int t = blockIdx.x;
    int b = t & (BB-1), s = t >> 3;
    int id = dec[b * SS + s];
    const float* src = emb + (size_t)id * DD;
    for (int d = threadIdx.x; d < DD; d += 256) {
        float v = src[d];
        core[(size_t)t * DD + d] = v;
        coreb[(size_t)t * DD + d] = __float2bfloat16_rn(v);
    }
}

__global__ void transpose_enc(const float* __restrict__ enc, float* __restrict__ enct,
                              bf16* __restrict__ enctb)
{
    int t = blockIdx.x;
    int b = t & (BB-1), e = t >> 3;
    const float* src = enc + ((size_t)b * EE + e) * DD;
    for (int d = threadIdx.x; d < DD; d += 256) {
        float v = src[d];
        enct[(size_t)t * DD + d] = v;
        enctb[(size_t)t * DD + d] = __float2bfloat16_rn(v);
    }
}

__device__ __forceinline__ float warp_max(float v)
{
#pragma unroll
    for (int o = 16; o > 0; o >>= 1) v = fmaxf(v, __shfl_xor_sync(0xffffffffu, v, o));
    return v;
}
__device__ __forceinline__ float warp_sum(float v)
{
#pragma unroll
    for (int o = 16; o > 0; o >>= 1) v += __shfl_xor_sync(0xffffffffu, v, o);
    return v;
}

__global__ void softmax_il(float* __restrict__ IL, const float* __restrict__ mask)
{
    int t = blockIdx.x;
    int b = t & (BB - 1);
    int k = threadIdx.x;
    int wid = k >> 5, lane = k & 31;
    float v = IL[(size_t)t * EE + k] + (1.0f - mask[b * EE + k]) * NEG_;
    __shared__ float red[16];
    float m = warp_max(v);
    if (lane == 0) red[wid] = m;
    __syncthreads();
    m = red[0];
#pragma unroll
    for (int w = 1; w < 16; w++) m = fmaxf(m, red[w]);
    float e = fexp(v - m);
    __shared__ float red2[16];
    float sum = warp_sum(e);
    if (lane == 0) red2[wid] = sum;
    __syncthreads();
    sum = red2[0];
#pragma unroll
    for (int w = 1; w < 16; w++) sum += red2[w];
    IL[(size_t)t * EE + k] = e / sum;
}

__global__ void add_ln(const float* __restrict__ resid, const float* __restrict__ parts,
                       int nparts,
                       float* __restrict__ out, bf16* __restrict__ outb,
                       const float* __restrict__ g, const float* __restrict__ bta)
{
    int t = blockIdx.x;
    int tid = threadIdx.x;
    __shared__ float zb[DD];
    __shared__ float red[256];
    float s = 0.f;
#pragma unroll
    for (int u = 0; u < 4; u++) {
        int d = tid + u * 256;
        float z = resid[(size_t)t * DD + d];
        for (int p = 0; p < nparts; p++)
            z += parts[(size_t)p * TT * DD + (size_t)t * DD + d];
        zb[d] = z; s += z;
    }
    red[tid] = s; __syncthreads();
    for (int st = 128; st > 0; st >>= 1) { if (tid < st) red[tid] += red[tid + st]; __syncthreads(); }
    float mean = red[0] * (1.0f / DD); __syncthreads();
    float v = 0.f;
#pragma unroll
    for (int u = 0; u < 4; u++) {
        int d = tid + u * 256;
        float dz = zb[d] - mean; v += dz * dz;
    }
    red[tid] = v; __syncthreads();
    for (int st = 128; st > 0; st >>= 1) { if (tid < st) red[tid] += red[tid + st]; __syncthreads(); }
    float inv = rsqrtf(red[0] * (1.0f / DD) + 1e-5f);
#pragma unroll
    for (int u = 0; u < 4; u++) {
        int d = tid + u * 256;
        float o = (zb[d] - mean) * inv * g[d] + bta[d];
        out[(size_t)t * DD + d] = o;
        if (outb) outb[(size_t)t * DD + d] = __float2bfloat16_rn(o);
    }
}

__global__ void mode_kernel(const float* __restrict__ core, const float* __restrict__ mw,
                            const float* __restrict__ mb, float* __restrict__ msig)
{
    int t = blockIdx.x;
    int tid = threadIdx.x;
    int wid = tid >> 5, lane = tid & 31;
    float s = 0.f;
    for (int d = tid; d < DD; d += 256) s += core[(size_t)t * DD + d] * mw[d];
    s = warp_sum(s);
    __shared__ float red[8];
    if (lane == 0) red[wid] = s;
    __syncthreads();
    if (tid == 0) {
        float tot = red[0];
#pragma unroll
        for (int w = 1; w < 8; w++) tot += red[w];
        msig[t] = 1.0f / (1.0f + expf(-(tot + mb[0])));
    }
}

__global__ void zero_loss()
{
    g_lossacc[0] = 0.f;
    g_lossacc[1] = 0.f;
}

__global__ void loss_partial(const float* __restrict__ tgtlog, const float* __restrict__ rmax,
                             const float* __restrict__ rsum, const float* __restrict__ msig,
                             const float* __restrict__ IL, const int* __restrict__ input_ids,
                             const int* __restrict__ decode_target)
{
    int tid = threadIdx.x;
    int wid = tid >> 5, lane = tid & 31;
    int t = blockIdx.x * 8 + wid;
    float acc = 0.f, cnt = 0.f;
    int b = t & (BB - 1), sIdx = t >> 3;
    int tgt = decode_target[b * SS + sIdx];
    if (tgt != 0) {
        const int* ids = input_ids + b * EE;
        const float* il = IL + (size_t)t * EE;
        float cp = 0.f;
        for (int j = lane; j < EE; j += 32)
            if (ids[j] == tgt) cp += il[j];
        cp = warp_sum(cp);
        if (lane == 0) {
            float mg = msig[t];
            float p = expf(tgtlog[t] - rmax[t]) / rsum[t] * mg;
            p += (1.0f - mg) * cp;
            acc = -logf(p + 1e-6f);
            cnt = 1.0f;
        }
    }
    __shared__ float sa[8], sc[8];
    if (lane == 0) { sa[wid] = acc; sc[wid] = cnt; }
    __syncthreads();
    if (tid == 0) {
        float A = 0.f, C = 0.f;
#pragma unroll
        for (int w = 0; w < 8; w++) { A += sa[w]; C += sc[w]; }
        atomicAdd(&g_lossacc[0], A);
        atomicAdd(&g_lossacc[1], C);
    }
}

__global__ void loss_final(float* __restrict__ out)
{
    out[threadIdx.x] = g_lossacc[0] / g_lossacc[1];
}

// ---------------- host orchestration --------------------------------------------------
static void* symaddr(const void* sym)
{
    void* p = nullptr;
    cudaGetSymbolAddress(&p, sym);
    return p;
}

static void cvtS(const float* src, bf16* dst, size_t n, cudaStream_t st)
{
    int blocks = (int)((n / 4 + 255) / 256);
    cvt_bf16<<<blocks, 256, 0, st>>>(src, dst, (int)n);
}

extern "C" void kernel_launch(void* const* d_in, const int* in_sizes, int n_in,
                              void* d_out, int out_size)
{
    const int*   input_ids     = (const int*)d_in[0];
    const float* encoder_rep   = (const float*)d_in[1];
    const float* input_mask    = (const float*)d_in[2];
    const int*   decode_input  = (const int*)d_in[3];
    const int*   decode_target = (const int*)d_in[4];
    const float* word_emb      = (const float*)d_in[5];
    const float* qkv_w         = (const float*)d_in[6];
    const float* r_w           = (const float*)d_in[7];
    const float* o_w           = (const float*)d_in[8];
    const float* kv_w          = (const float*)d_in[9];
    const float* q_w           = (const float*)d_in[10];
    const float* io_w          = (const float*)d_in[11];
    const float* rr_bias       = (const float*)d_in[12];
    const float* rw_bias       = (const float*)d_in[13];
    const float* ln1_g         = (const float*)d_in[14];
    const float* ln1_b         = (const float*)d_in[15];
    const float* ln2_g         = (const float*)d_in[16];
    const float* ln2_b         = (const float*)d_in[17];
    const float* ffn_w1        = (const float*)d_in[18];
    const float* ffn_b1        = (const float*)d_in[19];
    const float* ffn_w2        = (const float*)d_in[20];
    const float* ffn_b2        = (const float*)d_in[21];
    const float* ln3_g         = (const float*)d_in[22];
    const float* ln3_b         = (const float*)d_in[23];
    const float* out_w         = (const float*)d_in[24];
    const float* out_b         = (const float*)d_in[25];
    const float* copy_w        = (const float*)d_in[26];
    const float* copy_b        = (const float*)d_in[27];
    const float* mode_w        = (const float*)d_in[28];
    const float* mode_b        = (const float*)d_in[29];

    float* p_r     = (float*)symaddr(g_r);
    float* p_core  = (float*)symaddr(g_core);
    float* p_x     = (float*)symaddr(g_x);
    float* p_y     = (float*)symaddr(g_y);
    float* p_tmpk  = (float*)symaddr(g_tmpk);
    float* p_enct  = (float*)symaddr(g_enct);
    float* p_IL    = (float*)symaddr(g_IL);
    float* p_pm    = (float*)symaddr(g_pm);
    float* p_ps    = (float*)symaddr(g_ps);
    float* p_tgt   = (float*)symaddr(g_tgtlog);
    float* p_rmax  = (float*)symaddr(g_rmax);
    float* p_rsum  = (float*)symaddr(g_rsum);
    float* p_msig  = (float*)symaddr(g_msig);

    bf16* pb_core = (bf16*)symaddr(b_core);
    bf16* pb_r    = (bf16*)symaddr(b_r);
    bf16* pb_rkall= (bf16*)symaddr(b_rkall);
    bf16* pb_x    = (bf16*)symaddr(b_x);
    bf16* pb_y    = (bf16*)symaddr(b_y);
    bf16* pb_vec  = (bf16*)symaddr(b_vec);
    bf16* pb_enct = (bf16*)symaddr(b_enct);
    bf16* pb_h    = (bf16*)symaddr(b_h);
    bf16* pb_outb = (bf16*)symaddr(b_outb);
    bf16* pb_cpyh = (bf16*)symaddr(b_copyhb);
    bf16* pb_heads= (bf16*)symaddr(b_heads);
    bf16* pb_kvall= (bf16*)symaddr(b_kvall);
    bf16* pb_q2   = (bf16*)symaddr(b_q2);

    bf16* pw_qkv = (bf16*)symaddr(w_qkv);
    bf16* pw_r   = (bf16*)symaddr(w_r);
    bf16* pw_o   = (bf16*)symaddr(w_o);
    bf16* pw_kv  = (bf16*)symaddr(w_kv);
    bf16* pw_q   = (bf16*)symaddr(w_q);
    bf16* pw_io  = (bf16*)symaddr(w_io);
    bf16* pw_f1  = (bf16*)symaddr(w_f1);
    bf16* pw_f2  = (bf16*)symaddr(w_f2);
    bf16* pw_emb = (bf16*)symaddr(w_emb);
    bf16* pw_out = (bf16*)symaddr(w_out);
    bf16* pw_cp  = (bf16*)symaddr(w_copy);

    cudaFuncSetAttribute(sgemm_bf, cudaFuncAttributeMaxDynamicSharedMemorySize, SMEMSZ);
    cudaFuncSetAttribute(sgemm_vocab, cudaFuncAttributeMaxDynamicSharedMemorySize, SMEMSZ);
    cudaFuncSetAttribute(fused_self_attn, cudaFuncAttributeMaxDynamicSharedMemorySize, SMEM_ATT);
    cudaFuncSetAttribute(fused_cross_attn, cudaFuncAttributeMaxDynamicSharedMemorySize, SMEM_XATT);

    static cudaStream_t s2 = nullptr;
    static cudaEvent_t evFork = nullptr, evJoin = nullptr;
    if (!s2) {
        cudaStreamCreateWithFlags(&s2, cudaStreamNonBlocking);
        cudaEventCreateWithFlags(&evFork, cudaEventDisableTiming);
        cudaEventCreateWithFlags(&evJoin, cudaEventDisableTiming);
    }

    cvtS(r_w,    pw_r,   (size_t)LL*DD*DD, 0);
    cvtS(kv_w,   pw_kv,  (size_t)LL*2*DD*DD, 0);
    cvtS(qkv_w,  pw_qkv, (size_t)LL*3*DD*DD, 0);

    cudaEventRecord(evFork, 0);
    cudaStreamWaitEvent(s2, evFork, 0);
    cvtS(o_w,    pw_o,   (size_t)LL*DD*DD, s2);
    cvtS(q_w,    pw_q,   (size_t)LL*DD*DD, s2);
    cvtS(io_w,   pw_io,  (size_t)LL*DD*DD, s2);
    cvtS(ffn_w1, pw_f1,  (size_t)LL*FF_*DD, s2);
    cvtS(ffn_w2, pw_f2,  (size_t)LL*DD*FF_, s2);
    cvtS(word_emb, pw_emb, (size_t)VV*DD, s2);
    cvtS(out_w,  pw_out, (size_t)DD*DD, s2);
    cvtS(copy_w, pw_cp,  (size_t)DD*DD, s2);
    cudaEventRecord(evJoin, s2);

    pos_emb_kernel<<<SS, 256>>>(p_r, pb_r);
    embed_kernel<<<TT, 256>>>(decode_input, word_emb, p_core, pb_core);
    transpose_enc<<<TE, 256>>>(encoder_rep, p_enct, pb_enct);

    sgemm_bf<<<dim3(LL*DD/128, SS/128), 256, SMEMSZ>>>(pb_r, pw_r, nullptr, pb_rkall,
        nullptr, DD, DD, DD, LL*DD, 0, 1, 0, 0, 0, 0);
    sgemm_bf<<<dim3(LL*2*DD/128, TE/128), 256, SMEMSZ>>>(pb_enct, pw_kv, nullptr, pb_kvall,
        nullptr, DD, DD, DD, LL*2*DD, 0, 1, 0, 0, 0, 0);

    bool joined = false;
    for (int l = 0; l < LL; l++) {
        sgemm_bf<<<dim3(3*DD/128, TT/128), 256, SMEMSZ>>>(pb_core, pw_qkv + (size_t)l*3*DD*DD,
            nullptr, pb_heads, nullptr, DD, DD, DD, 3*DD, 0, 1, 0, 0, 0, 0);
        fused_self_attn<<<BB*HH, 256, SMEM_ATT>>>(pb_heads, pb_rkall, pb_vec,
            rw_bias + (size_t)l*HH*DHH, rr_bias + (size_t)l*HH*DHH, l);
        if (!joined) { cudaStreamWaitEvent(0, evJoin, 0); joined = true; }
        sgemm_bf<<<dim3(DD/128, TT/128, 2), 256, SMEMSZ>>>(pb_vec, pw_o + (size_t)l*DD*DD,
            p_tmpk, nullptr, nullptr, DD, DD, DD, DD, 0, 2, (long long)TT*DD, 0, 0, 0);
        add_ln<<<TT, 256>>>(p_core, p_tmpk, 2, p_x, pb_x, ln1_g + l*DD, ln1_b + l*DD);

        // cross attention (fully fused, flash-style)
        sgemm_bf<<<dim3(DD/128, TT/128), 256, SMEMSZ>>>(pb_x, pw_q + (size_t)l*DD*DD,
            nullptr, pb_q2, nullptr, DD, DD, DD, DD, 0, 1, 0, 0, 0, 0);
        fused_cross_attn<<<BB*HH, 256, SMEM_XATT>>>(pb_q2, pb_kvall, input_mask, pb_vec, l);
        sgemm_bf<<<dim3(DD/128, TT/128, 2), 256, SMEMSZ>>>(pb_vec, pw_io + (size_t)l*DD*DD,
            p_tmpk, nullptr, nullptr, DD, DD, DD, DD, 0, 2, (long long)TT*DD, 0, 0, 0);
        add_ln<<<TT, 256>>>(p_x, p_tmpk, 2, p_y, pb_y, ln2_g + l*DD, ln2_b + l*DD);

        // FFN
        sgemm_bf<<<dim3(FF_/128, TT/128), 256, SMEMSZ>>>(pb_y, pw_f1 + (size_t)l*FF_*DD,
            nullptr, pb_h, ffn_b1 + (size_t)l*FF_, DD, DD, DD, FF_, 1, 1, 0, 0, 0, 0);
        sgemm_bf<<<dim3(DD/128, TT/128, 4), 256, SMEMSZ>>>(pb_h, pw_f2 + (size_t)l*DD*FF_,
            p_tmpk, nullptr, ffn_b2 + (size_t)l*DD, FF_, FF_, FF_, DD, 0, 4, (long long)TT*DD, 0, 0, 0);
        add_ln<<<TT, 256>>>(p_y, p_tmpk, 4, p_core, pb_core, ln3_g + l*DD, ln3_b + l*DD);
    }

    // output head
    sgemm_bf<<<dim3(DD/128, TT/128), 256, SMEMSZ>>>(pb_core, pw_out, nullptr, pb_outb, out_b,
        DD, DD, DD, DD, 0, 1, 0, 0, 0, 0);
    sgemm_vocab<<<dim3(NTILE, TT/128), 256, SMEMSZ>>>(pb_outb, pw_emb, decode_target,
        p_pm, p_ps, p_tgt, DD, DD, DD);
    stats_final<<<TT, 32>>>(p_pm, p_ps, p_rmax, p_rsum);

    // copy head
    sgemm_bf<<<dim3(DD/128, TT/128), 256, SMEMSZ>>>(pb_core, pw_cp, nullptr, pb_cpyh, copy_b,
        DD, DD, DD, DD, 0, 1, 0, 0, 0, 0);
    sgemm_bf<<<dim3(EE/128, SS/128, BB), 256, SMEMSZ>>>(pb_cpyh, pb_enct, p_IL, nullptr,
        nullptr, DD, BB*DD, BB*DD, BB*EE, 0, 1, 0,
        (long long)DD, (long long)DD, (long long)EE);
    softmax_il<<<TT, 512>>>(p_IL, input_mask);
    mode_kernel<<<TT, 256>>>(p_core, mode_w, mode_b, p_msig);
    zero_loss<<<1, 1>>>();
    loss_partial<<<TT/8, 256>>>(p_tgt, p_rmax, p_rsum, p_msig, p_IL, input_ids, decode_target);
    loss_final<<<1, BB>>>((float*)d_out);
}

// round 14
// speedup vs baseline: 1.0494x; 1.0494x over previous
#include <cuda_runtime.h>
#include <cuda_bf16.h>
#include <math.h>
#include <stdint.h>

// Problem dims
#define BB 8
#define SS 128
#define EE 512
#define DD 1024
#define HH 16
#define LL 4
#define VV 32000
#define DHH 64
#define FF_ 4096
#define TT (SS*BB)
#define TE (EE*BB)
#define NTILE (VV/128)
#define SCALE_ 0.125f
#define NEG_ (-1e30f)

typedef __nv_bfloat16 bf16;

// ---------------- scratch ----------------
__device__ float g_r[SS*DD];
__device__ float g_core[TT*DD];
__device__ float g_x[TT*DD];
__device__ float g_y[TT*DD];
__device__ float g_tmpk[4*TT*DD];
__device__ float g_enct[TE*DD];
__device__ float g_IL[TT*EE];
__device__ float g_pm[TT*256];
__device__ float g_ps[TT*256];
__device__ float g_tgtlog[TT];
__device__ float g_rmax[TT];
__device__ float g_rsum[TT];
__device__ float g_msig[TT];
__device__ float g_lossacc[2];

// bf16 activations
__device__ bf16 b_core[TT*DD];
__device__ bf16 b_r[SS*DD];
__device__ bf16 b_rkall[SS*LL*DD];
__device__ bf16 b_x[TT*DD];
__device__ bf16 b_y[TT*DD];
__device__ bf16 b_vec[TT*DD];
__device__ bf16 b_enct[TE*DD];
__device__ bf16 b_h[TT*FF_];
__device__ bf16 b_outb[TT*DD];
__device__ bf16 b_copyhb[TT*DD];
__device__ bf16 b_heads[TT*3*DD];
__device__ bf16 b_kvall[(size_t)TE*LL*2*DD];
__device__ bf16 b_q2[TT*DD];

// bf16 weights
__device__ bf16 w_qkv[LL*3*DD*DD];
__device__ bf16 w_r[LL*DD*DD];
__device__ bf16 w_o[LL*DD*DD];
__device__ bf16 w_kv[LL*2*DD*DD];
__device__ bf16 w_q[LL*DD*DD];
__device__ bf16 w_io[LL*DD*DD];
__device__ bf16 w_f1[LL*FF_*DD];
__device__ bf16 w_f2[LL*DD*FF_];
__device__ bf16 w_emb[(size_t)VV*DD];
__device__ bf16 w_out[DD*DD];
__device__ bf16 w_copy[DD*DD];

__device__ __forceinline__ uint32_t smem_u32(const void* p)
{
    return (uint32_t)__cvta_generic_to_shared(p);
}

// FFMA-only exp (no MUFU)
__device__ __forceinline__ float fexp(float x)
{
    x = fmaxf(x, -87.0f);
    float y = x * 1.4426950408889634f;
    float z = y + 12582912.0f;
    int   ki = __float_as_int(z) - 0x4B400000;
    float kf = z - 12582912.0f;
    float f = y - kf;
    float p = 0.00133336f;
    p = fmaf(p, f, 0.00961813f);
    p = fmaf(p, f, 0.05550411f);
    p = fmaf(p, f, 0.24022651f);
    p = fmaf(p, f, 0.69314718f);
    p = fmaf(p, f, 1.0f);
    return p * __int_as_float((ki + 127) << 23);
}

// ---------------- f32 -> bf16 conversion ----------------
__global__ void cvt_bf16(const float* __restrict__ src, bf16* __restrict__ dst, int n)
{
    int i = (blockIdx.x * 256 + threadIdx.x) * 4;
    if (i >= n) return;
    float4 v = *reinterpret_cast<const float4*>(src + i);
    uint32_t lo = ((uint32_t)__bfloat16_as_ushort(__float2bfloat16_rn(v.y)) << 16)
                | (uint32_t)__bfloat16_as_ushort(__float2bfloat16_rn(v.x));
    uint32_t hi = ((uint32_t)__bfloat16_as_ushort(__float2bfloat16_rn(v.w)) << 16)
                | (uint32_t)__bfloat16_as_ushort(__float2bfloat16_rn(v.z));
    *reinterpret_cast<uint2*>(dst + i) = make_uint2(lo, hi);
}

// 3-stage cp.async pipeline, 128x128 block (R12 config — best known)
#define SMEMSZ (3*2*128*40*2)

__global__ __launch_bounds__(256, 2)
void sgemm_bf(const bf16* __restrict__ A, const bf16* __restrict__ Bw,
              float* __restrict__ Cf, bf16* __restrict__ Cb,
              const float* __restrict__ bias,
              int K, int lda, int ldb, int ldc, int act, int ksplit,
              long long partStride,
              long long aBS, long long bBS, long long cBS)
{
    extern __shared__ bf16 ds[];
    bf16* AsB = ds;
    bf16* BsB = ds + 3*128*40;

    int tid = threadIdx.x;
    int warp = tid >> 5, lane = tid & 31;
    int warp_m = warp >> 1;
    int warp_n = warp & 1;
    int rowA0 = blockIdx.y * 128;
    int colB0 = blockIdx.x * 128;

    long long zb = (ksplit == 1) ? (long long)blockIdx.z : 0;
    const bf16* Az = A + zb * aBS;
    const bf16* Bz = Bw + zb * bBS;

    int Kloc = K / ksplit;
    int kgbase = (ksplit > 1) ? blockIdx.z * Kloc : 0;

    int ldrow = tid >> 1;
    int ldkoff = (tid & 1) * 16;

    float c[2][8][4];
#pragma unroll
    for (int mi = 0; mi < 2; mi++)
#pragma unroll
        for (int ni = 0; ni < 8; ni++)
#pragma unroll
            for (int r = 0; r < 4; r++) c[mi][ni][r] = 0.f;

    const bf16* Agp = &Az[(size_t)(rowA0 + ldrow) * lda + kgbase + ldkoff];
    const bf16* Bgp = &Bz[(size_t)(colB0 + ldrow) * ldb + kgbase + ldkoff];

    int nk = Kloc >> 5;
#pragma unroll
    for (int s = 0; s < 2; s++) {
        bf16* as = AsB + s * (128*40);
        bf16* bs = BsB + s * (128*40);
        uint32_t sa = smem_u32(as + ldrow * 40 + ldkoff);
        uint32_t sb = smem_u32(bs + ldrow * 40 + ldkoff);
        const bf16* ag = Agp + s * 32;
        const bf16* bg = Bgp + s * 32;
        asm volatile("cp.async.ca.shared.global [%0], [%1], 16;\n"
                     "cp.async.ca.shared.global [%2], [%3], 16;\n"
                     "cp.async.ca.shared.global [%4], [%5], 16;\n"
                     "cp.async.ca.shared.global [%6], [%7], 16;\n"
                     :: "r"(sa), "l"(ag), "r"(sa + 16), "l"(ag + 8),
                        "r"(sb), "l"(bg), "r"(sb + 16), "l"(bg + 8));
        asm volatile("cp.async.commit_group;");
    }

    for (int kt = 0; kt < nk; kt++) {
        asm volatile("cp.async.wait_group 1;");
        __syncthreads();
        int pf = kt + 2;
        if (pf < nk) {
            int sbuf = pf - (pf / 3) * 3;
            bf16* as = AsB + sbuf * (128*40);
            bf16* bs = BsB + sbuf * (128*40);
            uint32_t sa = smem_u32(as + ldrow * 40 + ldkoff);
            uint32_t sb = smem_u32(bs + ldrow * 40 + ldkoff);
            const bf16* ag = Agp + pf * 32;
            const bf16* bg = Bgp + pf * 32;
            asm volatile("cp.async.ca.shared.global [%0], [%1], 16;\n"
                         "cp.async.ca.shared.global [%2], [%3], 16;\n"
                         "cp.async.ca.shared.global [%4], [%5], 16;\n"
                         "cp.async.ca.shared.global [%6], [%7], 16;\n"
                         :: "r"(sa), "l"(ag), "r"(sa + 16), "l"(ag + 8),
                            "r"(sb), "l"(bg), "r"(sb + 16), "l"(bg + 8));
        }
        asm volatile("cp.async.commit_group;");

        int cbuf = kt - (kt / 3) * 3;
        bf16* as = AsB + cbuf * (128*40);
        bf16* bs = BsB + cbuf * (128*40);
#pragma unroll
        for (int ks = 0; ks < 2; ks++) {
            int k0 = ks * 16;
            uint32_t a[2][4];
#pragma unroll
            for (int mi = 0; mi < 2; mi++) {
                int m = warp_m * 32 + mi * 16 + (lane & 15);
                int kc = k0 + ((lane >> 4) << 3);
                uint32_t addr = smem_u32(as + m * 40 + kc);
                asm volatile("ldmatrix.sync.aligned.m8n8.x4.shared.b16 {%0,%1,%2,%3}, [%4];"
                             : "=r"(a[mi][0]), "=r"(a[mi][1]), "=r"(a[mi][2]), "=r"(a[mi][3])
                             : "r"(addr));
            }
            uint32_t b[8][2];
#pragma unroll
            for (int nt = 0; nt < 4; nt++) {
                int n = warp_n * 64 + nt * 16 + (lane & 7) + ((lane >> 4) << 3);
                int kc = k0 + (((lane >> 3) & 1) << 3);
                uint32_t addr = smem_u32(bs + n * 40 + kc);
                asm volatile("ldmatrix.sync.aligned.m8n8.x4.shared.b16 {%0,%1,%2,%3}, [%4];"
                             : "=r"(b[nt*2][0]), "=r"(b[nt*2][1]),
                               "=r"(b[nt*2+1][0]), "=r"(b[nt*2+1][1])
                             : "r"(addr));
            }
#pragma unroll
            for (int mi = 0; mi < 2; mi++)
#pragma unroll
                for (int ni = 0; ni < 8; ni++) {
                    asm volatile(
                        "mma.sync.aligned.m16n8k16.row.col.f32.bf16.bf16.f32 "
                        "{%0,%1,%2,%3}, {%4,%5,%6,%7}, {%8,%9}, {%0,%1,%2,%3};\n"
                        : "+f"(c[mi][ni][0]), "+f"(c[mi][ni][1]),
                          "+f"(c[mi][ni][2]), "+f"(c[mi][ni][3])
                        : "r"(a[mi][0]), "r"(a[mi][1]), "r"(a[mi][2]), "r"(a[mi][3]),
                          "r"(b[ni][0]), "r"(b[ni][1]));
                }
        }
    }

    bool addbias = (bias != nullptr) && (ksplit == 1 || blockIdx.z == 0);
    float* Cfz = Cf ? (Cf + (ksplit > 1 ? (size_t)blockIdx.z * partStride : (size_t)zb * cBS)) : nullptr;
    bf16*  Cbz = Cb ? (Cb + (size_t)zb * cBS) : nullptr;
#pragma unroll
    for (int mi = 0; mi < 2; mi++) {
        int row0 = rowA0 + warp_m * 32 + mi * 16 + (lane >> 2);
#pragma unroll
        for (int ni = 0; ni < 8; ni++) {
            int col = colB0 + warp_n * 64 + ni * 8 + (lane & 3) * 2;
            float bv0 = 0.f, bv1 = 0.f;
            if (addbias) { bv0 = bias[col]; bv1 = bias[col + 1]; }
#pragma unroll
            for (int half = 0; half < 2; half++) {
                int gm = row0 + half * 8;
                float v0 = c[mi][ni][half * 2 + 0] + bv0;
                float v1 = c[mi][ni][half * 2 + 1] + bv1;
                if (ksplit > 1) {
                    Cfz[(size_t)gm * ldc + col]     = v0;
                    Cfz[(size_t)gm * ldc + col + 1] = v1;
                } else {
                    if (act == 1) {
                        v0 = 0.5f * v0 * (1.0f + erff(v0 * 0.70710678118654752f));
                        v1 = 0.5f * v1 * (1.0f + erff(v1 * 0.70710678118654752f));
                    }
                    if (Cfz) {
                        Cfz[(size_t)gm * ldc + col]     = v0;
                        Cfz[(size_t)gm * ldc + col + 1] = v1;
                    }
                    if (Cbz) {
                        uint32_t pk = ((uint32_t)__bfloat16_as_ushort(__float2bfloat16_rn(v1)) << 16)
                                    | (uint32_t)__bfloat16_as_ushort(__float2bfloat16_rn(v0));
                        *reinterpret_cast<uint32_t*>(&Cbz[(size_t)gm * ldc + col]) = pk;
                    }
                }
            }
        }
    }
}

// ======== fully fused self-attention ========
#define SMEM_ATT (5*128*72*2)
__global__ __launch_bounds__(256, 1)
void fused_self_attn(const bf16* __restrict__ heads, const bf16* __restrict__ rkall,
                     bf16* __restrict__ vecOut,
                     const float* __restrict__ rwb, const float* __restrict__ rrb,
                     int layer)
{
    extern __shared__ bf16 dsA[];
    bf16* vS   = dsA;
    bf16* regA = dsA + 128*72;
    bf16* qrw  = regA;
    bf16* qrr  = regA + 128*72;
    bf16* kS   = regA + 2*128*72;
    bf16* rkS  = regA + 3*128*72;
    float* bdS = (float*)regA;
    bf16*  PS  = regA;

    __shared__ float rowm[128][2];
    __shared__ float rowsum[128][2];

    int z = blockIdx.x;
    int h = z % HH, b = z / HH;
    int tid = threadIdx.x;
    int warp = tid >> 5, lane = tid & 31;
    int warp_m = warp >> 1, warp_n = warp & 1;
    int gid = lane >> 2, tig = lane & 3;

    {
        int row = tid >> 1;
        int koff = (tid & 1) * 32;
        const bf16* qg  = heads + (size_t)b*3*DD + (size_t)h*DHH + (size_t)row*(BB*3*DD) + koff;
        const bf16* kg  = qg + DD;
        const bf16* vg  = qg + 2*DD;
        const bf16* rkg = rkall + (size_t)layer*DD + (size_t)h*DHH + (size_t)row*(LL*DD) + koff;
        const float* rwh = rwb + h*DHH + koff;
        const float* rrh = rrb + h*DHH + koff;
#pragma unroll
        for (int j = 0; j < 4; j++) {
            bf16 tq[8], trw[8], trr[8];
            *reinterpret_cast<uint4*>(tq) = *reinterpret_cast<const uint4*>(qg + j*8);
#pragma unroll
            for (int e = 0; e < 8; e++) {
                float qv = __bfloat162float(tq[e]);
                trw[e] = __float2bfloat16_rn(qv + rwh[j*8+e]);
                trr[e] = __float2bfloat16_rn(qv + rrh[j*8+e]);
            }
            *reinterpret_cast<uint4*>(&qrw[row*72 + koff + j*8]) = *reinterpret_cast<uint4*>(trw);
            *reinterpret_cast<uint4*>(&qrr[row*72 + koff + j*8]) = *reinterpret_cast<uint4*>(trr);
            *reinterpret_cast<uint4*>(&kS [row*72 + koff + j*8]) =
                *reinterpret_cast<const uint4*>(kg + j*8);
            *reinterpret_cast<uint4*>(&rkS[row*72 + koff + j*8]) =
                *reinterpret_cast<const uint4*>(rkg + j*8);
            *reinterpret_cast<uint4*>(&vS [row*72 + koff + j*8]) =
                *reinterpret_cast<const uint4*>(vg + j*8);
        }
    }
    __syncthreads();

    float cac[2][8][4], cbd[2][8][4];
#pragma unroll
    for (int mi = 0; mi < 2; mi++)
#pragma unroll
        for (int ni = 0; ni < 8; ni++)
#pragma unroll
            for (int r = 0; r < 4; r++) { cac[mi][ni][r] = 0.f; cbd[mi][ni][r] = 0.f; }

#pragma unroll
    for (int ks = 0; ks < 4; ks++) {
        int k0 = ks * 16;
        int m0 = warp_m * 32 + (lane & 15);
        int kcA = k0 + ((lane >> 4) << 3);
        int nI  = warp_n * 64 + (lane & 7) + ((lane >> 4) << 3);
        int kcB = k0 + (((lane >> 3) & 1) << 3);
        uint32_t a1[2][4], a2[2][4];
#pragma unroll
        for (int mi = 0; mi < 2; mi++) {
            uint32_t ad1 = smem_u32(qrw + (m0 + mi*16)*72 + kcA);
            uint32_t ad2 = smem_u32(qrr + (m0 + mi*16)*72 + kcA);
            asm volatile("ldmatrix.sync.aligned.m8n8.x4.shared.b16 {%0,%1,%2,%3}, [%4];"
                         : "=r"(a1[mi][0]), "=r"(a1[mi][1]), "=r"(a1[mi][2]), "=r"(a1[mi][3])
                         : "r"(ad1));
            asm volatile("ldmatrix.sync.aligned.m8n8.x4.shared.b16 {%0,%1,%2,%3}, [%4];"
                         : "=r"(a2[mi][0]), "=r"(a2[mi][1]), "=r"(a2[mi][2]), "=r"(a2[mi][3])
                         : "r"(ad2));
        }
        uint32_t b1[8][2], b2[8][2];
#pragma unroll
        for (int nt = 0; nt < 4; nt++) {
            uint32_t bd1 = smem_u32(kS  + (nI + nt*16)*72 + kcB);
            uint32_t bd2 = smem_u32(rkS + (nI + nt*16)*72 + kcB);
            asm volatile("ldmatrix.sync.aligned.m8n8.x4.shared.b16 {%0,%1,%2,%3}, [%4];"
                         : "=r"(b1[nt*2][0]), "=r"(b1[nt*2][1]),
                           "=r"(b1[nt*2+1][0]), "=r"(b1[nt*2+1][1])
                         : "r"(bd1));
            asm volatile("ldmatrix.sync.aligned.m8n8.x4.shared.b16 {%0,%1,%2,%3}, [%4];"
                         : "=r"(b2[nt*2][0]), "=r"(b2[nt*2][1]),
                           "=r"(b2[nt*2+1][0]), "=r"(b2[nt*2+1][1])
                         : "r"(bd2));
        }
#pragma unroll
        for (int mi = 0; mi < 2; mi++)
#pragma unroll
            for (int ni = 0; ni < 8; ni++) {
                asm volatile("mma.sync.aligned.m16n8k16.row.col.f32.bf16.bf16.f32 "
                             "{%0,%1,%2,%3}, {%4,%5,%6,%7}, {%8,%9}, {%0,%1,%2,%3};\n"
                             : "+f"(cac[mi][ni][0]), "+f"(cac[mi][ni][1]),
                               "+f"(cac[mi][ni][2]), "+f"(cac[mi][ni][3])
                             : "r"(a1[mi][0]), "r"(a1[mi][1]), "r"(a1[mi][2]), "r"(a1[mi][3]),
                               "r"(b1[ni][0]), "r"(b1[ni][1]));
                asm volatile("mma.sync.aligned.m16n8k16.row.col.f32.bf16.bf16.f32 "
                             "{%0,%1,%2,%3}, {%4,%5,%6,%7}, {%8,%9}, {%0,%1,%2,%3};\n"
                             : "+f"(cbd[mi][ni][0]), "+f"(cbd[mi][ni][1]),
                               "+f"(cbd[mi][ni][2]), "+f"(cbd[mi][ni][3])
                             : "r"(a2[mi][0]), "r"(a2[mi][1]), "r"(a2[mi][2]), "r"(a2[mi][3]),
                               "r"(b2[ni][0]), "r"(b2[ni][1]));
            }
    }
    __syncthreads();

#pragma unroll
    for (int mi = 0; mi < 2; mi++) {
        int row0 = warp_m * 32 + mi * 16 + gid;
#pragma unroll
        for (int ni = 0; ni < 8; ni++) {
            int col = warp_n * 64 + ni * 8 + tig * 2;
#pragma unroll
            for (int half = 0; half < 2; half++) {
                int gm = row0 + half * 8;
                bdS[gm * 132 + col]     = cbd[mi][ni][half*2 + 0];
                bdS[gm * 132 + col + 1] = cbd[mi][ni][half*2 + 1];
            }
        }
    }
    __syncthreads();

#pragma unroll
    for (int mi = 0; mi < 2; mi++) {
#pragma unroll
        for (int half = 0; half < 2; half++) {
            int r = warp_m * 32 + mi * 16 + half * 8 + gid;
            float m = -1e30f;
#pragma unroll
            for (int ni = 0; ni < 8; ni++) {
#pragma unroll
                for (int e = 0; e < 2; e++) {
                    int j = warp_n * 64 + ni * 8 + tig * 2 + e;
                    float sc;
                    if (j > r) sc = NEG_;
                    else {
                        int f = r * SS + j + SS;
                        int qi = f / (SS + 1);
                        int cc = f - qi * (SS + 1);
                        float bdv = (cc > 0) ? bdS[qi * 132 + (cc - 1)] : 0.f;
                        sc = (cac[mi][ni][half*2 + e] + bdv) * SCALE_;
                    }
                    cac[mi][ni][half*2 + e] = sc;
                    m = fmaxf(m, sc);
                }
            }
#pragma unroll
            for (int o = 1; o <= 2; o <<= 1) m = fmaxf(m, __shfl_xor_sync(0xffffffffu, m, o));
            if (tig == 0) rowm[r][warp_n] = m;
        }
    }
    __syncthreads();

#pragma unroll
    for (int mi = 0; mi < 2; mi++) {
#pragma unroll
        for (int half = 0; half < 2; half++) {
            int r = warp_m * 32 + mi * 16 + half * 8 + gid;
            float m = fmaxf(rowm[r][0], rowm[r][1]);
            float s = 0.f;
#pragma unroll
            for (int ni = 0; ni < 8; ni++) {
#pragma unroll
                for (int e = 0; e < 2; e++) {
                    float ev = fexp(cac[mi][ni][half*2 + e] - m);
                    cac[mi][ni][half*2 + e] = ev;
                    s += ev;
                }
            }
#pragma unroll
            for (int o = 1; o <= 2; o <<= 1) s += __shfl_xor_sync(0xffffffffu, s, o);
            if (tig == 0) rowsum[r][warp_n] = s;
        }
    }
    __syncthreads();

#pragma unroll
    for (int mi = 0; mi < 2; mi++) {
#pragma unroll
        for (int half = 0; half < 2; half++) {
            int r = warp_m * 32 + mi * 16 + half * 8 + gid;
            float inv = 1.0f / (rowsum[r][0] + rowsum[r][1]);
#pragma unroll
            for (int ni = 0; ni < 8; ni++) {
                int col = warp_n * 64 + ni * 8 + tig * 2;
                uint32_t pk = ((uint32_t)__bfloat16_as_ushort(
                                  __float2bfloat16_rn(cac[mi][ni][half*2+1] * inv)) << 16)
                            | (uint32_t)__bfloat16_as_ushort(
                                  __float2bfloat16_rn(cac[mi][ni][half*2+0] * inv));
                *reinterpret_cast<uint32_t*>(&PS[r * 136 + col]) = pk;
            }
        }
    }
    __syncthreads();

    float c2[2][4][4];
#pragma unroll
    for (int mi = 0; mi < 2; mi++)
#pragma unroll
        for (int ni = 0; ni < 4; ni++)
#pragma unroll
            for (int r = 0; r < 4; r++) c2[mi][ni][r] = 0.f;

#pragma unroll
    for (int ks = 0; ks < 8; ks++) {
        int k0 = ks * 16;
        uint32_t a[2][4];
#pragma unroll
        for (int mi = 0; mi < 2; mi++) {
            int m = warp_m * 32 + mi * 16 + (lane & 15);
            int kc = k0 + ((lane >> 4) << 3);
            uint32_t addr = smem_u32(PS + m * 136 + kc);
            asm volatile("ldmatrix.sync.aligned.m8n8.x4.shared.b16 {%0,%1,%2,%3}, [%4];"
                         : "=r"(a[mi][0]), "=r"(a[mi][1]), "=r"(a[mi][2]), "=r"(a[mi][3])
                         : "r"(addr));
        }
        uint32_t bb[4][2];
#pragma unroll
        for (int nt = 0; nt < 2; nt++) {
            int kr = k0 + (lane & 15);
            int n = warp_n * 32 + nt * 16 + ((lane >> 4) << 3);
            uint32_t addr = smem_u32(vS + kr * 72 + n);
            asm volatile("ldmatrix.sync.aligned.m8n8.x4.trans.shared.b16 {%0,%1,%2,%3}, [%4];"
                         : "=r"(bb[nt*2][0]), "=r"(bb[nt*2][1]),
                           "=r"(bb[nt*2+1][0]), "=r"(bb[nt*2+1][1])
                         : "r"(addr));
        }
#pragma unroll
        for (int mi = 0; mi < 2; mi++)
#pragma unroll
            for (int ni = 0; ni < 4; ni++) {
                asm volatile("mma.sync.aligned.m16n8k16.row.col.f32.bf16.bf16.f32 "
                             "{%0,%1,%2,%3}, {%4,%5,%6,%7}, {%8,%9}, {%0,%1,%2,%3};\n"
                             : "+f"(c2[mi][ni][0]), "+f"(c2[mi][ni][1]),
                               "+f"(c2[mi][ni][2]), "+f"(c2[mi][ni][3])
                             : "r"(a[mi][0]), "r"(a[mi][1]), "r"(a[mi][2]), "r"(a[mi][3]),
                               "r"(bb[ni][0]), "r"(bb[ni][1]));
            }
    }

    bf16* outBase = vecOut + (size_t)b * DD + (size_t)h * DHH;
#pragma unroll
    for (int mi = 0; mi < 2; mi++) {
        int row0 = warp_m * 32 + mi * 16 + gid;
#pragma unroll
        for (int ni = 0; ni < 4; ni++) {
            int col = warp_n * 32 + ni * 8 + tig * 2;
#pragma unroll
            for (int half = 0; half < 2; half++) {
                int gm = row0 + half * 8;
                uint32_t pk = ((uint32_t)__bfloat16_as_ushort(__float2bfloat16_rn(c2[mi][ni][half*2+1])) << 16)
                            | (uint32_t)__bfloat16_as_ushort(__float2bfloat16_rn(c2[mi][ni][half*2+0]));
                *reinterpret_cast<uint32_t*>(&outBase[(size_t)gm * (BB*DD) + col]) = pk;
            }
        }
    }
}

// ======== fused cross-attention: flash-style over E=512 in 4 chunks of 128 ========
#define SMEM_XATT ((3*128*72 + 128*136)*2)
__global__ __launch_bounds__(256, 1)
void fused_cross_attn(const bf16* __restrict__ q2, const bf16* __restrict__ kvall,
                      const float* __restrict__ mask,
                      bf16* __restrict__ vecOut, int layer)
{
    extern __shared__ bf16 dsX[];
    bf16* qS = dsX;
    bf16* kS = dsX + 128*72;
    bf16* vS = dsX + 2*128*72;
    bf16* PS = dsX + 3*128*72;

    __shared__ float rowm[128][2];
    __shared__ float rowsum[128][2];
    __shared__ float maskS[128];

    int z = blockIdx.x;
    int h = z % HH, b = z / HH;
    int tid = threadIdx.x;
    int warp = tid >> 5, lane = tid & 31;
    int warp_m = warp >> 1, warp_n = warp & 1;
    int gid = lane >> 2, tig = lane & 3;
    int row = tid >> 1, koff = (tid & 1) * 32;

    {
        const bf16* qg = q2 + (size_t)b*DD + (size_t)h*DHH + (size_t)row*(BB*DD) + koff;
#pragma unroll
        for (int j = 0; j < 4; j++)
            *reinterpret_cast<uint4*>(&qS[row*72 + koff + j*8]) =
                *reinterpret_cast<const uint4*>(qg + j*8);
    }

    const bf16* kBase = kvall + (size_t)layer*2*DD + (size_t)b*(LL*2*DD) + (size_t)h*DHH;
    const bf16* vBase = kBase + DD;
    const long long kvRow = (long long)BB*LL*2*DD;

    float mstate[2][2], lstate[2][2];
#pragma unroll
    for (int mi = 0; mi < 2; mi++)
#pragma unroll
        for (int half = 0; half < 2; half++) { mstate[mi][half] = -1e30f; lstate[mi][half] = 0.f; }

    float c2[2][4][4];
#pragma unroll
    for (int mi = 0; mi < 2; mi++)
#pragma unroll
        for (int ni = 0; ni < 4; ni++)
#pragma unroll
            for (int r = 0; r < 4; r++) c2[mi][ni][r] = 0.f;

    for (int kc = 0; kc < 4; kc++) {
        {
            const bf16* kg = kBase + (size_t)(kc*128 + row) * kvRow + koff;
            const bf16* vg = vBase + (size_t)(kc*128 + row) * kvRow + koff;
#pragma unroll
            for (int j = 0; j < 4; j++) {
                *reinterpret_cast<uint4*>(&kS[row*72 + koff + j*8]) =
                    *reinterpret_cast<const uint4*>(kg + j*8);
                *reinterpret_cast<uint4*>(&vS[row*72 + koff + j*8]) =
                    *reinterpret_cast<const uint4*>(vg + j*8);
            }
            if (tid < 128) maskS[tid] = mask[b*EE + kc*128 + tid];
        }
        __syncthreads();

        float cs[2][8][4];
#pragma unroll
        for (int mi = 0; mi < 2; mi++)
#pragma unroll
            for (int ni = 0; ni < 8; ni++)
#pragma unroll
                for (int r = 0; r < 4; r++) cs[mi][ni][r] = 0.f;

#pragma unroll
        for (int ks = 0; ks < 4; ks++) {
            int k0 = ks * 16;
            uint32_t a[2][4];
#pragma unroll
            for (int mi = 0; mi < 2; mi++) {
                int m = warp_m * 32 + mi * 16 + (lane & 15);
                int kcc = k0 + ((lane >> 4) << 3);
                uint32_t addr = smem_u32(qS + m*72 + kcc);
                asm volatile("ldmatrix.sync.aligned.m8n8.x4.shared.b16 {%0,%1,%2,%3}, [%4];"
                             : "=r"(a[mi][0]), "=r"(a[mi][1]), "=r"(a[mi][2]), "=r"(a[mi][3])
                             : "r"(addr));
            }
            uint32_t bb[8][2];
#pragma unroll
            for (int nt = 0; nt < 4; nt++) {
                int n = warp_n * 64 + nt * 16 + (lane & 7) + ((lane >> 4) << 3);
                int kcc = k0 + (((lane >> 3) & 1) << 3);
                uint32_t addr = smem_u32(kS + n*72 + kcc);
                asm volatile("ldmatrix.sync.aligned.m8n8.x4.shared.b16 {%0,%1,%2,%3}, [%4];"
                             : "=r"(bb[nt*2][0]), "=r"(bb[nt*2][1]),
                               "=r"(bb[nt*2+1][0]), "=r"(bb[nt*2+1][1])
                             : "r"(addr));
            }
#pragma unroll
            for (int mi = 0; mi < 2; mi++)
#pragma unroll
                for (int ni = 0; ni < 8; ni++) {
                    asm volatile("mma.sync.aligned.m16n8k16.row.col.f32.bf16.bf16.f32 "
                                 "{%0,%1,%2,%3}, {%4,%5,%6,%7}, {%8,%9}, {%0,%1,%2,%3};\n"
                                 : "+f"(cs[mi][ni][0]), "+f"(cs[mi][ni][1]),
                                   "+f"(cs[mi][ni][2]), "+f"(cs[mi][ni][3])
                                 : "r"(a[mi][0]), "r"(a[mi][1]), "r"(a[mi][2]), "r"(a[mi][3]),
                                   "r"(bb[ni][0]), "r"(bb[ni][1]));
                }
        }

#pragma unroll
        for (int mi = 0; mi < 2; mi++) {
#pragma unroll
            for (int half = 0; half < 2; half++) {
                int r = warp_m * 32 + mi * 16 + half * 8 + gid;
                float m = -1e30f;
#pragma unroll
                for (int ni = 0; ni < 8; ni++) {
#pragma unroll
                    for (int e = 0; e < 2; e++) {
                        int j = warp_n * 64 + ni * 8 + tig * 2 + e;
                        float sc = cs[mi][ni][half*2 + e] * SCALE_
                                 + (1.0f - maskS[j]) * NEG_;
                        cs[mi][ni][half*2 + e] = sc;
                        m = fmaxf(m, sc);
                    }
                }
#pragma unroll
                for (int o = 1; o <= 2; o <<= 1) m = fmaxf(m, __shfl_xor_sync(0xffffffffu, m, o));
                if (tig == 0) rowm[r][warp_n] = m;
            }
        }
        __syncthreads();

        float scaleF[2][2], mnew[2][2];
#pragma unroll
        for (int mi = 0; mi < 2; mi++) {
#pragma unroll
            for (int half = 0; half < 2; half++) {
                int r = warp_m * 32 + mi * 16 + half * 8 + gid;
                float mc = fmaxf(rowm[r][0], rowm[r][1]);
                float mn = fmaxf(mstate[mi][half], mc);
                scaleF[mi][half] = fexp(mstate[mi][half] - mn);
                mnew[mi][half] = mn;
                float s = 0.f;
#pragma unroll
                for (int ni = 0; ni < 8; ni++) {
#pragma unroll
                    for (int e = 0; e < 2; e++) {
                        float ev = fexp(cs[mi][ni][half*2 + e] - mn);
                        cs[mi][ni][half*2 + e] = ev;
                        s += ev;
                    }
                }
#pragma unroll
                for (int o = 1; o <= 2; o <<= 1) s += __shfl_xor_sync(0xffffffffu, s, o);
                if (tig == 0) rowsum[r][warp_n] = s;
            }
        }
        __syncthreads();

#pragma unroll
        for (int mi = 0; mi < 2; mi++) {
#pragma unroll
            for (int half = 0; half < 2; half++) {
                int r = warp_m * 32 + mi * 16 + half * 8 + gid;
                float sc = scaleF[mi][half];
                lstate[mi][half] = lstate[mi][half] * sc + rowsum[r][0] + rowsum[r][1];
                mstate[mi][half] = mnew[mi][half];
#pragma unroll
                for (int ni = 0; ni < 4; ni++) {
                    c2[mi][ni][half*2 + 0] *= sc;
                    c2[mi][ni][half*2 + 1] *= sc;
                }
#pragma unroll
                for (int ni = 0; ni < 8; ni++) {
                    int col = warp_n * 64 + ni * 8 + tig * 2;
                    uint32_t pk = ((uint32_t)__bfloat16_as_ushort(
                                      __float2bfloat16_rn(cs[mi][ni][half*2+1])) << 16)
                                | (uint32_t)__bfloat16_as_ushort(
                                      __float2bfloat16_rn(cs[mi][ni][half*2+0]));
                    *reinterpret_cast<uint32_t*>(&PS[r * 136 + col]) = pk;
                }
            }
        }
        __syncthreads();

#pragma unroll
        for (int ks = 0; ks < 8; ks++) {
            int k0 = ks * 16;
            uint32_t a[2][4];
#pragma unroll
            for (int mi = 0; mi < 2; mi++) {
                int m = warp_m * 32 + mi * 16 + (lane & 15);
                int kcc = k0 + ((lane >> 4) << 3);
                uint32_t addr = smem_u32(PS + m * 136 + kcc);
                asm volatile("ldmatrix.sync.aligned.m8n8.x4.shared.b16 {%0,%1,%2,%3}, [%4];"
                             : "=r"(a[mi][0]), "=r"(a[mi][1]), "=r"(a[mi][2]), "=r"(a[mi][3])
                             : "r"(addr));
            }
            uint32_t bb[4][2];
#pragma unroll
            for (int nt = 0; nt < 2; nt++) {
                int kr = k0 + (lane & 15);
                int n = warp_n * 32 + nt * 16 + ((lane >> 4) << 3);
                uint32_t addr = smem_u32(vS + kr * 72 + n);
                asm volatile("ldmatrix.sync.aligned.m8n8.x4.trans.shared.b16 {%0,%1,%2,%3}, [%4];"
                             : "=r"(bb[nt*2][0]), "=r"(bb[nt*2][1]),
                               "=r"(bb[nt*2+1][0]), "=r"(bb[nt*2+1][1])
                             : "r"(addr));
            }
#pragma unroll
            for (int mi = 0; mi < 2; mi++)
#pragma unroll
                for (int ni = 0; ni < 4; ni++) {
                    asm volatile("mma.sync.aligned.m16n8k16.row.col.f32.bf16.bf16.f32 "
                                 "{%0,%1,%2,%3}, {%4,%5,%6,%7}, {%8,%9}, {%0,%1,%2,%3};\n"
                                 : "+f"(c2[mi][ni][0]), "+f"(c2[mi][ni][1]),
                                   "+f"(c2[mi][ni][2]), "+f"(c2[mi][ni][3])
                                 : "r"(a[mi][0]), "r"(a[mi][1]), "r"(a[mi][2]), "r"(a[mi][3]),
                                   "r"(bb[ni][0]), "r"(bb[ni][1]));
                }
        }
        __syncthreads();
    }

    bf16* outBase = vecOut + (size_t)b * DD + (size_t)h * DHH;
#pragma unroll
    for (int mi = 0; mi < 2; mi++) {
        int row0 = warp_m * 32 + mi * 16 + gid;
#pragma unroll
        for (int ni = 0; ni < 4; ni++) {
            int col = warp_n * 32 + ni * 8 + tig * 2;
#pragma unroll
            for (int half = 0; half < 2; half++) {
                int gm = row0 + half * 8;
                float inv = 1.0f / lstate[mi][half];
                uint32_t pk = ((uint32_t)__bfloat16_as_ushort(
                                  __float2bfloat16_rn(c2[mi][ni][half*2+1] * inv)) << 16)
                            | (uint32_t)__bfloat16_as_ushort(
                                  __float2bfloat16_rn(c2[mi][ni][half*2+0] * inv));
                *reinterpret_cast<uint32_t*>(&outBase[(size_t)gm * (BB*DD) + col]) = pk;
            }
        }
    }
}

// ======== vocab-logits GEMM with fused stats + tgt extract (3-stage) ========
__global__ __launch_bounds__(256, 2)
void sgemm_vocab(const bf16* __restrict__ A, const bf16* __restrict__ Bw,
                 const int* __restrict__ decode_target,
                 float* __restrict__ pm, float* __restrict__ ps,
                 float* __restrict__ tgtlog,
                 int K, int lda, int ldb)
{
    extern __shared__ bf16 ds[];
    bf16* AsB = ds;
    bf16* BsB = ds + 3*128*40;

    int tid = threadIdx.x;
    int warp = tid >> 5, lane = tid & 31;
    int warp_m = warp >> 1;
    int warp_n = warp & 1;
    int rowA0 = blockIdx.y * 128;
    int colB0 = blockIdx.x * 128;

    int ldrow = tid >> 1;
    int ldkoff = (tid & 1) * 16;

    float c[2][8][4];
#pragma unroll
    for (int mi = 0; mi < 2; mi++)
#pragma unroll
        for (int ni = 0; ni < 8; ni++)
#pragma unroll
            for (int r = 0; r < 4; r++) c[mi][ni][r] = 0.f;

    const bf16* Agp = &A[(size_t)(rowA0 + ldrow) * lda + ldkoff];
    const bf16* Bgp = &Bw[(size_t)(colB0 + ldrow) * ldb + ldkoff];

    int nk = K >> 5;
#pragma unroll
    for (int s = 0; s < 2; s++) {
        bf16* as = AsB + s * (128*40);
        bf16* bs = BsB + s * (128*40);
        uint32_t sa = smem_u32(as + ldrow * 40 + ldkoff);
        uint32_t sb = smem_u32(bs + ldrow * 40 + ldkoff);
        const bf16* ag = Agp + s * 32;
        const bf16* bg = Bgp + s * 32;
        asm volatile("cp.async.ca.shared.global [%0], [%1], 16;\n"
                     "cp.async.ca.shared.global [%2], [%3], 16;\n"
                     "cp.async.ca.shared.global [%4], [%5], 16;\n"
                     "cp.async.ca.shared.global [%6], [%7], 16;\n"
                     :: "r"(sa), "l"(ag), "r"(sa + 16), "l"(ag + 8),
                        "r"(sb), "l"(bg), "r"(sb + 16), "l"(bg + 8));
        asm volatile("cp.async.commit_group;");
    }

    for (int kt = 0; kt < nk; kt++) {
        asm volatile("cp.async.wait_group 1;");
        __syncthreads();
        int pf = kt + 2;
        if (pf < nk) {
            int sbuf = pf - (pf / 3) * 3;
            bf16* as = AsB + sbuf * (128*40);
            bf16* bs = BsB + sbuf * (128*40);
            uint32_t sa = smem_u32(as + ldrow * 40 + ldkoff);
            uint32_t sb = smem_u32(bs + ldrow * 40 + ldkoff);
            const bf16* ag = Agp + pf * 32;
            const bf16* bg = Bgp + pf * 32;
            asm volatile("cp.async.ca.shared.global [%0], [%1], 16;\n"
                         "cp.async.ca.shared.global [%2], [%3], 16;\n"
                         "cp.async.ca.shared.global [%4], [%5], 16;\n"
                         "cp.async.ca.shared.global [%6], [%7], 16;\n"
                         :: "r"(sa), "l"(ag), "r"(sa + 16), "l"(ag + 8),
                            "r"(sb), "l"(bg), "r"(sb + 16), "l"(bg + 8));
        }
        asm volatile("cp.async.commit_group;");

        int cbuf = kt - (kt / 3) * 3;
        bf16* as = AsB + cbuf * (128*40);
        bf16* bs = BsB + cbuf * (128*40);
#pragma unroll
        for (int ks = 0; ks < 2; ks++) {
            int k0 = ks * 16;
            uint32_t a[2][4];
#pragma unroll
            for (int mi = 0; mi < 2; mi++) {
                int m = warp_m * 32 + mi * 16 + (lane & 15);
                int kc = k0 + ((lane >> 4) << 3);
                uint32_t addr = smem_u32(as + m * 40 + kc);
                asm volatile("ldmatrix.sync.aligned.m8n8.x4.shared.b16 {%0,%1,%2,%3}, [%4];"
                             : "=r"(a[mi][0]), "=r"(a[mi][1]), "=r"(a[mi][2]), "=r"(a[mi][3])
                             : "r"(addr));
            }
            uint32_t b[8][2];
#pragma unroll
            for (int nt = 0; nt < 4; nt++) {
                int n = warp_n * 64 + nt * 16 + (lane & 7) + ((lane >> 4) << 3);
                int kc = k0 + (((lane >> 3) & 1) << 3);
                uint32_t addr = smem_u32(bs + n * 40 + kc);
                asm volatile("ldmatrix.sync.aligned.m8n8.x4.shared.b16 {%0,%1,%2,%3}, [%4];"
                             : "=r"(b[nt*2][0]), "=r"(b[nt*2][1]),
                               "=r"(b[nt*2+1][0]), "=r"(b[nt*2+1][1])
                             : "r"(addr));
            }
#pragma unroll
            for (int mi = 0; mi < 2; mi++)
#pragma unroll
                for (int ni = 0; ni < 8; ni++) {
                    asm volatile(
                        "mma.sync.aligned.m16n8k16.row.col.f32.bf16.bf16.f32 "
                        "{%0,%1,%2,%3}, {%4,%5,%6,%7}, {%8,%9}, {%0,%1,%2,%3};\n"
                        : "+f"(c[mi][ni][0]), "+f"(c[mi][ni][1]),
                          "+f"(c[mi][ni][2]), "+f"(c[mi][ni][3])
                        : "r"(a[mi][0]), "r"(a[mi][1]), "r"(a[mi][2]), "r"(a[mi][3]),
                          "r"(b[ni][0]), "r"(b[ni][1]));
                }
        }
    }

    __shared__ int   stgt[128];
    __shared__ float smx[128][2];
    __shared__ float ssx[128][2];
    if (tid < 128) {
        int grow = rowA0 + tid;
        stgt[tid] = decode_target[(grow & (BB-1)) * SS + (grow >> 3)];
    }
    __syncthreads();

    int gid = lane >> 2, tig = lane & 3;
#pragma unroll
    for (int mi = 0; mi < 2; mi++) {
#pragma unroll
        for (int half = 0; half < 2; half++) {
            int rl = warp_m * 32 + mi * 16 + half * 8 + gid;
            int tgt_c = stgt[rl] - colB0;
            float m = -1e30f, s = 0.f;
#pragma unroll
            for (int ni = 0; ni < 8; ni++) {
#pragma unroll
                for (int e = 0; e < 2; e++) {
                    float v = c[mi][ni][half * 2 + e];
                    int coll = warp_n * 64 + ni * 8 + tig * 2 + e;
                    if (coll == tgt_c) tgtlog[rowA0 + rl] = v;
                    if (v <= m) s += fexp(v - m);
                    else { s = s * fexp(m - v) + 1.0f; m = v; }
                }
            }
#pragma unroll
            for (int o = 1; o <= 2; o <<= 1) {
                float mo = __shfl_xor_sync(0xffffffffu, m, o);
                float so = __shfl_xor_sync(0xffffffffu, s, o);
                float M = fmaxf(m, mo);
                s = s * fexp(m - M) + so * fexp(mo - M);
                m = M;
            }
            if (tig == 0) { smx[rl][warp_n] = m; ssx[rl][warp_n] = s; }
        }
    }
    __syncthreads();
    if (tid < 128) {
        float m0 = smx[tid][0], s0 = ssx[tid][0];
        float m1 = smx[tid][1], s1 = ssx[tid][1];
        float M = fmaxf(m0, m1);
        float S = s0 * fexp(m0 - M) + s1 * fexp(m1 - M);
        pm[(size_t)(rowA0 + tid) * 256 + blockIdx.x] = M;
        ps[(size_t)(rowA0 + tid) * 256 + blockIdx.x] = S;
    }
}

__global__ void stats_final(const float* __restrict__ pm, const float* __restrict__ ps,
                            float* __restrict__ rmax, float* __restrict__ rsum)
{
    int t = blockIdx.x;
    int lane = threadIdx.x;
    float m = -1e30f, s = 0.f;
    for (int i = lane; i < NTILE; i += 32) {
        float mi = pm[(size_t)t * 256 + i];
        float si = ps[(size_t)t * 256 + i];
        float M = fmaxf(m, mi);
        s = s * fexp(m - M) + si * fexp(mi - M);
        m = M;
    }
#pragma unroll
    for (int o = 16; o > 0; o >>= 1) {
        float mo = __shfl_xor_sync(0xffffffffu, m, o);
        float so = __shfl_xor_sync(0xffffffffu, s, o);
        float M = fmaxf(m, mo);
        s = s * fexp(m - M) + so * fexp(mo - M);
        m = M;
    }
    if (lane == 0) { rmax[t] = m; rsum[t] = s; }
}

// ---------------- misc small kernels --------------------------------------------------
__global__ void pos_emb_kernel(float* __restrict__ r, bf16* __restrict__ rb)
{
    int i = blockIdx.x;
    float pos = (float)(SS - 1 - i);
    const float LOG1E4 = 9.210340371976184f;
    for (int d = threadIdx.x; d < DD; d += 256) {
        int j = (d < DD/2) ? d : d - DD/2;
        float invf = expf(-((float)j / (DD/2)) * LOG1E4);
        float a = pos * invf;
        float v = (d < DD/2) ? sinf(a) : cosf(a);
        r[i * DD + d] = v;
        rb[i * DD + d] = __float2bfloat16_rn(v);
    }
}

__global__ void embed_kernel(const int* __restrict__ dec, const float* __restrict__ emb,
                             float* __restrict__ core, bf16* __restrict__ coreb)
{
    int t = blockIdx.x;
    int b = t & (BB-1), s = t >> 3;
    int id = dec[b * SS + s];
    const float* src = emb + (size_t)id * DD;
    for (int d = threadIdx.x; d < DD; d += 256) {
        float v = src[d];
        core[(size_t)t * DD + d] = v;
        coreb[(size_t)t * DD + d] = __float2bfloat16_rn(v);
    }
}

__global__ void transpose_enc(const float* __restrict__ enc, float* __restrict__ enct,
                              bf16* __restrict__ enctb)
{
    int t = blockIdx.x;
    int b = t & (BB-1), e = t >> 3;
    const float* src = enc + ((size_t)b * EE + e) * DD;
    for (int d = threadIdx.x; d < DD; d += 256) {
        float v = src[d];
        enct[(size_t)t * DD + d] = v;
        enctb[(size_t)t * DD + d] = __float2bfloat16_rn(v);
    }
}

__device__ __forceinline__ float warp_max(float v)
{
#pragma unroll
    for (int o = 16; o > 0; o >>= 1) v = fmaxf(v, __shfl_xor_sync(0xffffffffu, v, o));
    return v;
}
__device__ __forceinline__ float warp_sum(float v)
{
#pragma unroll
    for (int o = 16; o > 0; o >>= 1) v += __shfl_xor_sync(0xffffffffu, v, o);
    return v;
}

__global__ void softmax_il(float* __restrict__ IL, const float* __restrict__ mask)
{
    int t = blockIdx.x;
    int b = t & (BB - 1);
    int k = threadIdx.x;
    int wid = k >> 5, lane = k & 31;
    float v = IL[(size_t)t * EE + k] + (1.0f - mask[b * EE + k]) * NEG_;
    __shared__ float red[16];
    float m = warp_max(v);
    if (lane == 0) red[wid] = m;
    __syncthreads();
    m = red[0];
#pragma unroll
    for (int w = 1; w < 16; w++) m = fmaxf(m, red[w]);
    float e = fexp(v - m);
    __shared__ float red2[16];
    float sum = warp_sum(e);
    if (lane == 0) red2[wid] = sum;
    __syncthreads();
    sum = red2[0];
#pragma unroll
    for (int w = 1; w < 16; w++) sum += red2[w];
    IL[(size_t)t * EE + k] = e / sum;
}

__global__ void add_ln(const float* __restrict__ resid, const float* __restrict__ parts,
                       int nparts,
                       float* __restrict__ out, bf16* __restrict__ outb,
                       const float* __restrict__ g, const float* __restrict__ bta)
{
    int t = blockIdx.x;
    int tid = threadIdx.x;
    __shared__ float zb[DD];
    __shared__ float red[256];
    float s = 0.f;
#pragma unroll
    for (int u = 0; u < 4; u++) {
        int d = tid + u * 256;
        float z = resid[(size_t)t * DD + d];
        for (int p = 0; p < nparts; p++)
            z += parts[(size_t)p * TT * DD + (size_t)t * DD + d];
        zb[d] = z; s += z;
    }
    red[tid] = s; __syncthreads();
    for (int st = 128; st > 0; st >>= 1) { if (tid < st) red[tid] += red[tid + st]; __syncthreads(); }
    float mean = red[0] * (1.0f / DD); __syncthreads();
    float v = 0.f;
#pragma unroll
    for (int u = 0; u < 4; u++) {
        int d = tid + u * 256;
        float dz = zb[d] - mean; v += dz * dz;
    }
    red[tid] = v; __syncthreads();
    for (int st = 128; st > 0; st >>= 1) { if (tid < st) red[tid] += red[tid + st]; __syncthreads(); }
    float inv = rsqrtf(red[0] * (1.0f / DD) + 1e-5f);
#pragma unroll
    for (int u = 0; u < 4; u++) {
        int d = tid + u * 256;
        float o = (zb[d] - mean) * inv * g[d] + bta[d];
        out[(size_t)t * DD + d] = o;
        if (outb) outb[(size_t)t * DD + d] = __float2bfloat16_rn(o);
    }
}

__global__ void mode_kernel(const float* __restrict__ core, const float* __restrict__ mw,
                            const float* __restrict__ mb, float* __restrict__ msig)
{
    int t = blockIdx.x;
    int tid = threadIdx.x;
    int wid = tid >> 5, lane = tid & 31;
    float s = 0.f;
    for (int d = tid; d < DD; d += 256) s += core[(size_t)t * DD + d] * mw[d];
    s = warp_sum(s);
    __shared__ float red[8];
    if (lane == 0) red[wid] = s;
    __syncthreads();
    if (tid == 0) {
        float tot = red[0];
#pragma unroll
        for (int w = 1; w < 8; w++) tot += red[w];
        msig[t] = 1.0f / (1.0f + expf(-(tot + mb[0])));
    }
}

__global__ void zero_loss()
{
    g_lossacc[0] = 0.f;
    g_lossacc[1] = 0.f;
}

__global__ void loss_partial(const float* __restrict__ tgtlog, const float* __restrict__ rmax,
                             const float* __restrict__ rsum, const float* __restrict__ msig,
                             const float* __restrict__ IL, const int* __restrict__ input_ids,
                             const int* __restrict__ decode_target)
{
    int tid = threadIdx.x;
    int wid = tid >> 5, lane = tid & 31;
    int t = blockIdx.x * 8 + wid;
    float acc = 0.f, cnt = 0.f;
    int b = t & (BB - 1), sIdx = t >> 3;
    int tgt = decode_target[b * SS + sIdx];
    if (tgt != 0) {
        const int* ids = input_ids + b * EE;
        const float* il = IL + (size_t)t * EE;
        float cp = 0.f;
        for (int j = lane; j < EE; j += 32)
            if (ids[j] == tgt) cp += il[j];
        cp = warp_sum(cp);
        if (lane == 0) {
            float mg = msig[t];
            float p = expf(tgtlog[t] - rmax[t]) / rsum[t] * mg;
            p += (1.0f - mg) * cp;
            acc = -logf(p + 1e-6f);
            cnt = 1.0f;
        }
    }
    __shared__ float sa[8], sc[8];
    if (lane == 0) { sa[wid] = acc; sc[wid] = cnt; }
    __syncthreads();
    if (tid == 0) {
        float A = 0.f, C = 0.f;
#pragma unroll
        for (int w = 0; w < 8; w++) { A += sa[w]; C += sc[w]; }
        atomicAdd(&g_lossacc[0], A);
        atomicAdd(&g_lossacc[1], C);
    }
}

__global__ void loss_final(float* __restrict__ out)
{
    out[threadIdx.x] = g_lossacc[0] / g_lossacc[1];
}

// ---------------- host orchestration --------------------------------------------------
static void* symaddr(const void* sym)
{
    void* p = nullptr;
    cudaGetSymbolAddress(&p, sym);
    return p;
}

static void cvtS(const float* src, bf16* dst, size_t n, cudaStream_t st)
{
    int blocks = (int)((n / 4 + 255) / 256);
    cvt_bf16<<<blocks, 256, 0, st>>>(src, dst, (int)n);
}

extern "C" void kernel_launch(void* const* d_in, const int* in_sizes, int n_in,
                              void* d_out, int out_size)
{
    const int*   input_ids     = (const int*)d_in[0];
    const float* encoder_rep   = (const float*)d_in[1];
    const float* input_mask    = (const float*)d_in[2];
    const int*   decode_input  = (const int*)d_in[3];
    const int*   decode_target = (const int*)d_in[4];
    const float* word_emb      = (const float*)d_in[5];
    const float* qkv_w         = (const float*)d_in[6];
    const float* r_w           = (const float*)d_in[7];
    const float* o_w           = (const float*)d_in[8];
    const float* kv_w          = (const float*)d_in[9];
    const float* q_w           = (const float*)d_in[10];
    const float* io_w          = (const float*)d_in[11];
    const float* rr_bias       = (const float*)d_in[12];
    const float* rw_bias       = (const float*)d_in[13];
    const float* ln1_g         = (const float*)d_in[14];
    const float* ln1_b         = (const float*)d_in[15];
    const float* ln2_g         = (const float*)d_in[16];
    const float* ln2_b         = (const float*)d_in[17];
    const float* ffn_w1        = (const float*)d_in[18];
    const float* ffn_b1        = (const float*)d_in[19];
    const float* ffn_w2        = (const float*)d_in[20];
    const float* ffn_b2        = (const float*)d_in[21];
    const float* ln3_g         = (const float*)d_in[22];
    const float* ln3_b         = (const float*)d_in[23];
    const float* out_w         = (const float*)d_in[24];
    const float* out_b         = (const float*)d_in[25];
    const float* copy_w        = (const float*)d_in[26];
    const float* copy_b        = (const float*)d_in[27];
    const float* mode_w        = (const float*)d_in[28];
    const float* mode_b        = (const float*)d_in[29];

    float* p_r     = (float*)symaddr(g_r);
    float* p_core  = (float*)symaddr(g_core);
    float* p_x     = (float*)symaddr(g_x);
    float* p_y     = (float*)symaddr(g_y);
    float* p_tmpk  = (float*)symaddr(g_tmpk);
    float* p_enct  = (float*)symaddr(g_enct);
    float* p_IL    = (float*)symaddr(g_IL);
    float* p_pm    = (float*)symaddr(g_pm);
    float* p_ps    = (float*)symaddr(g_ps);
    float* p_tgt   = (float*)symaddr(g_tgtlog);
    float* p_rmax  = (float*)symaddr(g_rmax);
    float* p_rsum  = (float*)symaddr(g_rsum);
    float* p_msig  = (float*)symaddr(g_msig);

    bf16* pb_core = (bf16*)symaddr(b_core);
    bf16* pb_r    = (bf16*)symaddr(b_r);
    bf16* pb_rkall= (bf16*)symaddr(b_rkall);
    bf16* pb_x    = (bf16*)symaddr(b_x);
    bf16* pb_y    = (bf16*)symaddr(b_y);
    bf16* pb_vec  = (bf16*)symaddr(b_vec);
    bf16* pb_enct = (bf16*)symaddr(b_enct);
    bf16* pb_h    = (bf16*)symaddr(b_h);
    bf16* pb_outb = (bf16*)symaddr(b_outb);
    bf16* pb_cpyh = (bf16*)symaddr(b_copyhb);
    bf16* pb_heads= (bf16*)symaddr(b_heads);
    bf16* pb_kvall= (bf16*)symaddr(b_kvall);
    bf16* pb_q2   = (bf16*)symaddr(b_q2);

    bf16* pw_qkv = (bf16*)symaddr(w_qkv);
    bf16* pw_r   = (bf16*)symaddr(w_r);
    bf16* pw_o   = (bf16*)symaddr(w_o);
    bf16* pw_kv  = (bf16*)symaddr(w_kv);
    bf16* pw_q   = (bf16*)symaddr(w_q);
    bf16* pw_io  = (bf16*)symaddr(w_io);
    bf16* pw_f1  = (bf16*)symaddr(w_f1);
    bf16* pw_f2  = (bf16*)symaddr(w_f2);
    bf16* pw_emb = (bf16*)symaddr(w_emb);
    bf16* pw_out = (bf16*)symaddr(w_out);
    bf16* pw_cp  = (bf16*)symaddr(w_copy);

    cudaFuncSetAttribute(sgemm_bf, cudaFuncAttributeMaxDynamicSharedMemorySize, SMEMSZ);
    cudaFuncSetAttribute(sgemm_vocab, cudaFuncAttributeMaxDynamicSharedMemorySize, SMEMSZ);
    cudaFuncSetAttribute(fused_self_attn, cudaFuncAttributeMaxDynamicSharedMemorySize, SMEM_ATT);
    cudaFuncSetAttribute(fused_cross_attn, cudaFuncAttributeMaxDynamicSharedMemorySize, SMEM_XATT);

    static cudaStream_t s2 = nullptr;
    static cudaEvent_t evFork = nullptr, evJoin = nullptr, evTail = nullptr, evTail2 = nullptr;
    if (!s2) {
        cudaStreamCreateWithFlags(&s2, cudaStreamNonBlocking);
        cudaEventCreateWithFlags(&evFork, cudaEventDisableTiming);
        cudaEventCreateWithFlags(&evJoin, cudaEventDisableTiming);
        cudaEventCreateWithFlags(&evTail, cudaEventDisableTiming);
        cudaEventCreateWithFlags(&evTail2, cudaEventDisableTiming);
    }

    cvtS(r_w,    pw_r,   (size_t)LL*DD*DD, 0);
    cvtS(kv_w,   pw_kv,  (size_t)LL*2*DD*DD, 0);
    cvtS(qkv_w,  pw_qkv, (size_t)LL*3*DD*DD, 0);

    cudaEventRecord(evFork, 0);
    cudaStreamWaitEvent(s2, evFork, 0);
    cvtS(o_w,    pw_o,   (size_t)LL*DD*DD, s2);
    cvtS(q_w,    pw_q,   (size_t)LL*DD*DD, s2);
    cvtS(io_w,   pw_io,  (size_t)LL*DD*DD, s2);
    cvtS(ffn_w1, pw_f1,  (size_t)LL*FF_*DD, s2);
    cvtS(ffn_w2, pw_f2,  (size_t)LL*DD*FF_, s2);
    cvtS(word_emb, pw_emb, (size_t)VV*DD, s2);
    cvtS(out_w,  pw_out, (size_t)DD*DD, s2);
    cvtS(copy_w, pw_cp,  (size_t)DD*DD, s2);
    cudaEventRecord(evJoin, s2);

    pos_emb_kernel<<<SS, 256>>>(p_r, pb_r);
    embed_kernel<<<TT, 256>>>(decode_input, word_emb, p_core, pb_core);
    transpose_enc<<<TE, 256>>>(encoder_rep, p_enct, pb_enct);

    sgemm_bf<<<dim3(LL*DD/128, SS/128), 256, SMEMSZ>>>(pb_r, pw_r, nullptr, pb_rkall,
        nullptr, DD, DD, DD, LL*DD, 0, 1, 0, 0, 0, 0);
    sgemm_bf<<<dim3(LL*2*DD/128, TE/128), 256, SMEMSZ>>>(pb_enct, pw_kv, nullptr, pb_kvall,
        nullptr, DD, DD, DD, LL*2*DD, 0, 1, 0, 0, 0, 0);

    bool joined = false;
    for (int l = 0; l < LL; l++) {
        sgemm_bf<<<dim3(3*DD/128, TT/128), 256, SMEMSZ>>>(pb_core, pw_qkv + (size_t)l*3*DD*DD,
            nullptr, pb_heads, nullptr, DD, DD, DD, 3*DD, 0, 1, 0, 0, 0, 0);
        fused_self_attn<<<BB*HH, 256, SMEM_ATT>>>(pb_heads, pb_rkall, pb_vec,
            rw_bias + (size_t)l*HH*DHH, rr_bias + (size_t)l*HH*DHH, l);
        if (!joined) { cudaStreamWaitEvent(0, evJoin, 0); joined = true; }
        sgemm_bf<<<dim3(DD/128, TT/128, 2), 256, SMEMSZ>>>(pb_vec, pw_o + (size_t)l*DD*DD,
            p_tmpk, nullptr, nullptr, DD, DD, DD, DD, 0, 2, (long long)TT*DD, 0, 0, 0);
        add_ln<<<TT, 256>>>(p_core, p_tmpk, 2, p_x, pb_x, ln1_g + l*DD, ln1_b + l*DD);

        sgemm_bf<<<dim3(DD/128, TT/128), 256, SMEMSZ>>>(pb_x, pw_q + (size_t)l*DD*DD,
            nullptr, pb_q2, nullptr, DD, DD, DD, DD, 0, 1, 0, 0, 0, 0);
        fused_cross_attn<<<BB*HH, 256, SMEM_XATT>>>(pb_q2, pb_kvall, input_mask, pb_vec, l);
        sgemm_bf<<<dim3(DD/128, TT/128, 2), 256, SMEMSZ>>>(pb_vec, pw_io + (size_t)l*DD*DD,
            p_tmpk, nullptr, nullptr, DD, DD, DD, DD, 0, 2, (long long)TT*DD, 0, 0, 0);
        add_ln<<<TT, 256>>>(p_x, p_tmpk, 2, p_y, pb_y, ln2_g + l*DD, ln2_b + l*DD);

        sgemm_bf<<<dim3(FF_/128, TT/128), 256, SMEMSZ>>>(pb_y, pw_f1 + (size_t)l*FF_*DD,
            nullptr, pb_h, ffn_b1 + (size_t)l*FF_, DD, DD, DD, FF_, 1, 1, 0, 0, 0, 0);
        sgemm_bf<<<dim3(DD/128, TT/128, 4), 256, SMEMSZ>>>(pb_h, pw_f2 + (size_t)l*DD*FF_,
            p_tmpk, nullptr, ffn_b2 + (size_t)l*DD, FF_, FF_, FF_, DD, 0, 4, (long long)TT*DD, 0, 0, 0);
        add_ln<<<TT, 256>>>(p_y, p_tmpk, 4, p_core, pb_core, ln3_g + l*DD, ln3_b + l*DD);
    }

    // ---- tail: two independent chains overlapped ----
    cudaEventRecord(evTail, 0);
    cudaStreamWaitEvent(s2, evTail, 0);
    // chain B on s2: copy head -> IL -> softmax_il -> mode
    sgemm_bf<<<dim3(DD/128, TT/128), 256, SMEMSZ, s2>>>(pb_core, pw_cp, nullptr, pb_cpyh, copy_b,
        DD, DD, DD, DD, 0, 1, 0, 0, 0, 0);
    sgemm_bf<<<dim3(EE/128, SS/128, BB), 256, SMEMSZ, s2>>>(pb_cpyh, pb_enct, p_IL, nullptr,
        nullptr, DD, BB*DD, BB*DD, BB*EE, 0, 1, 0,
        (long long)DD, (long long)DD, (long long)EE);
    softmax_il<<<TT, 512, 0, s2>>>(p_IL, input_mask);
    mode_kernel<<<TT, 256, 0, s2>>>(p_core, mode_w, mode_b, p_msig);
    cudaEventRecord(evTail2, s2);

    // chain A on stream 0: out head -> vocab (+fused stats) -> stats_final
    sgemm_bf<<<dim3(DD/128, TT/128), 256, SMEMSZ>>>(pb_core, pw_out, nullptr, pb_outb, out_b,
        DD, DD, DD, DD, 0, 1, 0, 0, 0, 0);
    sgemm_vocab<<<dim3(NTILE, TT/128), 256, SMEMSZ>>>(pb_outb, pw_emb, decode_target,
        p_pm, p_ps, p_tgt, DD, DD, DD);
    stats_final<<<TT, 32>>>(p_pm, p_ps, p_rmax, p_rsum);
    zero_loss<<<1, 1>>>();

    cudaStreamWaitEvent(0, evTail2, 0);
    loss_partial<<<TT/8, 256>>>(p_tgt, p_rmax, p_rsum, p_msig, p_IL, input_ids, decode_target);
    loss_final<<<1, BB>>>((float*)d_out);
}

// round 15
// speedup vs baseline: 1.0646x; 1.0145x over previous
#include <cuda_runtime.h>
#include <cuda_bf16.h>
#include <math.h>
#include <stdint.h>

// Problem dims
#define BB 8
#define SS 128
#define EE 512
#define DD 1024
#define HH 16
#define LL 4
#define VV 32000
#define DHH 64
#define FF_ 4096
#define TT (SS*BB)
#define TE (EE*BB)
#define NTILE (VV/128)
#define SCALE_ 0.125f
#define NEG_ (-1e30f)

typedef __nv_bfloat16 bf16;

// ---------------- scratch ----------------
__device__ float g_r[SS*DD];
__device__ float g_core[TT*DD];
__device__ float g_x[TT*DD];
__device__ float g_y[TT*DD];
__device__ float g_tmpk[4*TT*DD];
__device__ float g_enct[TE*DD];
__device__ float g_IL[TT*EE];
__device__ float g_pm[TT*256];
__device__ float g_ps[TT*256];
__device__ float g_tgtlog[TT];
__device__ float g_rmax[TT];
__device__ float g_rsum[TT];
__device__ float g_msig[TT];
__device__ float g_lossacc[2];

// bf16 activations
__device__ bf16 b_core[TT*DD];
__device__ bf16 b_r[SS*DD];
__device__ bf16 b_rkall[SS*LL*DD];
__device__ bf16 b_x[TT*DD];
__device__ bf16 b_y[TT*DD];
__device__ bf16 b_vec[TT*DD];
__device__ bf16 b_enct[TE*DD];
__device__ bf16 b_h[TT*FF_];
__device__ bf16 b_outb[TT*DD];
__device__ bf16 b_copyhb[TT*DD];
__device__ bf16 b_heads[TT*3*DD];
__device__ bf16 b_kvall[(size_t)TE*LL*2*DD];

// bf16 weights
__device__ bf16 w_qkv[LL*3*DD*DD];
__device__ bf16 w_r[LL*DD*DD];
__device__ bf16 w_o[LL*DD*DD];
__device__ bf16 w_kv[LL*2*DD*DD];
__device__ bf16 w_q[LL*DD*DD];
__device__ bf16 w_io[LL*DD*DD];
__device__ bf16 w_f1[LL*FF_*DD];
__device__ bf16 w_f2[LL*DD*FF_];
__device__ bf16 w_emb[(size_t)VV*DD];
__device__ bf16 w_out[DD*DD];
__device__ bf16 w_copy[DD*DD];

__device__ __forceinline__ uint32_t smem_u32(const void* p)
{
    return (uint32_t)__cvta_generic_to_shared(p);
}

// FFMA-only exp (no MUFU)
__device__ __forceinline__ float fexp(float x)
{
    x = fmaxf(x, -87.0f);
    float y = x * 1.4426950408889634f;
    float z = y + 12582912.0f;
    int   ki = __float_as_int(z) - 0x4B400000;
    float kf = z - 12582912.0f;
    float f = y - kf;
    float p = 0.00133336f;
    p = fmaf(p, f, 0.00961813f);
    p = fmaf(p, f, 0.05550411f);
    p = fmaf(p, f, 0.24022651f);
    p = fmaf(p, f, 0.69314718f);
    p = fmaf(p, f, 1.0f);
    return p * __int_as_float((ki + 127) << 23);
}

// ---------------- f32 -> bf16 conversion ----------------
__global__ void cvt_bf16(const float* __restrict__ src, bf16* __restrict__ dst, int n)
{
    int i = (blockIdx.x * 256 + threadIdx.x) * 4;
    if (i >= n) return;
    float4 v = *reinterpret_cast<const float4*>(src + i);
    uint32_t lo = ((uint32_t)__bfloat16_as_ushort(__float2bfloat16_rn(v.y)) << 16)
                | (uint32_t)__bfloat16_as_ushort(__float2bfloat16_rn(v.x));
    uint32_t hi = ((uint32_t)__bfloat16_as_ushort(__float2bfloat16_rn(v.w)) << 16)
                | (uint32_t)__bfloat16_as_ushort(__float2bfloat16_rn(v.z));
    *reinterpret_cast<uint2*>(dst + i) = make_uint2(lo, hi);
}

// 3-stage cp.async pipeline, 128x128 block (best known)
#define SMEMSZ (3*2*128*40*2)

__global__ __launch_bounds__(256, 2)
void sgemm_bf(const bf16* __restrict__ A, const bf16* __restrict__ Bw,
              float* __restrict__ Cf, bf16* __restrict__ Cb,
              const float* __restrict__ bias,
              int K, int lda, int ldb, int ldc, int act, int ksplit,
              long long partStride,
              long long aBS, long long bBS, long long cBS)
{
    extern __shared__ bf16 ds[];
    bf16* AsB = ds;
    bf16* BsB = ds + 3*128*40;

    int tid = threadIdx.x;
    int warp = tid >> 5, lane = tid & 31;
    int warp_m = warp >> 1;
    int warp_n = warp & 1;
    int rowA0 = blockIdx.y * 128;
    int colB0 = blockIdx.x * 128;

    long long zb = (ksplit == 1) ? (long long)blockIdx.z : 0;
    const bf16* Az = A + zb * aBS;
    const bf16* Bz = Bw + zb * bBS;

    int Kloc = K / ksplit;
    int kgbase = (ksplit > 1) ? blockIdx.z * Kloc : 0;

    int ldrow = tid >> 1;
    int ldkoff = (tid & 1) * 16;

    float c[2][8][4];
#pragma unroll
    for (int mi = 0; mi < 2; mi++)
#pragma unroll
        for (int ni = 0; ni < 8; ni++)
#pragma unroll
            for (int r = 0; r < 4; r++) c[mi][ni][r] = 0.f;

    const bf16* Agp = &Az[(size_t)(rowA0 + ldrow) * lda + kgbase + ldkoff];
    const bf16* Bgp = &Bz[(size_t)(colB0 + ldrow) * ldb + kgbase + ldkoff];

    int nk = Kloc >> 5;
#pragma unroll
    for (int s = 0; s < 2; s++) {
        bf16* as = AsB + s * (128*40);
        bf16* bs = BsB + s * (128*40);
        uint32_t sa = smem_u32(as + ldrow * 40 + ldkoff);
        uint32_t sb = smem_u32(bs + ldrow * 40 + ldkoff);
        const bf16* ag = Agp + s * 32;
        const bf16* bg = Bgp + s * 32;
        asm volatile("cp.async.ca.shared.global [%0], [%1], 16;\n"
                     "cp.async.ca.shared.global [%2], [%3], 16;\n"
                     "cp.async.ca.shared.global [%4], [%5], 16;\n"
                     "cp.async.ca.shared.global [%6], [%7], 16;\n"
                     :: "r"(sa), "l"(ag), "r"(sa + 16), "l"(ag + 8),
                        "r"(sb), "l"(bg), "r"(sb + 16), "l"(bg + 8));
        asm volatile("cp.async.commit_group;");
    }

    for (int kt = 0; kt < nk; kt++) {
        asm volatile("cp.async.wait_group 1;");
        __syncthreads();
        int pf = kt + 2;
        if (pf < nk) {
            int sbuf = pf - (pf / 3) * 3;
            bf16* as = AsB + sbuf * (128*40);
            bf16* bs = BsB + sbuf * (128*40);
            uint32_t sa = smem_u32(as + ldrow * 40 + ldkoff);
            uint32_t sb = smem_u32(bs + ldrow * 40 + ldkoff);
            const bf16* ag = Agp + pf * 32;
            const bf16* bg = Bgp + pf * 32;
            asm volatile("cp.async.ca.shared.global [%0], [%1], 16;\n"
                         "cp.async.ca.shared.global [%2], [%3], 16;\n"
                         "cp.async.ca.shared.global [%4], [%5], 16;\n"
                         "cp.async.ca.shared.global [%6], [%7], 16;\n"
                         :: "r"(sa), "l"(ag), "r"(sa + 16), "l"(ag + 8),
                            "r"(sb), "l"(bg), "r"(sb + 16), "l"(bg + 8));
        }
        asm volatile("cp.async.commit_group;");

        int cbuf = kt - (kt / 3) * 3;
        bf16* as = AsB + cbuf * (128*40);
        bf16* bs = BsB + cbuf * (128*40);
#pragma unroll
        for (int ks = 0; ks < 2; ks++) {
            int k0 = ks * 16;
            uint32_t a[2][4];
#pragma unroll
            for (int mi = 0; mi < 2; mi++) {
                int m = warp_m * 32 + mi * 16 + (lane & 15);
                int kc = k0 + ((lane >> 4) << 3);
                uint32_t addr = smem_u32(as + m * 40 + kc);
                asm volatile("ldmatrix.sync.aligned.m8n8.x4.shared.b16 {%0,%1,%2,%3}, [%4];"
                             : "=r"(a[mi][0]), "=r"(a[mi][1]), "=r"(a[mi][2]), "=r"(a[mi][3])
                             : "r"(addr));
            }
            uint32_t b[8][2];
#pragma unroll
            for (int nt = 0; nt < 4; nt++) {
                int n = warp_n * 64 + nt * 16 + (lane & 7) + ((lane >> 4) << 3);
                int kc = k0 + (((lane >> 3) & 1) << 3);
                uint32_t addr = smem_u32(bs + n * 40 + kc);
                asm volatile("ldmatrix.sync.aligned.m8n8.x4.shared.b16 {%0,%1,%2,%3}, [%4];"
                             : "=r"(b[nt*2][0]), "=r"(b[nt*2][1]),
                               "=r"(b[nt*2+1][0]), "=r"(b[nt*2+1][1])
                             : "r"(addr));
            }
#pragma unroll
            for (int mi = 0; mi < 2; mi++)
#pragma unroll
                for (int ni = 0; ni < 8; ni++) {
                    asm volatile(
                        "mma.sync.aligned.m16n8k16.row.col.f32.bf16.bf16.f32 "
                        "{%0,%1,%2,%3}, {%4,%5,%6,%7}, {%8,%9}, {%0,%1,%2,%3};\n"
                        : "+f"(c[mi][ni][0]), "+f"(c[mi][ni][1]),
                          "+f"(c[mi][ni][2]), "+f"(c[mi][ni][3])
                        : "r"(a[mi][0]), "r"(a[mi][1]), "r"(a[mi][2]), "r"(a[mi][3]),
                          "r"(b[ni][0]), "r"(b[ni][1]));
                }
        }
    }

    bool addbias = (bias != nullptr) && (ksplit == 1 || blockIdx.z == 0);
    float* Cfz = Cf ? (Cf + (ksplit > 1 ? (size_t)blockIdx.z * partStride : (size_t)zb * cBS)) : nullptr;
    bf16*  Cbz = Cb ? (Cb + (size_t)zb * cBS) : nullptr;
#pragma unroll
    for (int mi = 0; mi < 2; mi++) {
        int row0 = rowA0 + warp_m * 32 + mi * 16 + (lane >> 2);
#pragma unroll
        for (int ni = 0; ni < 8; ni++) {
            int col = colB0 + warp_n * 64 + ni * 8 + (lane & 3) * 2;
            float bv0 = 0.f, bv1 = 0.f;
            if (addbias) { bv0 = bias[col]; bv1 = bias[col + 1]; }
#pragma unroll
            for (int half = 0; half < 2; half++) {
                int gm = row0 + half * 8;
                float v0 = c[mi][ni][half * 2 + 0] + bv0;
                float v1 = c[mi][ni][half * 2 + 1] + bv1;
                if (ksplit > 1) {
                    Cfz[(size_t)gm * ldc + col]     = v0;
                    Cfz[(size_t)gm * ldc + col + 1] = v1;
                } else {
                    if (act == 1) {
                        v0 = 0.5f * v0 * (1.0f + erff(v0 * 0.70710678118654752f));
                        v1 = 0.5f * v1 * (1.0f + erff(v1 * 0.70710678118654752f));
                    }
                    if (Cfz) {
                        Cfz[(size_t)gm * ldc + col]     = v0;
                        Cfz[(size_t)gm * ldc + col + 1] = v1;
                    }
                    if (Cbz) {
                        uint32_t pk = ((uint32_t)__bfloat16_as_ushort(__float2bfloat16_rn(v1)) << 16)
                                    | (uint32_t)__bfloat16_as_ushort(__float2bfloat16_rn(v0));
                        *reinterpret_cast<uint32_t*>(&Cbz[(size_t)gm * ldc + col]) = pk;
                    }
                }
            }
        }
    }
}

// ======== fully fused self-attention ========
#define SMEM_ATT (5*128*72*2)
__global__ __launch_bounds__(256, 1)
void fused_self_attn(const bf16* __restrict__ heads, const bf16* __restrict__ rkall,
                     bf16* __restrict__ vecOut,
                     const float* __restrict__ rwb, const float* __restrict__ rrb,
                     int layer)
{
    extern __shared__ bf16 dsA[];
    bf16* vS   = dsA;
    bf16* regA = dsA + 128*72;
    bf16* qrw  = regA;
    bf16* qrr  = regA + 128*72;
    bf16* kS   = regA + 2*128*72;
    bf16* rkS  = regA + 3*128*72;
    float* bdS = (float*)regA;
    bf16*  PS  = regA;

    __shared__ float rowm[128][2];
    __shared__ float rowsum[128][2];

    int z = blockIdx.x;
    int h = z % HH, b = z / HH;
    int tid = threadIdx.x;
    int warp = tid >> 5, lane = tid & 31;
    int warp_m = warp >> 1, warp_n = warp & 1;
    int gid = lane >> 2, tig = lane & 3;

    {
        int row = tid >> 1;
        int koff = (tid & 1) * 32;
        const bf16* qg  = heads + (size_t)b*3*DD + (size_t)h*DHH + (size_t)row*(BB*3*DD) + koff;
        const bf16* kg  = qg + DD;
        const bf16* vg  = qg + 2*DD;
        const bf16* rkg = rkall + (size_t)layer*DD + (size_t)h*DHH + (size_t)row*(LL*DD) + koff;
        const float* rwh = rwb + h*DHH + koff;
        const float* rrh = rrb + h*DHH + koff;
#pragma unroll
        for (int j = 0; j < 4; j++) {
            bf16 tq[8], trw[8], trr[8];
            *reinterpret_cast<uint4*>(tq) = *reinterpret_cast<const uint4*>(qg + j*8);
#pragma unroll
            for (int e = 0; e < 8; e++) {
                float qv = __bfloat162float(tq[e]);
                trw[e] = __float2bfloat16_rn(qv + rwh[j*8+e]);
                trr[e] = __float2bfloat16_rn(qv + rrh[j*8+e]);
            }
            *reinterpret_cast<uint4*>(&qrw[row*72 + koff + j*8]) = *reinterpret_cast<uint4*>(trw);
            *reinterpret_cast<uint4*>(&qrr[row*72 + koff + j*8]) = *reinterpret_cast<uint4*>(trr);
            *reinterpret_cast<uint4*>(&kS [row*72 + koff + j*8]) =
                *reinterpret_cast<const uint4*>(kg + j*8);
            *reinterpret_cast<uint4*>(&rkS[row*72 + koff + j*8]) =
                *reinterpret_cast<const uint4*>(rkg + j*8);
            *reinterpret_cast<uint4*>(&vS [row*72 + koff + j*8]) =
                *reinterpret_cast<const uint4*>(vg + j*8);
        }
    }
    __syncthreads();

    float cac[2][8][4], cbd[2][8][4];
#pragma unroll
    for (int mi = 0; mi < 2; mi++)
#pragma unroll
        for (int ni = 0; ni < 8; ni++)
#pragma unroll
            for (int r = 0; r < 4; r++) { cac[mi][ni][r] = 0.f; cbd[mi][ni][r] = 0.f; }

#pragma unroll
    for (int ks = 0; ks < 4; ks++) {
        int k0 = ks * 16;
        int m0 = warp_m * 32 + (lane & 15);
        int kcA = k0 + ((lane >> 4) << 3);
        int nI  = warp_n * 64 + (lane & 7) + ((lane >> 4) << 3);
        int kcB = k0 + (((lane >> 3) & 1) << 3);
        uint32_t a1[2][4], a2[2][4];
#pragma unroll
        for (int mi = 0; mi < 2; mi++) {
            uint32_t ad1 = smem_u32(qrw + (m0 + mi*16)*72 + kcA);
            uint32_t ad2 = smem_u32(qrr + (m0 + mi*16)*72 + kcA);
            asm volatile("ldmatrix.sync.aligned.m8n8.x4.shared.b16 {%0,%1,%2,%3}, [%4];"
                         : "=r"(a1[mi][0]), "=r"(a1[mi][1]), "=r"(a1[mi][2]), "=r"(a1[mi][3])
                         : "r"(ad1));
            asm volatile("ldmatrix.sync.aligned.m8n8.x4.shared.b16 {%0,%1,%2,%3}, [%4];"
                         : "=r"(a2[mi][0]), "=r"(a2[mi][1]), "=r"(a2[mi][2]), "=r"(a2[mi][3])
                         : "r"(ad2));
        }
        uint32_t b1[8][2], b2[8][2];
#pragma unroll
        for (int nt = 0; nt < 4; nt++) {
            uint32_t bd1 = smem_u32(kS  + (nI + nt*16)*72 + kcB);
            uint32_t bd2 = smem_u32(rkS + (nI + nt*16)*72 + kcB);
            asm volatile("ldmatrix.sync.aligned.m8n8.x4.shared.b16 {%0,%1,%2,%3}, [%4];"
                         : "=r"(b1[nt*2][0]), "=r"(b1[nt*2][1]),
                           "=r"(b1[nt*2+1][0]), "=r"(b1[nt*2+1][1])
                         : "r"(bd1));
            asm volatile("ldmatrix.sync.aligned.m8n8.x4.shared.b16 {%0,%1,%2,%3}, [%4];"
                         : "=r"(b2[nt*2][0]), "=r"(b2[nt*2][1]),
                           "=r"(b2[nt*2+1][0]), "=r"(b2[nt*2+1][1])
                         : "r"(bd2));
        }
#pragma unroll
        for (int mi = 0; mi < 2; mi++)
#pragma unroll
            for (int ni = 0; ni < 8; ni++) {
                asm volatile("mma.sync.aligned.m16n8k16.row.col.f32.bf16.bf16.f32 "
                             "{%0,%1,%2,%3}, {%4,%5,%6,%7}, {%8,%9}, {%0,%1,%2,%3};\n"
                             : "+f"(cac[mi][ni][0]), "+f"(cac[mi][ni][1]),
                               "+f"(cac[mi][ni][2]), "+f"(cac[mi][ni][3])
                             : "r"(a1[mi][0]), "r"(a1[mi][1]), "r"(a1[mi][2]), "r"(a1[mi][3]),
                               "r"(b1[ni][0]), "r"(b1[ni][1]));
                asm volatile("mma.sync.aligned.m16n8k16.row.col.f32.bf16.bf16.f32 "
                             "{%0,%1,%2,%3}, {%4,%5,%6,%7}, {%8,%9}, {%0,%1,%2,%3};\n"
                             : "+f"(cbd[mi][ni][0]), "+f"(cbd[mi][ni][1]),
                               "+f"(cbd[mi][ni][2]), "+f"(cbd[mi][ni][3])
                             : "r"(a2[mi][0]), "r"(a2[mi][1]), "r"(a2[mi][2]), "r"(a2[mi][3]),
                               "r"(b2[ni][0]), "r"(b2[ni][1]));
            }
    }
    __syncthreads();

#pragma unroll
    for (int mi = 0; mi < 2; mi++) {
        int row0 = warp_m * 32 + mi * 16 + gid;
#pragma unroll
        for (int ni = 0; ni < 8; ni++) {
            int col = warp_n * 64 + ni * 8 + tig * 2;
#pragma unroll
            for (int half = 0; half < 2; half++) {
                int gm = row0 + half * 8;
                bdS[gm * 132 + col]     = cbd[mi][ni][half*2 + 0];
                bdS[gm * 132 + col + 1] = cbd[mi][ni][half*2 + 1];
            }
        }
    }
    __syncthreads();

#pragma unroll
    for (int mi = 0; mi < 2; mi++) {
#pragma unroll
        for (int half = 0; half < 2; half++) {
            int r = warp_m * 32 + mi * 16 + half * 8 + gid;
            float m = -1e30f;
#pragma unroll
            for (int ni = 0; ni < 8; ni++) {
#pragma unroll
                for (int e = 0; e < 2; e++) {
                    int j = warp_n * 64 + ni * 8 + tig * 2 + e;
                    float sc;
                    if (j > r) sc = NEG_;
                    else {
                        int f = r * SS + j + SS;
                        int qi = f / (SS + 1);
                        int cc = f - qi * (SS + 1);
                        float bdv = (cc > 0) ? bdS[qi * 132 + (cc - 1)] : 0.f;
                        sc = (cac[mi][ni][half*2 + e] + bdv) * SCALE_;
                    }
                    cac[mi][ni][half*2 + e] = sc;
                    m = fmaxf(m, sc);
                }
            }
#pragma unroll
            for (int o = 1; o <= 2; o <<= 1) m = fmaxf(m, __shfl_xor_sync(0xffffffffu, m, o));
            if (tig == 0) rowm[r][warp_n] = m;
        }
    }
    __syncthreads();

#pragma unroll
    for (int mi = 0; mi < 2; mi++) {
#pragma unroll
        for (int half = 0; half < 2; half++) {
            int r = warp_m * 32 + mi * 16 + half * 8 + gid;
            float m = fmaxf(rowm[r][0], rowm[r][1]);
            float s = 0.f;
#pragma unroll
            for (int ni = 0; ni < 8; ni++) {
#pragma unroll
                for (int e = 0; e < 2; e++) {
                    float ev = fexp(cac[mi][ni][half*2 + e] - m);
                    cac[mi][ni][half*2 + e] = ev;
                    s += ev;
                }
            }
#pragma unroll
            for (int o = 1; o <= 2; o <<= 1) s += __shfl_xor_sync(0xffffffffu, s, o);
            if (tig == 0) rowsum[r][warp_n] = s;
        }
    }
    __syncthreads();

#pragma unroll
    for (int mi = 0; mi < 2; mi++) {
#pragma unroll
        for (int half = 0; half < 2; half++) {
            int r = warp_m * 32 + mi * 16 + half * 8 + gid;
            float inv = 1.0f / (rowsum[r][0] + rowsum[r][1]);
#pragma unroll
            for (int ni = 0; ni < 8; ni++) {
                int col = warp_n * 64 + ni * 8 + tig * 2;
                uint32_t pk = ((uint32_t)__bfloat16_as_ushort(
                                  __float2bfloat16_rn(cac[mi][ni][half*2+1] * inv)) << 16)
                            | (uint32_t)__bfloat16_as_ushort(
                                  __float2bfloat16_rn(cac[mi][ni][half*2+0] * inv));
                *reinterpret_cast<uint32_t*>(&PS[r * 136 + col]) = pk;
            }
        }
    }
    __syncthreads();

    float c2[2][4][4];
#pragma unroll
    for (int mi = 0; mi < 2; mi++)
#pragma unroll
        for (int ni = 0; ni < 4; ni++)
#pragma unroll
            for (int r = 0; r < 4; r++) c2[mi][ni][r] = 0.f;

#pragma unroll
    for (int ks = 0; ks < 8; ks++) {
        int k0 = ks * 16;
        uint32_t a[2][4];
#pragma unroll
        for (int mi = 0; mi < 2; mi++) {
            int m = warp_m * 32 + mi * 16 + (lane & 15);
            int kc = k0 + ((lane >> 4) << 3);
            uint32_t addr = smem_u32(PS + m * 136 + kc);
            asm volatile("ldmatrix.sync.aligned.m8n8.x4.shared.b16 {%0,%1,%2,%3}, [%4];"
                         : "=r"(a[mi][0]), "=r"(a[mi][1]), "=r"(a[mi][2]), "=r"(a[mi][3])
                         : "r"(addr));
        }
        uint32_t bb[4][2];
#pragma unroll
        for (int nt = 0; nt < 2; nt++) {
            int kr = k0 + (lane & 15);
            int n = warp_n * 32 + nt * 16 + ((lane >> 4) << 3);
            uint32_t addr = smem_u32(vS + kr * 72 + n);
            asm volatile("ldmatrix.sync.aligned.m8n8.x4.trans.shared.b16 {%0,%1,%2,%3}, [%4];"
                         : "=r"(bb[nt*2][0]), "=r"(bb[nt*2][1]),
                           "=r"(bb[nt*2+1][0]), "=r"(bb[nt*2+1][1])
                         : "r"(addr));
        }
#pragma unroll
        for (int mi = 0; mi < 2; mi++)
#pragma unroll
            for (int ni = 0; ni < 4; ni++) {
                asm volatile("mma.sync.aligned.m16n8k16.row.col.f32.bf16.bf16.f32 "
                             "{%0,%1,%2,%3}, {%4,%5,%6,%7}, {%8,%9}, {%0,%1,%2,%3};\n"
                             : "+f"(c2[mi][ni][0]), "+f"(c2[mi][ni][1]),
                               "+f"(c2[mi][ni][2]), "+f"(c2[mi][ni][3])
                             : "r"(a[mi][0]), "r"(a[mi][1]), "r"(a[mi][2]), "r"(a[mi][3]),
                               "r"(bb[ni][0]), "r"(bb[ni][1]));
            }
    }

    bf16* outBase = vecOut + (size_t)b * DD + (size_t)h * DHH;
#pragma unroll
    for (int mi = 0; mi < 2; mi++) {
        int row0 = warp_m * 32 + mi * 16 + gid;
#pragma unroll
        for (int ni = 0; ni < 4; ni++) {
            int col = warp_n * 32 + ni * 8 + tig * 2;
#pragma unroll
            for (int half = 0; half < 2; half++) {
                int gm = row0 + half * 8;
                uint32_t pk = ((uint32_t)__bfloat16_as_ushort(__float2bfloat16_rn(c2[mi][ni][half*2+1])) << 16)
                            | (uint32_t)__bfloat16_as_ushort(__float2bfloat16_rn(c2[mi][ni][half*2+0]));
                *reinterpret_cast<uint32_t*>(&outBase[(size_t)gm * (BB*DD) + col]) = pk;
            }
        }
    }
}

// ======== fused cross-attention: flash-style; q from two f32 split-K partial slabs ====
#define SMEM_XATT ((3*128*72 + 128*136)*2)
__global__ __launch_bounds__(256, 1)
void fused_cross_attn(const float* __restrict__ qp0, const float* __restrict__ qp1,
                      const bf16* __restrict__ kvall,
                      const float* __restrict__ mask,
                      bf16* __restrict__ vecOut, int layer)
{
    extern __shared__ bf16 dsX[];
    bf16* qS = dsX;
    bf16* kS = dsX + 128*72;
    bf16* vS = dsX + 2*128*72;
    bf16* PS = dsX + 3*128*72;

    __shared__ float rowm[128][2];
    __shared__ float rowsum[128][2];
    __shared__ float maskS[128];

    int z = blockIdx.x;
    int h = z % HH, b = z / HH;
    int tid = threadIdx.x;
    int warp = tid >> 5, lane = tid & 31;
    int warp_m = warp >> 1, warp_n = warp & 1;
    int gid = lane >> 2, tig = lane & 3;
    int row = tid >> 1, koff = (tid & 1) * 32;

    // q tile = sum of two f32 partial slabs, converted to bf16 (same math as before)
    {
        size_t base = (size_t)b*DD + (size_t)h*DHH + (size_t)row*(BB*DD) + koff;
        const float* q0 = qp0 + base;
        const float* q1 = qp1 + base;
#pragma unroll
        for (int j = 0; j < 8; j++) {     // 8 x float4 = 32 floats
            float4 v0 = *reinterpret_cast<const float4*>(q0 + j*4);
            float4 v1 = *reinterpret_cast<const float4*>(q1 + j*4);
            bf16 t[4];
            t[0] = __float2bfloat16_rn(v0.x + v1.x);
            t[1] = __float2bfloat16_rn(v0.y + v1.y);
            t[2] = __float2bfloat16_rn(v0.z + v1.z);
            t[3] = __float2bfloat16_rn(v0.w + v1.w);
            *reinterpret_cast<uint2*>(&qS[row*72 + koff + j*4]) = *reinterpret_cast<uint2*>(t);
        }
    }

    const bf16* kBase = kvall + (size_t)layer*2*DD + (size_t)b*(LL*2*DD) + (size_t)h*DHH;
    const bf16* vBase = kBase + DD;
    const long long kvRow = (long long)BB*LL*2*DD;

    float mstate[2][2], lstate[2][2];
#pragma unroll
    for (int mi = 0; mi < 2; mi++)
#pragma unroll
        for (int half = 0; half < 2; half++) { mstate[mi][half] = -1e30f; lstate[mi][half] = 0.f; }

    float c2[2][4][4];
#pragma unroll
    for (int mi = 0; mi < 2; mi++)
#pragma unroll
        for (int ni = 0; ni < 4; ni++)
#pragma unroll
            for (int r = 0; r < 4; r++) c2[mi][ni][r] = 0.f;

    for (int kc = 0; kc < 4; kc++) {
        {
            const bf16* kg = kBase + (size_t)(kc*128 + row) * kvRow + koff;
            const bf16* vg = vBase + (size_t)(kc*128 + row) * kvRow + koff;
#pragma unroll
            for (int j = 0; j < 4; j++) {
                *reinterpret_cast<uint4*>(&kS[row*72 + koff + j*8]) =
                    *reinterpret_cast<const uint4*>(kg + j*8);
                *reinterpret_cast<uint4*>(&vS[row*72 + koff + j*8]) =
                    *reinterpret_cast<const uint4*>(vg + j*8);
            }
            if (tid < 128) maskS[tid] = mask[b*EE + kc*128 + tid];
        }
        __syncthreads();

        float cs[2][8][4];
#pragma unroll
        for (int mi = 0; mi < 2; mi++)
#pragma unroll
            for (int ni = 0; ni < 8; ni++)
#pragma unroll
                for (int r = 0; r < 4; r++) cs[mi][ni][r] = 0.f;

#pragma unroll
        for (int ks = 0; ks < 4; ks++) {
            int k0 = ks * 16;
            uint32_t a[2][4];
#pragma unroll
            for (int mi = 0; mi < 2; mi++) {
                int m = warp_m * 32 + mi * 16 + (lane & 15);
                int kcc = k0 + ((lane >> 4) << 3);
                uint32_t addr = smem_u32(qS + m*72 + kcc);
                asm volatile("ldmatrix.sync.aligned.m8n8.x4.shared.b16 {%0,%1,%2,%3}, [%4];"
                             : "=r"(a[mi][0]), "=r"(a[mi][1]), "=r"(a[mi][2]), "=r"(a[mi][3])
                             : "r"(addr));
            }
            uint32_t bb[8][2];
#pragma unroll
            for (int nt = 0; nt < 4; nt++) {
                int n = warp_n * 64 + nt * 16 + (lane & 7) + ((lane >> 4) << 3);
                int kcc = k0 + (((lane >> 3) & 1) << 3);
                uint32_t addr = smem_u32(kS + n*72 + kcc);
                asm volatile("ldmatrix.sync.aligned.m8n8.x4.shared.b16 {%0,%1,%2,%3}, [%4];"
                             : "=r"(bb[nt*2][0]), "=r"(bb[nt*2][1]),
                               "=r"(bb[nt*2+1][0]), "=r"(bb[nt*2+1][1])
                             : "r"(addr));
            }
#pragma unroll
            for (int mi = 0; mi < 2; mi++)
#pragma unroll
                for (int ni = 0; ni < 8; ni++) {
                    asm volatile("mma.sync.aligned.m16n8k16.row.col.f32.bf16.bf16.f32 "
                                 "{%0,%1,%2,%3}, {%4,%5,%6,%7}, {%8,%9}, {%0,%1,%2,%3};\n"
                                 : "+f"(cs[mi][ni][0]), "+f"(cs[mi][ni][1]),
                                   "+f"(cs[mi][ni][2]), "+f"(cs[mi][ni][3])
                                 : "r"(a[mi][0]), "r"(a[mi][1]), "r"(a[mi][2]), "r"(a[mi][3]),
                                   "r"(bb[ni][0]), "r"(bb[ni][1]));
                }
        }

#pragma unroll
        for (int mi = 0; mi < 2; mi++) {
#pragma unroll
            for (int half = 0; half < 2; half++) {
                int r = warp_m * 32 + mi * 16 + half * 8 + gid;
                float m = -1e30f;
#pragma unroll
                for (int ni = 0; ni < 8; ni++) {
#pragma unroll
                    for (int e = 0; e < 2; e++) {
                        int j = warp_n * 64 + ni * 8 + tig * 2 + e;
                        float sc = cs[mi][ni][half*2 + e] * SCALE_
                                 + (1.0f - maskS[j]) * NEG_;
                        cs[mi][ni][half*2 + e] = sc;
                        m = fmaxf(m, sc);
                    }
                }
#pragma unroll
                for (int o = 1; o <= 2; o <<= 1) m = fmaxf(m, __shfl_xor_sync(0xffffffffu, m, o));
                if (tig == 0) rowm[r][warp_n] = m;
            }
        }
        __syncthreads();

        float scaleF[2][2], mnew[2][2];
#pragma unroll
        for (int mi = 0; mi < 2; mi++) {
#pragma unroll
            for (int half = 0; half < 2; half++) {
                int r = warp_m * 32 + mi * 16 + half * 8 + gid;
                float mc = fmaxf(rowm[r][0], rowm[r][1]);
                float mn = fmaxf(mstate[mi][half], mc);
                scaleF[mi][half] = fexp(mstate[mi][half] - mn);
                mnew[mi][half] = mn;
                float s = 0.f;
#pragma unroll
                for (int ni = 0; ni < 8; ni++) {
#pragma unroll
                    for (int e = 0; e < 2; e++) {
                        float ev = fexp(cs[mi][ni][half*2 + e] - mn);
                        cs[mi][ni][half*2 + e] = ev;
                        s += ev;
                    }
                }
#pragma unroll
                for (int o = 1; o <= 2; o <<= 1) s += __shfl_xor_sync(0xffffffffu, s, o);
                if (tig == 0) rowsum[r][warp_n] = s;
            }
        }
        __syncthreads();

#pragma unroll
        for (int mi = 0; mi < 2; mi++) {
#pragma unroll
            for (int half = 0; half < 2; half++) {
                int r = warp_m * 32 + mi * 16 + half * 8 + gid;
                float sc = scaleF[mi][half];
                lstate[mi][half] = lstate[mi][half] * sc + rowsum[r][0] + rowsum[r][1];
                mstate[mi][half] = mnew[mi][half];
#pragma unroll
                for (int ni = 0; ni < 4; ni++) {
                    c2[mi][ni][half*2 + 0] *= sc;
                    c2[mi][ni][half*2 + 1] *= sc;
                }
#pragma unroll
                for (int ni = 0; ni < 8; ni++) {
                    int col = warp_n * 64 + ni * 8 + tig * 2;
                    uint32_t pk = ((uint32_t)__bfloat16_as_ushort(
                                      __float2bfloat16_rn(cs[mi][ni][half*2+1])) << 16)
                                | (uint32_t)__bfloat16_as_ushort(
                                      __float2bfloat16_rn(cs[mi][ni][half*2+0]));
                    *reinterpret_cast<uint32_t*>(&PS[r * 136 + col]) = pk;
                }
            }
        }
        __syncthreads();

#pragma unroll
        for (int ks = 0; ks < 8; ks++) {
            int k0 = ks * 16;
            uint32_t a[2][4];
#pragma unroll
            for (int mi = 0; mi < 2; mi++) {
                int m = warp_m * 32 + mi * 16 + (lane & 15);
                int kcc = k0 + ((lane >> 4) << 3);
                uint32_t addr = smem_u32(PS + m * 136 + kcc);
                asm volatile("ldmatrix.sync.aligned.m8n8.x4.shared.b16 {%0,%1,%2,%3}, [%4];"
                             : "=r"(a[mi][0]), "=r"(a[mi][1]), "=r"(a[mi][2]), "=r"(a[mi][3])
                             : "r"(addr));
            }
            uint32_t bb[4][2];
#pragma unroll
            for (int nt = 0; nt < 2; nt++) {
                int kr = k0 + (lane & 15);
                int n = warp_n * 32 + nt * 16 + ((lane >> 4) << 3);
                uint32_t addr = smem_u32(vS + kr * 72 + n);
                asm volatile("ldmatrix.sync.aligned.m8n8.x4.trans.shared.b16 {%0,%1,%2,%3}, [%4];"
                             : "=r"(bb[nt*2][0]), "=r"(bb[nt*2][1]),
                               "=r"(bb[nt*2+1][0]), "=r"(bb[nt*2+1][1])
                             : "r"(addr));
            }
#pragma unroll
            for (int mi = 0; mi < 2; mi++)
#pragma unroll
                for (int ni = 0; ni < 4; ni++) {
                    asm volatile("mma.sync.aligned.m16n8k16.row.col.f32.bf16.bf16.f32 "
                                 "{%0,%1,%2,%3}, {%4,%5,%6,%7}, {%8,%9}, {%0,%1,%2,%3};\n"
                                 : "+f"(c2[mi][ni][0]), "+f"(c2[mi][ni][1]),
                                   "+f"(c2[mi][ni][2]), "+f"(c2[mi][ni][3])
                                 : "r"(a[mi][0]), "r"(a[mi][1]), "r"(a[mi][2]), "r"(a[mi][3]),
                                   "r"(bb[ni][0]), "r"(bb[ni][1]));
                }
        }
        __syncthreads();
    }

    bf16* outBase = vecOut + (size_t)b * DD + (size_t)h * DHH;
#pragma unroll
    for (int mi = 0; mi < 2; mi++) {
        int row0 = warp_m * 32 + mi * 16 + gid;
#pragma unroll
        for (int ni = 0; ni < 4; ni++) {
            int col = warp_n * 32 + ni * 8 + tig * 2;
#pragma unroll
            for (int half = 0; half < 2; half++) {
                int gm = row0 + half * 8;
                float inv = 1.0f / lstate[mi][half];
                uint32_t pk = ((uint32_t)__bfloat16_as_ushort(
                                  __float2bfloat16_rn(c2[mi][ni][half*2+1] * inv)) << 16)
                            | (uint32_t)__bfloat16_as_ushort(
                                  __float2bfloat16_rn(c2[mi][ni][half*2+0] * inv));
                *reinterpret_cast<uint32_t*>(&outBase[(size_t)gm * (BB*DD) + col]) = pk;
            }
        }
    }
}

// ======== vocab-logits GEMM with fused stats + tgt extract (3-stage) ========
__global__ __launch_bounds__(256, 2)
void sgemm_vocab(const bf16* __restrict__ A, const bf16* __restrict__ Bw,
                 const int* __restrict__ decode_target,
                 float* __restrict__ pm, float* __restrict__ ps,
                 float* __restrict__ tgtlog,
                 int K, int lda, int ldb)
{
    extern __shared__ bf16 ds[];
    bf16* AsB = ds;
    bf16* BsB = ds + 3*128*40;

    int tid = threadIdx.x;
    int warp = tid >> 5, lane = tid & 31;
    int warp_m = warp >> 1;
    int warp_n = warp & 1;
    int rowA0 = blockIdx.y * 128;
    int colB0 = blockIdx.x * 128;

    int ldrow = tid >> 1;
    int ldkoff = (tid & 1) * 16;

    float c[2][8][4];
#pragma unroll
    for (int mi = 0; mi < 2; mi++)
#pragma unroll
        for (int ni = 0; ni < 8; ni++)
#pragma unroll
            for (int r = 0; r < 4; r++) c[mi][ni][r] = 0.f;

    const bf16* Agp = &A[(size_t)(rowA0 + ldrow) * lda + ldkoff];
    const bf16* Bgp = &Bw[(size_t)(colB0 + ldrow) * ldb + ldkoff];

    int nk = K >> 5;
#pragma unroll
    for (int s = 0; s < 2; s++) {
        bf16* as = AsB + s * (128*40);
        bf16* bs = BsB + s * (128*40);
        uint32_t sa = smem_u32(as + ldrow * 40 + ldkoff);
        uint32_t sb = smem_u32(bs + ldrow * 40 + ldkoff);
        const bf16* ag = Agp + s * 32;
        const bf16* bg = Bgp + s * 32;
        asm volatile("cp.async.ca.shared.global [%0], [%1], 16;\n"
                     "cp.async.ca.shared.global [%2], [%3], 16;\n"
                     "cp.async.ca.shared.global [%4], [%5], 16;\n"
                     "cp.async.ca.shared.global [%6], [%7], 16;\n"
                     :: "r"(sa), "l"(ag), "r"(sa + 16), "l"(ag + 8),
                        "r"(sb), "l"(bg), "r"(sb + 16), "l"(bg + 8));
        asm volatile("cp.async.commit_group;");
    }

    for (int kt = 0; kt < nk; kt++) {
        asm volatile("cp.async.wait_group 1;");
        __syncthreads();
        int pf = kt + 2;
        if (pf < nk) {
            int sbuf = pf - (pf / 3) * 3;
            bf16* as = AsB + sbuf * (128*40);
            bf16* bs = BsB + sbuf * (128*40);
            uint32_t sa = smem_u32(as + ldrow * 40 + ldkoff);
            uint32_t sb = smem_u32(bs + ldrow * 40 + ldkoff);
            const bf16* ag = Agp + pf * 32;
            const bf16* bg = Bgp + pf * 32;
            asm volatile("cp.async.ca.shared.global [%0], [%1], 16;\n"
                         "cp.async.ca.shared.global [%2], [%3], 16;\n"
                         "cp.async.ca.shared.global [%4], [%5], 16;\n"
                         "cp.async.ca.shared.global [%6], [%7], 16;\n"
                         :: "r"(sa), "l"(ag), "r"(sa + 16), "l"(ag + 8),
                            "r"(sb), "l"(bg), "r"(sb + 16), "l"(bg + 8));
        }
        asm volatile("cp.async.commit_group;");

        int cbuf = kt - (kt / 3) * 3;
        bf16* as = AsB + cbuf * (128*40);
        bf16* bs = BsB + cbuf * (128*40);
#pragma unroll
        for (int ks = 0; ks < 2; ks++) {
            int k0 = ks * 16;
            uint32_t a[2][4];
#pragma unroll
            for (int mi = 0; mi < 2; mi++) {
                int m = warp_m * 32 + mi * 16 + (lane & 15);
                int kc = k0 + ((lane >> 4) << 3);
                uint32_t addr = smem_u32(as + m * 40 + kc);
                asm volatile("ldmatrix.sync.aligned.m8n8.x4.shared.b16 {%0,%1,%2,%3}, [%4];"
                             : "=r"(a[mi][0]), "=r"(a[mi][1]), "=r"(a[mi][2]), "=r"(a[mi][3])
                             : "r"(addr));
            }
            uint32_t b[8][2];
#pragma unroll
            for (int nt = 0; nt < 4; nt++) {
                int n = warp_n * 64 + nt * 16 + (lane & 7) + ((lane >> 4) << 3);
                int kc = k0 + (((lane >> 3) & 1) << 3);
                uint32_t addr = smem_u32(bs + n * 40 + kc);
                asm volatile("ldmatrix.sync.aligned.m8n8.x4.shared.b16 {%0,%1,%2,%3}, [%4];"
                             : "=r"(b[nt*2][0]), "=r"(b[nt*2][1]),
                               "=r"(b[nt*2+1][0]), "=r"(b[nt*2+1][1])
                             : "r"(addr));
            }
#pragma unroll
            for (int mi = 0; mi < 2; mi++)
#pragma unroll
                for (int ni = 0; ni < 8; ni++) {
                    asm volatile(
                        "mma.sync.aligned.m16n8k16.row.col.f32.bf16.bf16.f32 "
                        "{%0,%1,%2,%3}, {%4,%5,%6,%7}, {%8,%9}, {%0,%1,%2,%3};\n"
                        : "+f"(c[mi][ni][0]), "+f"(c[mi][ni][1]),
                          "+f"(c[mi][ni][2]), "+f"(c[mi][ni][3])
                        : "r"(a[mi][0]), "r"(a[mi][1]), "r"(a[mi][2]), "r"(a[mi][3]),
                          "r"(b[ni][0]), "r"(b[ni][1]));
                }
        }
    }

    __shared__ int   stgt[128];
    __shared__ float smx[128][2];
    __shared__ float ssx[128][2];
    if (tid < 128) {
        int grow = rowA0 + tid;
        stgt[tid] = decode_target[(grow & (BB-1)) * SS + (grow >> 3)];
    }
    __syncthreads();

    int gid = lane >> 2, tig = lane & 3;
#pragma unroll
    for (int mi = 0; mi < 2; mi++) {
#pragma unroll
        for (int half = 0; half < 2; half++) {
            int rl = warp_m * 32 + mi * 16 + half * 8 + gid;
            int tgt_c = stgt[rl] - colB0;
            float m = -1e30f, s = 0.f;
#pragma unroll
            for (int ni = 0; ni < 8; ni++) {
#pragma unroll
                for (int e = 0; e < 2; e++) {
                    float v = c[mi][ni][half * 2 + e];
                    int coll = warp_n * 64 + ni * 8 + tig * 2 + e;
                    if (coll == tgt_c) tgtlog[rowA0 + rl] = v;
                    if (v <= m) s += fexp(v - m);
                    else { s = s * fexp(m - v) + 1.0f; m = v; }
                }
            }
#pragma unroll
            for (int o = 1; o <= 2; o <<= 1) {
                float mo = __shfl_xor_sync(0xffffffffu, m, o);
                float so = __shfl_xor_sync(0xffffffffu, s, o);
                float M = fmaxf(m, mo);
                s = s * fexp(m - M) + so * fexp(mo - M);
                m = M;
            }
            if (tig == 0) { smx[rl][warp_n] = m; ssx[rl][warp_n] = s; }
        }
    }
    __syncthreads();
    if (tid < 128) {
        float m0 = smx[tid][0], s0 = ssx[tid][0];
        float m1 = smx[tid][1], s1 = ssx[tid][1];
        float M = fmaxf(m0, m1);
        float S = s0 * fexp(m0 - M) + s1 * fexp(m1 - M);
        pm[(size_t)(rowA0 + tid) * 256 + blockIdx.x] = M;
        ps[(size_t)(rowA0 + tid) * 256 + blockIdx.x] = S;
    }
}

__global__ void stats_final(const float* __restrict__ pm, const float* __restrict__ ps,
                            float* __restrict__ rmax, float* __restrict__ rsum)
{
    int t = blockIdx.x;
    int lane = threadIdx.x;
    float m = -1e30f, s = 0.f;
    for (int i = lane; i < NTILE; i += 32) {
        float mi = pm[(size_t)t * 256 + i];
        float si = ps[(size_t)t * 256 + i];
        float M = fmaxf(m, mi);
        s = s * fexp(m - M) + si * fexp(mi - M);
        m = M;
    }
#pragma unroll
    for (int o = 16; o > 0; o >>= 1) {
        float mo = __shfl_xor_sync(0xffffffffu, m, o);
        float so = __shfl_xor_sync(0xffffffffu, s, o);
        float M = fmaxf(m, mo);
        s = s * fexp(m - M) + so * fexp(mo - M);
        m = M;
    }
    if (lane == 0) { rmax[t] = m; rsum[t] = s; }
}

// ---------------- misc small kernels --------------------------------------------------
__global__ void pos_emb_kernel(float* __restrict__ r, bf16* __restrict__ rb)
{
    int i = blockIdx.x;
    float pos = (float)(SS - 1 - i);
    const float LOG1E4 = 9.210340371976184f;
    for (int d = threadIdx.x; d < DD; d += 256) {
        int j = (d < DD/2) ? d : d - DD/2;
        float invf = expf(-((float)j / (DD/2)) * LOG1E4);
        float a = pos * invf;
        float v = (d < DD/2) ? sinf(a) : cosf(a);
        r[i * DD + d] = v;
        rb[i * DD + d] = __float2bfloat16_rn(v);
    }
}

__global__ void embed_kernel(const int* __restrict__ dec, const float* __restrict__ emb,
                             float* __restrict__ core, bf16* __restrict__ coreb)
{
    int t = blockIdx.x;
    int b = t & (BB-1), s = t >> 3;
    int id = dec[b * SS + s];
    const float* src = emb + (size_t)id * DD;
    for (int d = threadIdx.x; d < DD; d += 256) {
        float v = src[d];
        core[(size_t)t * DD + d] = v;
        coreb[(size_t)t * DD + d] = __float2bfloat16_rn(v);
    }
}

__global__ void transpose_enc(const float* __restrict__ enc, float* __restrict__ enct,
                              bf16* __restrict__ enctb)
{
    int t = blockIdx.x;
    int b = t & (BB-1), e = t >> 3;
    const float* src = enc + ((size_t)b * EE + e) * DD;
    for (int d = threadIdx.x; d < DD; d += 256) {
        float v = src[d];
        enct[(size_t)t * DD + d] = v;
        enctb[(size_t)t * DD + d] = __float2bfloat16_rn(v);
    }
}

__device__ __forceinline__ float warp_max(float v)
{
#pragma unroll
    for (int o = 16; o > 0; o >>= 1) v = fmaxf(v, __shfl_xor_sync(0xffffffffu, v, o));
    return v;
}
__device__ __forceinline__ float warp_sum(float v)
{
#pragma unroll
    for (int o = 16; o > 0; o >>= 1) v += __shfl_xor_sync(0xffffffffu, v, o);
    return v;
}

__global__ void softmax_il(float* __restrict__ IL, const float* __restrict__ mask)
{
    int t = blockIdx.x;
    int b = t & (BB - 1);
    int k = threadIdx.x;
    int wid = k >> 5, lane = k & 31;
    float v = IL[(size_t)t * EE + k] + (1.0f - mask[b * EE + k]) * NEG_;
    __shared__ float red[16];
    float m = warp_max(v);
    if (lane == 0) red[wid] = m;
    __syncthreads();
    m = red[0];
#pragma unroll
    for (int w = 1; w < 16; w++) m = fmaxf(m, red[w]);
    float e = fexp(v - m);
    __shared__ float red2[16];
    float sum = warp_sum(e);
    if (lane == 0) red2[wid] = sum;
    __syncthreads();
    sum = red2[0];
#pragma unroll
    for (int w = 1; w < 16; w++) sum += red2[w];
    IL[(size_t)t * EE + k] = e / sum;
}

__global__ void add_ln(const float* __restrict__ resid, const float* __restrict__ parts,
                       int nparts,
                       float* __restrict__ out, bf16* __restrict__ outb,
                       const float* __restrict__ g, const float* __restrict__ bta)
{
    int t = blockIdx.x;
    int tid = threadIdx.x;
    __shared__ float zb[DD];
    __shared__ float red[256];
    float s = 0.f;
#pragma unroll
    for (int u = 0; u < 4; u++) {
        int d = tid + u * 256;
        float z = resid[(size_t)t * DD + d];
        for (int p = 0; p < nparts; p++)
            z += parts[(size_t)p * TT * DD + (size_t)t * DD + d];
        zb[d] = z; s += z;
    }
    red[tid] = s; __syncthreads();
    for (int st = 128; st > 0; st >>= 1) { if (tid < st) red[tid] += red[tid + st]; __syncthreads(); }
    float mean = red[0] * (1.0f / DD); __syncthreads();
    float v = 0.f;
#pragma unroll
    for (int u = 0; u < 4; u++) {
        int d = tid + u * 256;
        float dz = zb[d] - mean; v += dz * dz;
    }
    red[tid] = v; __syncthreads();
    for (int st = 128; st > 0; st >>= 1) { if (tid < st) red[tid] += red[tid + st]; __syncthreads(); }
    float inv = rsqrtf(red[0] * (1.0f / DD) + 1e-5f);
#pragma unroll
    for (int u = 0; u < 4; u++) {
        int d = tid + u * 256;
        float o = (zb[d] - mean) * inv * g[d] + bta[d];
        out[(size_t)t * DD + d] = o;
        if (outb) outb[(size_t)t * DD + d] = __float2bfloat16_rn(o);
    }
}

__global__ void mode_kernel(const float* __restrict__ core, const float* __restrict__ mw,
                            const float* __restrict__ mb, float* __restrict__ msig)
{
    int t = blockIdx.x;
    int tid = threadIdx.x;
    int wid = tid >> 5, lane = tid & 31;
    float s = 0.f;
    for (int d = tid; d < DD; d += 256) s += core[(size_t)t * DD + d] * mw[d];
    s = warp_sum(s);
    __shared__ float red[8];
    if (lane == 0) red[wid] = s;
    __syncthreads();
    if (tid == 0) {
        float tot = red[0];
#pragma unroll
        for (int w = 1; w < 8; w++) tot += red[w];
        msig[t] = 1.0f / (1.0f + expf(-(tot + mb[0])));
    }
}

__global__ void zero_loss()
{
    g_lossacc[0] = 0.f;
    g_lossacc[1] = 0.f;
}

__global__ void loss_partial(const float* __restrict__ tgtlog, const float* __restrict__ rmax,
                             const float* __restrict__ rsum, const float* __restrict__ msig,
                             const float* __restrict__ IL, const int* __restrict__ input_ids,
                             const int* __restrict__ decode_target)
{
    int tid = threadIdx.x;
    int wid = tid >> 5, lane = tid & 31;
    int t = blockIdx.x * 8 + wid;
    float acc = 0.f, cnt = 0.f;
    int b = t & (BB - 1), sIdx = t >> 3;
    int tgt = decode_target[b * SS + sIdx];
    if (tgt != 0) {
        const int* ids = input_ids + b * EE;
        const float* il = IL + (size_t)t * EE;
        float cp = 0.f;
        for (int j = lane; j < EE; j += 32)
            if (ids[j] == tgt) cp += il[j];
        cp = warp_sum(cp);
        if (lane == 0) {
            float mg = msig[t];
            float p = expf(tgtlog[t] - rmax[t]) / rsum[t] * mg;
            p += (1.0f - mg) * cp;
            acc = -logf(p + 1e-6f);
            cnt = 1.0f;
        }
    }
    __shared__ float sa[8], sc[8];
    if (lane == 0) { sa[wid] = acc; sc[wid] = cnt; }
    __syncthreads();
    if (tid == 0) {
        float A = 0.f, C = 0.f;
#pragma unroll
        for (int w = 0; w < 8; w++) { A += sa[w]; C += sc[w]; }
        atomicAdd(&g_lossacc[0], A);
        atomicAdd(&g_lossacc[1], C);
    }
}

__global__ void loss_final(float* __restrict__ out)
{
    out[threadIdx.x] = g_lossacc[0] / g_lossacc[1];
}

// ---------------- host orchestration --------------------------------------------------
static void* symaddr(const void* sym)
{
    void* p = nullptr;
    cudaGetSymbolAddress(&p, sym);
    return p;
}

static void cvtS(const float* src, bf16* dst, size_t n, cudaStream_t st)
{
    int blocks = (int)((n / 4 + 255) / 256);
    cvt_bf16<<<blocks, 256, 0, st>>>(src, dst, (int)n);
}

extern "C" void kernel_launch(void* const* d_in, const int* in_sizes, int n_in,
                              void* d_out, int out_size)
{
    const int*   input_ids     = (const int*)d_in[0];
    const float* encoder_rep   = (const float*)d_in[1];
    const float* input_mask    = (const float*)d_in[2];
    const int*   decode_input  = (const int*)d_in[3];
    const int*   decode_target = (const int*)d_in[4];
    const float* word_emb      = (const float*)d_in[5];
    const float* qkv_w         = (const float*)d_in[6];
    const float* r_w           = (const float*)d_in[7];
    const float* o_w           = (const float*)d_in[8];
    const float* kv_w          = (const float*)d_in[9];
    const float* q_w           = (const float*)d_in[10];
    const float* io_w          = (const float*)d_in[11];
    const float* rr_bias       = (const float*)d_in[12];
    const float* rw_bias       = (const float*)d_in[13];
    const float* ln1_g         = (const float*)d_in[14];
    const float* ln1_b         = (const float*)d_in[15];
    const float* ln2_g         = (const float*)d_in[16];
    const float* ln2_b         = (const float*)d_in[17];
    const float* ffn_w1        = (const float*)d_in[18];
    const float* ffn_b1        = (const float*)d_in[19];
    const float* ffn_w2        = (const float*)d_in[20];
    const float* ffn_b2        = (const float*)d_in[21];
    const float* ln3_g         = (const float*)d_in[22];
    const float* ln3_b         = (const float*)d_in[23];
    const float* out_w         = (const float*)d_in[24];
    const float* out_b         = (const float*)d_in[25];
    const float* copy_w        = (const float*)d_in[26];
    const float* copy_b        = (const float*)d_in[27];
    const float* mode_w        = (const float*)d_in[28];
    const float* mode_b        = (const float*)d_in[29];

    float* p_core  = (float*)symaddr(g_core);
    float* p_r     = (float*)symaddr(g_r);
    float* p_x     = (float*)symaddr(g_x);
    float* p_y     = (float*)symaddr(g_y);
    float* p_tmpk  = (float*)symaddr(g_tmpk);
    float* p_enct  = (float*)symaddr(g_enct);
    float* p_IL    = (float*)symaddr(g_IL);
    float* p_pm    = (float*)symaddr(g_pm);
    float* p_ps    = (float*)symaddr(g_ps);
    float* p_tgt   = (float*)symaddr(g_tgtlog);
    float* p_rmax  = (float*)symaddr(g_rmax);
    float* p_rsum  = (float*)symaddr(g_rsum);
    float* p_msig  = (float*)symaddr(g_msig);

    bf16* pb_core = (bf16*)symaddr(b_core);
    bf16* pb_r    = (bf16*)symaddr(b_r);
    bf16* pb_rkall= (bf16*)symaddr(b_rkall);
    bf16* pb_x    = (bf16*)symaddr(b_x);
    bf16* pb_y    = (bf16*)symaddr(b_y);
    bf16* pb_vec  = (bf16*)symaddr(b_vec);
    bf16* pb_enct = (bf16*)symaddr(b_enct);
    bf16* pb_h    = (bf16*)symaddr(b_h);
    bf16* pb_outb = (bf16*)symaddr(b_outb);
    bf16* pb_cpyh = (bf16*)symaddr(b_copyhb);
    bf16* pb_heads= (bf16*)symaddr(b_heads);
    bf16* pb_kvall= (bf16*)symaddr(b_kvall);

    bf16* pw_qkv = (bf16*)symaddr(w_qkv);
    bf16* pw_r   = (bf16*)symaddr(w_r);
    bf16* pw_o   = (bf16*)symaddr(w_o);
    bf16* pw_kv  = (bf16*)symaddr(w_kv);
    bf16* pw_q   = (bf16*)symaddr(w_q);
    bf16* pw_io  = (bf16*)symaddr(w_io);
    bf16* pw_f1  = (bf16*)symaddr(w_f1);
    bf16* pw_f2  = (bf16*)symaddr(w_f2);
    bf16* pw_emb = (bf16*)symaddr(w_emb);
    bf16* pw_out = (bf16*)symaddr(w_out);
    bf16* pw_cp  = (bf16*)symaddr(w_copy);

    cudaFuncSetAttribute(sgemm_bf, cudaFuncAttributeMaxDynamicSharedMemorySize, SMEMSZ);
    cudaFuncSetAttribute(sgemm_vocab, cudaFuncAttributeMaxDynamicSharedMemorySize, SMEMSZ);
    cudaFuncSetAttribute(fused_self_attn, cudaFuncAttributeMaxDynamicSharedMemorySize, SMEM_ATT);
    cudaFuncSetAttribute(fused_cross_attn, cudaFuncAttributeMaxDynamicSharedMemorySize, SMEM_XATT);

    static cudaStream_t s2 = nullptr;
    static cudaEvent_t evFork = nullptr, evJoin = nullptr, evTail = nullptr, evTail2 = nullptr;
    if (!s2) {
        cudaStreamCreateWithFlags(&s2, cudaStreamNonBlocking);
        cudaEventCreateWithFlags(&evFork, cudaEventDisableTiming);
        cudaEventCreateWithFlags(&evJoin, cudaEventDisableTiming);
        cudaEventCreateWithFlags(&evTail, cudaEventDisableTiming);
        cudaEventCreateWithFlags(&evTail2, cudaEventDisableTiming);
    }

    cvtS(r_w,    pw_r,   (size_t)LL*DD*DD, 0);
    cvtS(kv_w,   pw_kv,  (size_t)LL*2*DD*DD, 0);
    cvtS(qkv_w,  pw_qkv, (size_t)LL*3*DD*DD, 0);

    cudaEventRecord(evFork, 0);
    cudaStreamWaitEvent(s2, evFork, 0);
    cvtS(o_w,    pw_o,   (size_t)LL*DD*DD, s2);
    cvtS(q_w,    pw_q,   (size_t)LL*DD*DD, s2);
    cvtS(io_w,   pw_io,  (size_t)LL*DD*DD, s2);
    cvtS(ffn_w1, pw_f1,  (size_t)LL*FF_*DD, s2);
    cvtS(ffn_w2, pw_f2,  (size_t)LL*DD*FF_, s2);
    cvtS(word_emb, pw_emb, (size_t)VV*DD, s2);
    cvtS(out_w,  pw_out, (size_t)DD*DD, s2);
    cvtS(copy_w, pw_cp,  (size_t)DD*DD, s2);
    cudaEventRecord(evJoin, s2);

    pos_emb_kernel<<<SS, 256>>>(p_r, pb_r);
    embed_kernel<<<TT, 256>>>(decode_input, word_emb, p_core, pb_core);
    transpose_enc<<<TE, 256>>>(encoder_rep, p_enct, pb_enct);

    sgemm_bf<<<dim3(LL*DD/128, SS/128), 256, SMEMSZ>>>(pb_r, pw_r, nullptr, pb_rkall,
        nullptr, DD, DD, DD, LL*DD, 0, 1, 0, 0, 0, 0);
    sgemm_bf<<<dim3(LL*2*DD/128, TE/128), 256, SMEMSZ>>>(pb_enct, pw_kv, nullptr, pb_kvall,
        nullptr, DD, DD, DD, LL*2*DD, 0, 1, 0, 0, 0, 0);

    bool joined = false;
    for (int l = 0; l < LL; l++) {
        sgemm_bf<<<dim3(3*DD/128, TT/128), 256, SMEMSZ>>>(pb_core, pw_qkv + (size_t)l*3*DD*DD,
            nullptr, pb_heads, nullptr, DD, DD, DD, 3*DD, 0, 1, 0, 0, 0, 0);
        fused_self_attn<<<BB*HH, 256, SMEM_ATT>>>(pb_heads, pb_rkall, pb_vec,
            rw_bias + (size_t)l*HH*DHH, rr_bias + (size_t)l*HH*DHH, l);
        if (!joined) { cudaStreamWaitEvent(0, evJoin, 0); joined = true; }
        sgemm_bf<<<dim3(DD/128, TT/128, 2), 256, SMEMSZ>>>(pb_vec, pw_o + (size_t)l*DD*DD,
            p_tmpk, nullptr, nullptr, DD, DD, DD, DD, 0, 2, (long long)TT*DD, 0, 0, 0);
        add_ln<<<TT, 256>>>(p_core, p_tmpk, 2, p_x, pb_x, ln1_g + l*DD, ln1_b + l*DD);

        // cross attention: q2 as split-K=2 (128 CTAs) into partial slabs, summed in fused_cross
        sgemm_bf<<<dim3(DD/128, TT/128, 2), 256, SMEMSZ>>>(pb_x, pw_q + (size_t)l*DD*DD,
            p_tmpk, nullptr, nullptr, DD, DD, DD, DD, 0, 2, (long long)TT*DD, 0, 0, 0);
        fused_cross_attn<<<BB*HH, 256, SMEM_XATT>>>(p_tmpk, p_tmpk + (size_t)TT*DD,
            pb_kvall, input_mask, pb_vec, l);
        sgemm_bf<<<dim3(DD/128, TT/128, 2), 256, SMEMSZ>>>(pb_vec, pw_io + (size_t)l*DD*DD,
            p_tmpk, nullptr, nullptr, DD, DD, DD, DD, 0, 2, (long long)TT*DD, 0, 0, 0);
        add_ln<<<TT, 256>>>(p_x, p_tmpk, 2, p_y, pb_y, ln2_g + l*DD, ln2_b + l*DD);

        // FFN
        sgemm_bf<<<dim3(FF_/128, TT/128), 256, SMEMSZ>>>(pb_y, pw_f1 + (size_t)l*FF_*DD,
            nullptr, pb_h, ffn_b1 + (size_t)l*FF_, DD, DD, DD, FF_, 1, 1, 0, 0, 0, 0);
        sgemm_bf<<<dim3(DD/128, TT/128, 4), 256, SMEMSZ>>>(pb_h, pw_f2 + (size_t)l*DD*FF_,
            p_tmpk, nullptr, ffn_b2 + (size_t)l*DD, FF_, FF_, FF_, DD, 0, 4, (long long)TT*DD, 0, 0, 0);
        add_ln<<<TT, 256>>>(p_y, p_tmpk, 4, p_core, pb_core, ln3_g + l*DD, ln3_b + l*DD);
    }

    // ---- tail: two independent chains overlapped ----
    cudaEventRecord(evTail, 0);
    cudaStreamWaitEvent(s2, evTail, 0);
    sgemm_bf<<<dim3(DD/128, TT/128), 256, SMEMSZ, s2>>>(pb_core, pw_cp, nullptr, pb_cpyh, copy_b,
        DD, DD, DD, DD, 0, 1, 0, 0, 0, 0);
    sgemm_bf<<<dim3(EE/128, SS/128, BB), 256, SMEMSZ, s2>>>(pb_cpyh, pb_enct, p_IL, nullptr,
        nullptr, DD, BB*DD, BB*DD, BB*EE, 0, 1, 0,
        (long long)DD, (long long)DD, (long long)EE);
    softmax_il<<<TT, 512, 0, s2>>>(p_IL, input_mask);
    mode_kernel<<<TT, 256, 0, s2>>>(p_core, mode_w, mode_b, p_msig);
    cudaEventRecord(evTail2, s2);

    sgemm_bf<<<dim3(DD/128, TT/128), 256, SMEMSZ>>>(pb_core, pw_out, nullptr, pb_outb, out_b,
        DD, DD, DD, DD, 0, 1, 0, 0, 0, 0);
    sgemm_vocab<<<dim3(NTILE, TT/128), 256, SMEMSZ>>>(pb_outb, pw_emb, decode_target,
        p_pm, p_ps, p_tgt, DD, DD, DD);
    stats_final<<<TT, 32>>>(p_pm, p_ps, p_rmax, p_rsum);
    zero_loss<<<1, 1>>>();

    cudaStreamWaitEvent(0, evTail2, 0);
    loss_partial<<<TT/8, 256>>>(p_tgt, p_rmax, p_rsum, p_msig, p_IL, input_ids, decode_target);
    loss_final<<<1, BB>>>((float*)d_out);
}

// round 16
// speedup vs baseline: 1.0992x; 1.0325x over previous
#include <cuda_runtime.h>
#include <cuda_bf16.h>
#include <math.h>
#include <stdint.h>

// Problem dims
#define BB 8
#define SS 128
#define EE 512
#define DD 1024
#define HH 16
#define LL 4
#define VV 32000
#define DHH 64
#define FF_ 4096
#define TT (SS*BB)
#define TE (EE*BB)
#define NTILE (VV/128)
#define SCALE_ 0.125f
#define NEG_ (-1e30f)

typedef __nv_bfloat16 bf16;

// ---------------- scratch ----------------
__device__ float g_r[SS*DD];
__device__ float g_core[TT*DD];
__device__ float g_x[TT*DD];
__device__ float g_y[TT*DD];
__device__ float g_tmpk[4*TT*DD];
__device__ float g_enct[TE*DD];
__device__ float g_IL[TT*EE];
__device__ float g_pm[TT*256];
__device__ float g_ps[TT*256];
__device__ float g_tgtlog[TT];
__device__ float g_rmax[TT];
__device__ float g_rsum[TT];
__device__ float g_msig[TT];
__device__ float g_lossacc[2];

// bf16 activations
__device__ bf16 b_core[TT*DD];
__device__ bf16 b_r[SS*DD];
__device__ bf16 b_rkall[SS*LL*DD];
__device__ bf16 b_x[TT*DD];
__device__ bf16 b_y[TT*DD];
__device__ bf16 b_vec[TT*DD];
__device__ bf16 b_enct[TE*DD];
__device__ bf16 b_h[TT*FF_];
__device__ bf16 b_outb[TT*DD];
__device__ bf16 b_copyhb[TT*DD];
__device__ bf16 b_heads[TT*3*DD];
__device__ bf16 b_kvall[(size_t)TE*LL*2*DD];

// bf16 weights
__device__ bf16 w_qkv[LL*3*DD*DD];
__device__ bf16 w_r[LL*DD*DD];
__device__ bf16 w_o[LL*DD*DD];
__device__ bf16 w_kv[LL*2*DD*DD];
__device__ bf16 w_q[LL*DD*DD];
__device__ bf16 w_io[LL*DD*DD];
__device__ bf16 w_f1[LL*FF_*DD];
__device__ bf16 w_f2[LL*DD*FF_];
__device__ bf16 w_emb[(size_t)VV*DD];
__device__ bf16 w_out[DD*DD];
__device__ bf16 w_copy[DD*DD];

__device__ __forceinline__ uint32_t smem_u32(const void* p)
{
    return (uint32_t)__cvta_generic_to_shared(p);
}

// FFMA-only exp (no MUFU)
__device__ __forceinline__ float fexp(float x)
{
    x = fmaxf(x, -87.0f);
    float y = x * 1.4426950408889634f;
    float z = y + 12582912.0f;
    int   ki = __float_as_int(z) - 0x4B400000;
    float kf = z - 12582912.0f;
    float f = y - kf;
    float p = 0.00133336f;
    p = fmaf(p, f, 0.00961813f);
    p = fmaf(p, f, 0.05550411f);
    p = fmaf(p, f, 0.24022651f);
    p = fmaf(p, f, 0.69314718f);
    p = fmaf(p, f, 1.0f);
    return p * __int_as_float((ki + 127) << 23);
}

// ---------------- f32 -> bf16 conversion ----------------
__global__ void cvt_bf16(const float* __restrict__ src, bf16* __restrict__ dst, int n)
{
    int i = (blockIdx.x * 256 + threadIdx.x) * 4;
    if (i >= n) return;
    float4 v = *reinterpret_cast<const float4*>(src + i);
    uint32_t lo = ((uint32_t)__bfloat16_as_ushort(__float2bfloat16_rn(v.y)) << 16)
                | (uint32_t)__bfloat16_as_ushort(__float2bfloat16_rn(v.x));
    uint32_t hi = ((uint32_t)__bfloat16_as_ushort(__float2bfloat16_rn(v.w)) << 16)
                | (uint32_t)__bfloat16_as_ushort(__float2bfloat16_rn(v.z));
    *reinterpret_cast<uint2*>(dst + i) = make_uint2(lo, hi);
}

// 3-stage cp.async pipeline, 128x128 block (best known)
#define SMEMSZ (3*2*128*40*2)

__global__ __launch_bounds__(256, 2)
void sgemm_bf(const bf16* __restrict__ A, const bf16* __restrict__ Bw,
              float* __restrict__ Cf, bf16* __restrict__ Cb,
              const float* __restrict__ bias,
              int K, int lda, int ldb, int ldc, int act, int ksplit,
              long long partStride,
              long long aBS, long long bBS, long long cBS)
{
    extern __shared__ bf16 ds[];
    bf16* AsB = ds;
    bf16* BsB = ds + 3*128*40;

    int tid = threadIdx.x;
    int warp = tid >> 5, lane = tid & 31;
    int warp_m = warp >> 1;
    int warp_n = warp & 1;
    int rowA0 = blockIdx.y * 128;
    int colB0 = blockIdx.x * 128;

    long long zb = (ksplit == 1) ? (long long)blockIdx.z : 0;
    const bf16* Az = A + zb * aBS;
    const bf16* Bz = Bw + zb * bBS;

    int Kloc = K / ksplit;
    int kgbase = (ksplit > 1) ? blockIdx.z * Kloc : 0;

    int ldrow = tid >> 1;
    int ldkoff = (tid & 1) * 16;

    float c[2][8][4];
#pragma unroll
    for (int mi = 0; mi < 2; mi++)
#pragma unroll
        for (int ni = 0; ni < 8; ni++)
#pragma unroll
            for (int r = 0; r < 4; r++) c[mi][ni][r] = 0.f;

    const bf16* Agp = &Az[(size_t)(rowA0 + ldrow) * lda + kgbase + ldkoff];
    const bf16* Bgp = &Bz[(size_t)(colB0 + ldrow) * ldb + kgbase + ldkoff];

    int nk = Kloc >> 5;
#pragma unroll
    for (int s = 0; s < 2; s++) {
        bf16* as = AsB + s * (128*40);
        bf16* bs = BsB + s * (128*40);
        uint32_t sa = smem_u32(as + ldrow * 40 + ldkoff);
        uint32_t sb = smem_u32(bs + ldrow * 40 + ldkoff);
        const bf16* ag = Agp + s * 32;
        const bf16* bg = Bgp + s * 32;
        asm volatile("cp.async.ca.shared.global [%0], [%1], 16;\n"
                     "cp.async.ca.shared.global [%2], [%3], 16;\n"
                     "cp.async.ca.shared.global [%4], [%5], 16;\n"
                     "cp.async.ca.shared.global [%6], [%7], 16;\n"
                     :: "r"(sa), "l"(ag), "r"(sa + 16), "l"(ag + 8),
                        "r"(sb), "l"(bg), "r"(sb + 16), "l"(bg + 8));
        asm volatile("cp.async.commit_group;");
    }

    for (int kt = 0; kt < nk; kt++) {
        asm volatile("cp.async.wait_group 1;");
        __syncthreads();
        int pf = kt + 2;
        if (pf < nk) {
            int sbuf = pf - (pf / 3) * 3;
            bf16* as = AsB + sbuf * (128*40);
            bf16* bs = BsB + sbuf * (128*40);
            uint32_t sa = smem_u32(as + ldrow * 40 + ldkoff);
            uint32_t sb = smem_u32(bs + ldrow * 40 + ldkoff);
            const bf16* ag = Agp + pf * 32;
            const bf16* bg = Bgp + pf * 32;
            asm volatile("cp.async.ca.shared.global [%0], [%1], 16;\n"
                         "cp.async.ca.shared.global [%2], [%3], 16;\n"
                         "cp.async.ca.shared.global [%4], [%5], 16;\n"
                         "cp.async.ca.shared.global [%6], [%7], 16;\n"
                         :: "r"(sa), "l"(ag), "r"(sa + 16), "l"(ag + 8),
                            "r"(sb), "l"(bg), "r"(sb + 16), "l"(bg + 8));
        }
        asm volatile("cp.async.commit_group;");

        int cbuf = kt - (kt / 3) * 3;
        bf16* as = AsB + cbuf * (128*40);
        bf16* bs = BsB + cbuf * (128*40);
#pragma unroll
        for (int ks = 0; ks < 2; ks++) {
            int k0 = ks * 16;
            uint32_t a[2][4];
#pragma unroll
            for (int mi = 0; mi < 2; mi++) {
                int m = warp_m * 32 + mi * 16 + (lane & 15);
                int kc = k0 + ((lane >> 4) << 3);
                uint32_t addr = smem_u32(as + m * 40 + kc);
                asm volatile("ldmatrix.sync.aligned.m8n8.x4.shared.b16 {%0,%1,%2,%3}, [%4];"
                             : "=r"(a[mi][0]), "=r"(a[mi][1]), "=r"(a[mi][2]), "=r"(a[mi][3])
                             : "r"(addr));
            }
            uint32_t b[8][2];
#pragma unroll
            for (int nt = 0; nt < 4; nt++) {
                int n = warp_n * 64 + nt * 16 + (lane & 7) + ((lane >> 4) << 3);
                int kc = k0 + (((lane >> 3) & 1) << 3);
                uint32_t addr = smem_u32(bs + n * 40 + kc);
                asm volatile("ldmatrix.sync.aligned.m8n8.x4.shared.b16 {%0,%1,%2,%3}, [%4];"
                             : "=r"(b[nt*2][0]), "=r"(b[nt*2][1]),
                               "=r"(b[nt*2+1][0]), "=r"(b[nt*2+1][1])
                             : "r"(addr));
            }
#pragma unroll
            for (int mi = 0; mi < 2; mi++)
#pragma unroll
                for (int ni = 0; ni < 8; ni++) {
                    asm volatile(
                        "mma.sync.aligned.m16n8k16.row.col.f32.bf16.bf16.f32 "
                        "{%0,%1,%2,%3}, {%4,%5,%6,%7}, {%8,%9}, {%0,%1,%2,%3};\n"
                        : "+f"(c[mi][ni][0]), "+f"(c[mi][ni][1]),
                          "+f"(c[mi][ni][2]), "+f"(c[mi][ni][3])
                        : "r"(a[mi][0]), "r"(a[mi][1]), "r"(a[mi][2]), "r"(a[mi][3]),
                          "r"(b[ni][0]), "r"(b[ni][1]));
                }
        }
    }

    bool addbias = (bias != nullptr) && (ksplit == 1 || blockIdx.z == 0);
    float* Cfz = Cf ? (Cf + (ksplit > 1 ? (size_t)blockIdx.z * partStride : (size_t)zb * cBS)) : nullptr;
    bf16*  Cbz = Cb ? (Cb + (size_t)zb * cBS) : nullptr;
#pragma unroll
    for (int mi = 0; mi < 2; mi++) {
        int row0 = rowA0 + warp_m * 32 + mi * 16 + (lane >> 2);
#pragma unroll
        for (int ni = 0; ni < 8; ni++) {
            int col = colB0 + warp_n * 64 + ni * 8 + (lane & 3) * 2;
            float bv0 = 0.f, bv1 = 0.f;
            if (addbias) { bv0 = bias[col]; bv1 = bias[col + 1]; }
#pragma unroll
            for (int half = 0; half < 2; half++) {
                int gm = row0 + half * 8;
                float v0 = c[mi][ni][half * 2 + 0] + bv0;
                float v1 = c[mi][ni][half * 2 + 1] + bv1;
                if (ksplit > 1) {
                    Cfz[(size_t)gm * ldc + col]     = v0;
                    Cfz[(size_t)gm * ldc + col + 1] = v1;
                } else {
                    if (act == 1) {
                        v0 = 0.5f * v0 * (1.0f + erff(v0 * 0.70710678118654752f));
                        v1 = 0.5f * v1 * (1.0f + erff(v1 * 0.70710678118654752f));
                    }
                    if (Cfz) {
                        Cfz[(size_t)gm * ldc + col]     = v0;
                        Cfz[(size_t)gm * ldc + col + 1] = v1;
                    }
                    if (Cbz) {
                        uint32_t pk = ((uint32_t)__bfloat16_as_ushort(__float2bfloat16_rn(v1)) << 16)
                                    | (uint32_t)__bfloat16_as_ushort(__float2bfloat16_rn(v0));
                        *reinterpret_cast<uint32_t*>(&Cbz[(size_t)gm * ldc + col]) = pk;
                    }
                }
            }
        }
    }
}

// ======== fully fused self-attention ========
#define SMEM_ATT (5*128*72*2)
__global__ __launch_bounds__(256, 1)
void fused_self_attn(const bf16* __restrict__ heads, const bf16* __restrict__ rkall,
                     bf16* __restrict__ vecOut,
                     const float* __restrict__ rwb, const float* __restrict__ rrb,
                     int layer)
{
    extern __shared__ bf16 dsA[];
    bf16* vS   = dsA;
    bf16* regA = dsA + 128*72;
    bf16* qrw  = regA;
    bf16* qrr  = regA + 128*72;
    bf16* kS   = regA + 2*128*72;
    bf16* rkS  = regA + 3*128*72;
    float* bdS = (float*)regA;
    bf16*  PS  = regA;

    __shared__ float rowm[128][2];
    __shared__ float rowsum[128][2];

    int z = blockIdx.x;
    int h = z % HH, b = z / HH;
    int tid = threadIdx.x;
    int warp = tid >> 5, lane = tid & 31;
    int warp_m = warp >> 1, warp_n = warp & 1;
    int gid = lane >> 2, tig = lane & 3;

    {
        int row = tid >> 1;
        int koff = (tid & 1) * 32;
        const bf16* qg  = heads + (size_t)b*3*DD + (size_t)h*DHH + (size_t)row*(BB*3*DD) + koff;
        const bf16* kg  = qg + DD;
        const bf16* vg  = qg + 2*DD;
        const bf16* rkg = rkall + (size_t)layer*DD + (size_t)h*DHH + (size_t)row*(LL*DD) + koff;
        const float* rwh = rwb + h*DHH + koff;
        const float* rrh = rrb + h*DHH + koff;
#pragma unroll
        for (int j = 0; j < 4; j++) {
            bf16 tq[8], trw[8], trr[8];
            *reinterpret_cast<uint4*>(tq) = *reinterpret_cast<const uint4*>(qg + j*8);
#pragma unroll
            for (int e = 0; e < 8; e++) {
                float qv = __bfloat162float(tq[e]);
                trw[e] = __float2bfloat16_rn(qv + rwh[j*8+e]);
                trr[e] = __float2bfloat16_rn(qv + rrh[j*8+e]);
            }
            *reinterpret_cast<uint4*>(&qrw[row*72 + koff + j*8]) = *reinterpret_cast<uint4*>(trw);
            *reinterpret_cast<uint4*>(&qrr[row*72 + koff + j*8]) = *reinterpret_cast<uint4*>(trr);
            *reinterpret_cast<uint4*>(&kS [row*72 + koff + j*8]) =
                *reinterpret_cast<const uint4*>(kg + j*8);
            *reinterpret_cast<uint4*>(&rkS[row*72 + koff + j*8]) =
                *reinterpret_cast<const uint4*>(rkg + j*8);
            *reinterpret_cast<uint4*>(&vS [row*72 + koff + j*8]) =
                *reinterpret_cast<const uint4*>(vg + j*8);
        }
    }
    __syncthreads();

    float cac[2][8][4], cbd[2][8][4];
#pragma unroll
    for (int mi = 0; mi < 2; mi++)
#pragma unroll
        for (int ni = 0; ni < 8; ni++)
#pragma unroll
            for (int r = 0; r < 4; r++) { cac[mi][ni][r] = 0.f; cbd[mi][ni][r] = 0.f; }

#pragma unroll
    for (int ks = 0; ks < 4; ks++) {
        int k0 = ks * 16;
        int m0 = warp_m * 32 + (lane & 15);
        int kcA = k0 + ((lane >> 4) << 3);
        int nI  = warp_n * 64 + (lane & 7) + ((lane >> 4) << 3);
        int kcB = k0 + (((lane >> 3) & 1) << 3);
        uint32_t a1[2][4], a2[2][4];
#pragma unroll
        for (int mi = 0; mi < 2; mi++) {
            uint32_t ad1 = smem_u32(qrw + (m0 + mi*16)*72 + kcA);
            uint32_t ad2 = smem_u32(qrr + (m0 + mi*16)*72 + kcA);
            asm volatile("ldmatrix.sync.aligned.m8n8.x4.shared.b16 {%0,%1,%2,%3}, [%4];"
                         : "=r"(a1[mi][0]), "=r"(a1[mi][1]), "=r"(a1[mi][2]), "=r"(a1[mi][3])
                         : "r"(ad1));
            asm volatile("ldmatrix.sync.aligned.m8n8.x4.shared.b16 {%0,%1,%2,%3}, [%4];"
                         : "=r"(a2[mi][0]), "=r"(a2[mi][1]), "=r"(a2[mi][2]), "=r"(a2[mi][3])
                         : "r"(ad2));
        }
        uint32_t b1[8][2], b2[8][2];
#pragma unroll
        for (int nt = 0; nt < 4; nt++) {
            uint32_t bd1 = smem_u32(kS  + (nI + nt*16)*72 + kcB);
            uint32_t bd2 = smem_u32(rkS + (nI + nt*16)*72 + kcB);
            asm volatile("ldmatrix.sync.aligned.m8n8.x4.shared.b16 {%0,%1,%2,%3}, [%4];"
                         : "=r"(b1[nt*2][0]), "=r"(b1[nt*2][1]),
                           "=r"(b1[nt*2+1][0]), "=r"(b1[nt*2+1][1])
                         : "r"(bd1));
            asm volatile("ldmatrix.sync.aligned.m8n8.x4.shared.b16 {%0,%1,%2,%3}, [%4];"
                         : "=r"(b2[nt*2][0]), "=r"(b2[nt*2][1]),
                           "=r"(b2[nt*2+1][0]), "=r"(b2[nt*2+1][1])
                         : "r"(bd2));
        }
#pragma unroll
        for (int mi = 0; mi < 2; mi++)
#pragma unroll
            for (int ni = 0; ni < 8; ni++) {
                asm volatile("mma.sync.aligned.m16n8k16.row.col.f32.bf16.bf16.f32 "
                             "{%0,%1,%2,%3}, {%4,%5,%6,%7}, {%8,%9}, {%0,%1,%2,%3};\n"
                             : "+f"(cac[mi][ni][0]), "+f"(cac[mi][ni][1]),
                               "+f"(cac[mi][ni][2]), "+f"(cac[mi][ni][3])
                             : "r"(a1[mi][0]), "r"(a1[mi][1]), "r"(a1[mi][2]), "r"(a1[mi][3]),
                               "r"(b1[ni][0]), "r"(b1[ni][1]));
                asm volatile("mma.sync.aligned.m16n8k16.row.col.f32.bf16.bf16.f32 "
                             "{%0,%1,%2,%3}, {%4,%5,%6,%7}, {%8,%9}, {%0,%1,%2,%3};\n"
                             : "+f"(cbd[mi][ni][0]), "+f"(cbd[mi][ni][1]),
                               "+f"(cbd[mi][ni][2]), "+f"(cbd[mi][ni][3])
                             : "r"(a2[mi][0]), "r"(a2[mi][1]), "r"(a2[mi][2]), "r"(a2[mi][3]),
                               "r"(b2[ni][0]), "r"(b2[ni][1]));
            }
    }
    __syncthreads();

#pragma unroll
    for (int mi = 0; mi < 2; mi++) {
        int row0 = warp_m * 32 + mi * 16 + gid;
#pragma unroll
        for (int ni = 0; ni < 8; ni++) {
            int col = warp_n * 64 + ni * 8 + tig * 2;
#pragma unroll
            for (int half = 0; half < 2; half++) {
                int gm = row0 + half * 8;
                bdS[gm * 132 + col]     = cbd[mi][ni][half*2 + 0];
                bdS[gm * 132 + col + 1] = cbd[mi][ni][half*2 + 1];
            }
        }
    }
    __syncthreads();

#pragma unroll
    for (int mi = 0; mi < 2; mi++) {
#pragma unroll
        for (int half = 0; half < 2; half++) {
            int r = warp_m * 32 + mi * 16 + half * 8 + gid;
            float m = -1e30f;
#pragma unroll
            for (int ni = 0; ni < 8; ni++) {
#pragma unroll
                for (int e = 0; e < 2; e++) {
                    int j = warp_n * 64 + ni * 8 + tig * 2 + e;
                    float sc;
                    if (j > r) sc = NEG_;
                    else {
                        int f = r * SS + j + SS;
                        int qi = f / (SS + 1);
                        int cc = f - qi * (SS + 1);
                        float bdv = (cc > 0) ? bdS[qi * 132 + (cc - 1)] : 0.f;
                        sc = (cac[mi][ni][half*2 + e] + bdv) * SCALE_;
                    }
                    cac[mi][ni][half*2 + e] = sc;
                    m = fmaxf(m, sc);
                }
            }
#pragma unroll
            for (int o = 1; o <= 2; o <<= 1) m = fmaxf(m, __shfl_xor_sync(0xffffffffu, m, o));
            if (tig == 0) rowm[r][warp_n] = m;
        }
    }
    __syncthreads();

#pragma unroll
    for (int mi = 0; mi < 2; mi++) {
#pragma unroll
        for (int half = 0; half < 2; half++) {
            int r = warp_m * 32 + mi * 16 + half * 8 + gid;
            float m = fmaxf(rowm[r][0], rowm[r][1]);
            float s = 0.f;
#pragma unroll
            for (int ni = 0; ni < 8; ni++) {
#pragma unroll
                for (int e = 0; e < 2; e++) {
                    float ev = fexp(cac[mi][ni][half*2 + e] - m);
                    cac[mi][ni][half*2 + e] = ev;
                    s += ev;
                }
            }
#pragma unroll
            for (int o = 1; o <= 2; o <<= 1) s += __shfl_xor_sync(0xffffffffu, s, o);
            if (tig == 0) rowsum[r][warp_n] = s;
        }
    }
    __syncthreads();

#pragma unroll
    for (int mi = 0; mi < 2; mi++) {
#pragma unroll
        for (int half = 0; half < 2; half++) {
            int r = warp_m * 32 + mi * 16 + half * 8 + gid;
            float inv = 1.0f / (rowsum[r][0] + rowsum[r][1]);
#pragma unroll
            for (int ni = 0; ni < 8; ni++) {
                int col = warp_n * 64 + ni * 8 + tig * 2;
                uint32_t pk = ((uint32_t)__bfloat16_as_ushort(
                                  __float2bfloat16_rn(cac[mi][ni][half*2+1] * inv)) << 16)
                            | (uint32_t)__bfloat16_as_ushort(
                                  __float2bfloat16_rn(cac[mi][ni][half*2+0] * inv));
                *reinterpret_cast<uint32_t*>(&PS[r * 136 + col]) = pk;
            }
        }
    }
    __syncthreads();

    float c2[2][4][4];
#pragma unroll
    for (int mi = 0; mi < 2; mi++)
#pragma unroll
        for (int ni = 0; ni < 4; ni++)
#pragma unroll
            for (int r = 0; r < 4; r++) c2[mi][ni][r] = 0.f;

#pragma unroll
    for (int ks = 0; ks < 8; ks++) {
        int k0 = ks * 16;
        uint32_t a[2][4];
#pragma unroll
        for (int mi = 0; mi < 2; mi++) {
            int m = warp_m * 32 + mi * 16 + (lane & 15);
            int kc = k0 + ((lane >> 4) << 3);
            uint32_t addr = smem_u32(PS + m * 136 + kc);
            asm volatile("ldmatrix.sync.aligned.m8n8.x4.shared.b16 {%0,%1,%2,%3}, [%4];"
                         : "=r"(a[mi][0]), "=r"(a[mi][1]), "=r"(a[mi][2]), "=r"(a[mi][3])
                         : "r"(addr));
        }
        uint32_t bb[4][2];
#pragma unroll
        for (int nt = 0; nt < 2; nt++) {
            int kr = k0 + (lane & 15);
            int n = warp_n * 32 + nt * 16 + ((lane >> 4) << 3);
            uint32_t addr = smem_u32(vS + kr * 72 + n);
            asm volatile("ldmatrix.sync.aligned.m8n8.x4.trans.shared.b16 {%0,%1,%2,%3}, [%4];"
                         : "=r"(bb[nt*2][0]), "=r"(bb[nt*2][1]),
                           "=r"(bb[nt*2+1][0]), "=r"(bb[nt*2+1][1])
                         : "r"(addr));
        }
#pragma unroll
        for (int mi = 0; mi < 2; mi++)
#pragma unroll
            for (int ni = 0; ni < 4; ni++) {
                asm volatile("mma.sync.aligned.m16n8k16.row.col.f32.bf16.bf16.f32 "
                             "{%0,%1,%2,%3}, {%4,%5,%6,%7}, {%8,%9}, {%0,%1,%2,%3};\n"
                             : "+f"(c2[mi][ni][0]), "+f"(c2[mi][ni][1]),
                               "+f"(c2[mi][ni][2]), "+f"(c2[mi][ni][3])
                             : "r"(a[mi][0]), "r"(a[mi][1]), "r"(a[mi][2]), "r"(a[mi][3]),
                               "r"(bb[ni][0]), "r"(bb[ni][1]));
            }
    }

    bf16* outBase = vecOut + (size_t)b * DD + (size_t)h * DHH;
#pragma unroll
    for (int mi = 0; mi < 2; mi++) {
        int row0 = warp_m * 32 + mi * 16 + gid;
#pragma unroll
        for (int ni = 0; ni < 4; ni++) {
            int col = warp_n * 32 + ni * 8 + tig * 2;
#pragma unroll
            for (int half = 0; half < 2; half++) {
                int gm = row0 + half * 8;
                uint32_t pk = ((uint32_t)__bfloat16_as_ushort(__float2bfloat16_rn(c2[mi][ni][half*2+1])) << 16)
                            | (uint32_t)__bfloat16_as_ushort(__float2bfloat16_rn(c2[mi][ni][half*2+0]));
                *reinterpret_cast<uint32_t*>(&outBase[(size_t)gm * (BB*DD) + col]) = pk;
            }
        }
    }
}

// ======== fused cross-attention: flash-style; q from two f32 split-K partial slabs ====
#define SMEM_XATT ((3*128*72 + 128*136)*2)
__global__ __launch_bounds__(256, 1)
void fused_cross_attn(const float* __restrict__ qp0, const float* __restrict__ qp1,
                      const bf16* __restrict__ kvall,
                      const float* __restrict__ mask,
                      bf16* __restrict__ vecOut, int layer)
{
    extern __shared__ bf16 dsX[];
    bf16* qS = dsX;
    bf16* kS = dsX + 128*72;
    bf16* vS = dsX + 2*128*72;
    bf16* PS = dsX + 3*128*72;

    __shared__ float rowm[128][2];
    __shared__ float rowsum[128][2];
    __shared__ float maskS[128];

    int z = blockIdx.x;
    int h = z % HH, b = z / HH;
    int tid = threadIdx.x;
    int warp = tid >> 5, lane = tid & 31;
    int warp_m = warp >> 1, warp_n = warp & 1;
    int gid = lane >> 2, tig = lane & 3;
    int row = tid >> 1, koff = (tid & 1) * 32;

    {
        size_t base = (size_t)b*DD + (size_t)h*DHH + (size_t)row*(BB*DD) + koff;
        const float* q0 = qp0 + base;
        const float* q1 = qp1 + base;
#pragma unroll
        for (int j = 0; j < 8; j++) {
            float4 v0 = *reinterpret_cast<const float4*>(q0 + j*4);
            float4 v1 = *reinterpret_cast<const float4*>(q1 + j*4);
            bf16 t[4];
            t[0] = __float2bfloat16_rn(v0.x + v1.x);
            t[1] = __float2bfloat16_rn(v0.y + v1.y);
            t[2] = __float2bfloat16_rn(v0.z + v1.z);
            t[3] = __float2bfloat16_rn(v0.w + v1.w);
            *reinterpret_cast<uint2*>(&qS[row*72 + koff + j*4]) = *reinterpret_cast<uint2*>(t);
        }
    }

    const bf16* kBase = kvall + (size_t)layer*2*DD + (size_t)b*(LL*2*DD) + (size_t)h*DHH;
    const bf16* vBase = kBase + DD;
    const long long kvRow = (long long)BB*LL*2*DD;

    float mstate[2][2], lstate[2][2];
#pragma unroll
    for (int mi = 0; mi < 2; mi++)
#pragma unroll
        for (int half = 0; half < 2; half++) { mstate[mi][half] = -1e30f; lstate[mi][half] = 0.f; }

    float c2[2][4][4];
#pragma unroll
    for (int mi = 0; mi < 2; mi++)
#pragma unroll
        for (int ni = 0; ni < 4; ni++)
#pragma unroll
            for (int r = 0; r < 4; r++) c2[mi][ni][r] = 0.f;

    for (int kc = 0; kc < 4; kc++) {
        {
            const bf16* kg = kBase + (size_t)(kc*128 + row) * kvRow + koff;
            const bf16* vg = vBase + (size_t)(kc*128 + row) * kvRow + koff;
#pragma unroll
            for (int j = 0; j < 4; j++) {
                *reinterpret_cast<uint4*>(&kS[row*72 + koff + j*8]) =
                    *reinterpret_cast<const uint4*>(kg + j*8);
                *reinterpret_cast<uint4*>(&vS[row*72 + koff + j*8]) =
                    *reinterpret_cast<const uint4*>(vg + j*8);
            }
            if (tid < 128) maskS[tid] = mask[b*EE + kc*128 + tid];
        }
        __syncthreads();

        float cs[2][8][4];
#pragma unroll
        for (int mi = 0; mi < 2; mi++)
#pragma unroll
            for (int ni = 0; ni < 8; ni++)
#pragma unroll
                for (int r = 0; r < 4; r++) cs[mi][ni][r] = 0.f;

#pragma unroll
        for (int ks = 0; ks < 4; ks++) {
            int k0 = ks * 16;
            uint32_t a[2][4];
#pragma unroll
            for (int mi = 0; mi < 2; mi++) {
                int m = warp_m * 32 + mi * 16 + (lane & 15);
                int kcc = k0 + ((lane >> 4) << 3);
                uint32_t addr = smem_u32(qS + m*72 + kcc);
                asm volatile("ldmatrix.sync.aligned.m8n8.x4.shared.b16 {%0,%1,%2,%3}, [%4];"
                             : "=r"(a[mi][0]), "=r"(a[mi][1]), "=r"(a[mi][2]), "=r"(a[mi][3])
                             : "r"(addr));
            }
            uint32_t bb[8][2];
#pragma unroll
            for (int nt = 0; nt < 4; nt++) {
                int n = warp_n * 64 + nt * 16 + (lane & 7) + ((lane >> 4) << 3);
                int kcc = k0 + (((lane >> 3) & 1) << 3);
                uint32_t addr = smem_u32(kS + n*72 + kcc);
                asm volatile("ldmatrix.sync.aligned.m8n8.x4.shared.b16 {%0,%1,%2,%3}, [%4];"
                             : "=r"(bb[nt*2][0]), "=r"(bb[nt*2][1]),
                               "=r"(bb[nt*2+1][0]), "=r"(bb[nt*2+1][1])
                             : "r"(addr));
            }
#pragma unroll
            for (int mi = 0; mi < 2; mi++)
#pragma unroll
                for (int ni = 0; ni < 8; ni++) {
                    asm volatile("mma.sync.aligned.m16n8k16.row.col.f32.bf16.bf16.f32 "
                                 "{%0,%1,%2,%3}, {%4,%5,%6,%7}, {%8,%9}, {%0,%1,%2,%3};\n"
                                 : "+f"(cs[mi][ni][0]), "+f"(cs[mi][ni][1]),
                                   "+f"(cs[mi][ni][2]), "+f"(cs[mi][ni][3])
                                 : "r"(a[mi][0]), "r"(a[mi][1]), "r"(a[mi][2]), "r"(a[mi][3]),
                                   "r"(bb[ni][0]), "r"(bb[ni][1]));
                }
        }

#pragma unroll
        for (int mi = 0; mi < 2; mi++) {
#pragma unroll
            for (int half = 0; half < 2; half++) {
                int r = warp_m * 32 + mi * 16 + half * 8 + gid;
                float m = -1e30f;
#pragma unroll
                for (int ni = 0; ni < 8; ni++) {
#pragma unroll
                    for (int e = 0; e < 2; e++) {
                        int j = warp_n * 64 + ni * 8 + tig * 2 + e;
                        float sc = cs[mi][ni][half*2 + e] * SCALE_
                                 + (1.0f - maskS[j]) * NEG_;
                        cs[mi][ni][half*2 + e] = sc;
                        m = fmaxf(m, sc);
                    }
                }
#pragma unroll
                for (int o = 1; o <= 2; o <<= 1) m = fmaxf(m, __shfl_xor_sync(0xffffffffu, m, o));
                if (tig == 0) rowm[r][warp_n] = m;
            }
        }
        __syncthreads();

        float scaleF[2][2], mnew[2][2];
#pragma unroll
        for (int mi = 0; mi < 2; mi++) {
#pragma unroll
            for (int half = 0; half < 2; half++) {
                int r = warp_m * 32 + mi * 16 + half * 8 + gid;
                float mc = fmaxf(rowm[r][0], rowm[r][1]);
                float mn = fmaxf(mstate[mi][half], mc);
                scaleF[mi][half] = fexp(mstate[mi][half] - mn);
                mnew[mi][half] = mn;
                float s = 0.f;
#pragma unroll
                for (int ni = 0; ni < 8; ni++) {
#pragma unroll
                    for (int e = 0; e < 2; e++) {
                        float ev = fexp(cs[mi][ni][half*2 + e] - mn);
                        cs[mi][ni][half*2 + e] = ev;
                        s += ev;
                    }
                }
#pragma unroll
                for (int o = 1; o <= 2; o <<= 1) s += __shfl_xor_sync(0xffffffffu, s, o);
                if (tig == 0) rowsum[r][warp_n] = s;
            }
        }
        __syncthreads();

#pragma unroll
        for (int mi = 0; mi < 2; mi++) {
#pragma unroll
            for (int half = 0; half < 2; half++) {
                int r = warp_m * 32 + mi * 16 + half * 8 + gid;
                float sc = scaleF[mi][half];
                lstate[mi][half] = lstate[mi][half] * sc + rowsum[r][0] + rowsum[r][1];
                mstate[mi][half] = mnew[mi][half];
#pragma unroll
                for (int ni = 0; ni < 4; ni++) {
                    c2[mi][ni][half*2 + 0] *= sc;
                    c2[mi][ni][half*2 + 1] *= sc;
                }
#pragma unroll
                for (int ni = 0; ni < 8; ni++) {
                    int col = warp_n * 64 + ni * 8 + tig * 2;
                    uint32_t pk = ((uint32_t)__bfloat16_as_ushort(
                                      __float2bfloat16_rn(cs[mi][ni][half*2+1])) << 16)
                                | (uint32_t)__bfloat16_as_ushort(
                                      __float2bfloat16_rn(cs[mi][ni][half*2+0]));
                    *reinterpret_cast<uint32_t*>(&PS[r * 136 + col]) = pk;
                }
            }
        }
        __syncthreads();

#pragma unroll
        for (int ks = 0; ks < 8; ks++) {
            int k0 = ks * 16;
            uint32_t a[2][4];
#pragma unroll
            for (int mi = 0; mi < 2; mi++) {
                int m = warp_m * 32 + mi * 16 + (lane & 15);
                int kcc = k0 + ((lane >> 4) << 3);
                uint32_t addr = smem_u32(PS + m * 136 + kcc);
                asm volatile("ldmatrix.sync.aligned.m8n8.x4.shared.b16 {%0,%1,%2,%3}, [%4];"
                             : "=r"(a[mi][0]), "=r"(a[mi][1]), "=r"(a[mi][2]), "=r"(a[mi][3])
                             : "r"(addr));
            }
            uint32_t bb[4][2];
#pragma unroll
            for (int nt = 0; nt < 2; nt++) {
                int kr = k0 + (lane & 15);
                int n = warp_n * 32 + nt * 16 + ((lane >> 4) << 3);
                uint32_t addr = smem_u32(vS + kr * 72 + n);
                asm volatile("ldmatrix.sync.aligned.m8n8.x4.trans.shared.b16 {%0,%1,%2,%3}, [%4];"
                             : "=r"(bb[nt*2][0]), "=r"(bb[nt*2][1]),
                               "=r"(bb[nt*2+1][0]), "=r"(bb[nt*2+1][1])
                             : "r"(addr));
            }
#pragma unroll
            for (int mi = 0; mi < 2; mi++)
#pragma unroll
                for (int ni = 0; ni < 4; ni++) {
                    asm volatile("mma.sync.aligned.m16n8k16.row.col.f32.bf16.bf16.f32 "
                                 "{%0,%1,%2,%3}, {%4,%5,%6,%7}, {%8,%9}, {%0,%1,%2,%3};\n"
                                 : "+f"(c2[mi][ni][0]), "+f"(c2[mi][ni][1]),
                                   "+f"(c2[mi][ni][2]), "+f"(c2[mi][ni][3])
                                 : "r"(a[mi][0]), "r"(a[mi][1]), "r"(a[mi][2]), "r"(a[mi][3]),
                                   "r"(bb[ni][0]), "r"(bb[ni][1]));
                }
        }
        __syncthreads();
    }

    bf16* outBase = vecOut + (size_t)b * DD + (size_t)h * DHH;
#pragma unroll
    for (int mi = 0; mi < 2; mi++) {
        int row0 = warp_m * 32 + mi * 16 + gid;
#pragma unroll
        for (int ni = 0; ni < 4; ni++) {
            int col = warp_n * 32 + ni * 8 + tig * 2;
#pragma unroll
            for (int half = 0; half < 2; half++) {
                int gm = row0 + half * 8;
                float inv = 1.0f / lstate[mi][half];
                uint32_t pk = ((uint32_t)__bfloat16_as_ushort(
                                  __float2bfloat16_rn(c2[mi][ni][half*2+1] * inv)) << 16)
                            | (uint32_t)__bfloat16_as_ushort(
                                  __float2bfloat16_rn(c2[mi][ni][half*2+0] * inv));
                *reinterpret_cast<uint32_t*>(&outBase[(size_t)gm * (BB*DD) + col]) = pk;
            }
        }
    }
}

// ======== vocab-logits GEMM with fused stats + tgt extract (3-stage) ========
__global__ __launch_bounds__(256, 2)
void sgemm_vocab(const bf16* __restrict__ A, const bf16* __restrict__ Bw,
                 const int* __restrict__ decode_target,
                 float* __restrict__ pm, float* __restrict__ ps,
                 float* __restrict__ tgtlog,
                 int K, int lda, int ldb)
{
    extern __shared__ bf16 ds[];
    bf16* AsB = ds;
    bf16* BsB = ds + 3*128*40;

    int tid = threadIdx.x;
    int warp = tid >> 5, lane = tid & 31;
    int warp_m = warp >> 1;
    int warp_n = warp & 1;
    int rowA0 = blockIdx.y * 128;
    int colB0 = blockIdx.x * 128;

    int ldrow = tid >> 1;
    int ldkoff = (tid & 1) * 16;

    float c[2][8][4];
#pragma unroll
    for (int mi = 0; mi < 2; mi++)
#pragma unroll
        for (int ni = 0; ni < 8; ni++)
#pragma unroll
            for (int r = 0; r < 4; r++) c[mi][ni][r] = 0.f;

    const bf16* Agp = &A[(size_t)(rowA0 + ldrow) * lda + ldkoff];
    const bf16* Bgp = &Bw[(size_t)(colB0 + ldrow) * ldb + ldkoff];

    int nk = K >> 5;
#pragma unroll
    for (int s = 0; s < 2; s++) {
        bf16* as = AsB + s * (128*40);
        bf16* bs = BsB + s * (128*40);
        uint32_t sa = smem_u32(as + ldrow * 40 + ldkoff);
        uint32_t sb = smem_u32(bs + ldrow * 40 + ldkoff);
        const bf16* ag = Agp + s * 32;
        const bf16* bg = Bgp + s * 32;
        asm volatile("cp.async.ca.shared.global [%0], [%1], 16;\n"
                     "cp.async.ca.shared.global [%2], [%3], 16;\n"
                     "cp.async.ca.shared.global [%4], [%5], 16;\n"
                     "cp.async.ca.shared.global [%6], [%7], 16;\n"
                     :: "r"(sa), "l"(ag), "r"(sa + 16), "l"(ag + 8),
                        "r"(sb), "l"(bg), "r"(sb + 16), "l"(bg + 8));
        asm volatile("cp.async.commit_group;");
    }

    for (int kt = 0; kt < nk; kt++) {
        asm volatile("cp.async.wait_group 1;");
        __syncthreads();
        int pf = kt + 2;
        if (pf < nk) {
            int sbuf = pf - (pf / 3) * 3;
            bf16* as = AsB + sbuf * (128*40);
            bf16* bs = BsB + sbuf * (128*40);
            uint32_t sa = smem_u32(as + ldrow * 40 + ldkoff);
            uint32_t sb = smem_u32(bs + ldrow * 40 + ldkoff);
            const bf16* ag = Agp + pf * 32;
            const bf16* bg = Bgp + pf * 32;
            asm volatile("cp.async.ca.shared.global [%0], [%1], 16;\n"
                         "cp.async.ca.shared.global [%2], [%3], 16;\n"
                         "cp.async.ca.shared.global [%4], [%5], 16;\n"
                         "cp.async.ca.shared.global [%6], [%7], 16;\n"
                         :: "r"(sa), "l"(ag), "r"(sa + 16), "l"(ag + 8),
                            "r"(sb), "l"(bg), "r"(sb + 16), "l"(bg + 8));
        }
        asm volatile("cp.async.commit_group;");

        int cbuf = kt - (kt / 3) * 3;
        bf16* as = AsB + cbuf * (128*40);
        bf16* bs = BsB + cbuf * (128*40);
#pragma unroll
        for (int ks = 0; ks < 2; ks++) {
            int k0 = ks * 16;
            uint32_t a[2][4];
#pragma unroll
            for (int mi = 0; mi < 2; mi++) {
                int m = warp_m * 32 + mi * 16 + (lane & 15);
                int kc = k0 + ((lane >> 4) << 3);
                uint32_t addr = smem_u32(as + m * 40 + kc);
                asm volatile("ldmatrix.sync.aligned.m8n8.x4.shared.b16 {%0,%1,%2,%3}, [%4];"
                             : "=r"(a[mi][0]), "=r"(a[mi][1]), "=r"(a[mi][2]), "=r"(a[mi][3])
                             : "r"(addr));
            }
            uint32_t b[8][2];
#pragma unroll
            for (int nt = 0; nt < 4; nt++) {
                int n = warp_n * 64 + nt * 16 + (lane & 7) + ((lane >> 4) << 3);
                int kc = k0 + (((lane >> 3) & 1) << 3);
                uint32_t addr = smem_u32(bs + n * 40 + kc);
                asm volatile("ldmatrix.sync.aligned.m8n8.x4.shared.b16 {%0,%1,%2,%3}, [%4];"
                             : "=r"(b[nt*2][0]), "=r"(b[nt*2][1]),
                               "=r"(b[nt*2+1][0]), "=r"(b[nt*2+1][1])
                             : "r"(addr));
            }
#pragma unroll
            for (int mi = 0; mi < 2; mi++)
#pragma unroll
                for (int ni = 0; ni < 8; ni++) {
                    asm volatile(
                        "mma.sync.aligned.m16n8k16.row.col.f32.bf16.bf16.f32 "
                        "{%0,%1,%2,%3}, {%4,%5,%6,%7}, {%8,%9}, {%0,%1,%2,%3};\n"
                        : "+f"(c[mi][ni][0]), "+f"(c[mi][ni][1]),
                          "+f"(c[mi][ni][2]), "+f"(c[mi][ni][3])
                        : "r"(a[mi][0]), "r"(a[mi][1]), "r"(a[mi][2]), "r"(a[mi][3]),
                          "r"(b[ni][0]), "r"(b[ni][1]));
                }
        }
    }

    __shared__ int   stgt[128];
    __shared__ float smx[128][2];
    __shared__ float ssx[128][2];
    if (tid < 128) {
        int grow = rowA0 + tid;
        stgt[tid] = decode_target[(grow & (BB-1)) * SS + (grow >> 3)];
    }
    __syncthreads();

    int gid = lane >> 2, tig = lane & 3;
#pragma unroll
    for (int mi = 0; mi < 2; mi++) {
#pragma unroll
        for (int half = 0; half < 2; half++) {
            int rl = warp_m * 32 + mi * 16 + half * 8 + gid;
            int tgt_c = stgt[rl] - colB0;
            float m = -1e30f, s = 0.f;
#pragma unroll
            for (int ni = 0; ni < 8; ni++) {
#pragma unroll
                for (int e = 0; e < 2; e++) {
                    float v = c[mi][ni][half * 2 + e];
                    int coll = warp_n * 64 + ni * 8 + tig * 2 + e;
                    if (coll == tgt_c) tgtlog[rowA0 + rl] = v;
                    if (v <= m) s += fexp(v - m);
                    else { s = s * fexp(m - v) + 1.0f; m = v; }
                }
            }
#pragma unroll
            for (int o = 1; o <= 2; o <<= 1) {
                float mo = __shfl_xor_sync(0xffffffffu, m, o);
                float so = __shfl_xor_sync(0xffffffffu, s, o);
                float M = fmaxf(m, mo);
                s = s * fexp(m - M) + so * fexp(mo - M);
                m = M;
            }
            if (tig == 0) { smx[rl][warp_n] = m; ssx[rl][warp_n] = s; }
        }
    }
    __syncthreads();
    if (tid < 128) {
        float m0 = smx[tid][0], s0 = ssx[tid][0];
        float m1 = smx[tid][1], s1 = ssx[tid][1];
        float M = fmaxf(m0, m1);
        float S = s0 * fexp(m0 - M) + s1 * fexp(m1 - M);
        pm[(size_t)(rowA0 + tid) * 256 + blockIdx.x] = M;
        ps[(size_t)(rowA0 + tid) * 256 + blockIdx.x] = S;
    }
}

__global__ void stats_final(const float* __restrict__ pm, const float* __restrict__ ps,
                            float* __restrict__ rmax, float* __restrict__ rsum)
{
    int t = blockIdx.x;
    int lane = threadIdx.x;
    float m = -1e30f, s = 0.f;
    for (int i = lane; i < NTILE; i += 32) {
        float mi = pm[(size_t)t * 256 + i];
        float si = ps[(size_t)t * 256 + i];
        float M = fmaxf(m, mi);
        s = s * fexp(m - M) + si * fexp(mi - M);
        m = M;
    }
#pragma unroll
    for (int o = 16; o > 0; o >>= 1) {
        float mo = __shfl_xor_sync(0xffffffffu, m, o);
        float so = __shfl_xor_sync(0xffffffffu, s, o);
        float M = fmaxf(m, mo);
        s = s * fexp(m - M) + so * fexp(mo - M);
        m = M;
    }
    if (lane == 0) { rmax[t] = m; rsum[t] = s; }
}

// ---------------- misc small kernels --------------------------------------------------
__global__ void pos_emb_kernel(float* __restrict__ r, bf16* __restrict__ rb)
{
    int i = blockIdx.x;
    float pos = (float)(SS - 1 - i);
    const float LOG1E4 = 9.210340371976184f;
    for (int d = threadIdx.x; d < DD; d += 256) {
        int j = (d < DD/2) ? d : d - DD/2;
        float invf = expf(-((float)j / (DD/2)) * LOG1E4);
        float a = pos * invf;
        float v = (d < DD/2) ? sinf(a) : cosf(a);
        r[i * DD + d] = v;
        rb[i * DD + d] = __float2bfloat16_rn(v);
    }
}

__global__ void embed_kernel(const int* __restrict__ dec, const float* __restrict__ emb,
                             float* __restrict__ core, bf16* __restrict__ coreb)
{
    int t = blockIdx.x;
    int b = t & (BB-1), s = t >> 3;
    int id = dec[b * SS + s];
    const float* src = emb + (size_t)id * DD;
    for (int d = threadIdx.x; d < DD; d += 256) {
        float v = src[d];
        core[(size_t)t * DD + d] = v;
        coreb[(size_t)t * DD + d] = __float2bfloat16_rn(v);
    }
}

__global__ void transpose_enc(const float* __restrict__ enc, float* __restrict__ enct,
                              bf16* __restrict__ enctb)
{
    int t = blockIdx.x;
    int b = t & (BB-1), e = t >> 3;
    const float* src = enc + ((size_t)b * EE + e) * DD;
    for (int d = threadIdx.x; d < DD; d += 256) {
        float v = src[d];
        enct[(size_t)t * DD + d] = v;
        enctb[(size_t)t * DD + d] = __float2bfloat16_rn(v);
    }
}

__device__ __forceinline__ float warp_max(float v)
{
#pragma unroll
    for (int o = 16; o > 0; o >>= 1) v = fmaxf(v, __shfl_xor_sync(0xffffffffu, v, o));
    return v;
}
__device__ __forceinline__ float warp_sum(float v)
{
#pragma unroll
    for (int o = 16; o > 0; o >>= 1) v += __shfl_xor_sync(0xffffffffu, v, o);
    return v;
}

__global__ void softmax_il(float* __restrict__ IL, const float* __restrict__ mask)
{
    int t = blockIdx.x;
    int b = t & (BB - 1);
    int k = threadIdx.x;
    int wid = k >> 5, lane = k & 31;
    float v = IL[(size_t)t * EE + k] + (1.0f - mask[b * EE + k]) * NEG_;
    __shared__ float red[16];
    float m = warp_max(v);
    if (lane == 0) red[wid] = m;
    __syncthreads();
    m = red[0];
#pragma unroll
    for (int w = 1; w < 16; w++) m = fmaxf(m, red[w]);
    float e = fexp(v - m);
    __shared__ float red2[16];
    float sum = warp_sum(e);
    if (lane == 0) red2[wid] = sum;
    __syncthreads();
    sum = red2[0];
#pragma unroll
    for (int w = 1; w < 16; w++) sum += red2[w];
    IL[(size_t)t * EE + k] = e / sum;
}

__global__ void add_ln(const float* __restrict__ resid, const float* __restrict__ parts,
                       int nparts,
                       float* __restrict__ out, bf16* __restrict__ outb,
                       const float* __restrict__ g, const float* __restrict__ bta)
{
    int t = blockIdx.x;
    int tid = threadIdx.x;
    __shared__ float zb[DD];
    __shared__ float red[256];
    float s = 0.f;
#pragma unroll
    for (int u = 0; u < 4; u++) {
        int d = tid + u * 256;
        float z = resid[(size_t)t * DD + d];
        for (int p = 0; p < nparts; p++)
            z += parts[(size_t)p * TT * DD + (size_t)t * DD + d];
        zb[d] = z; s += z;
    }
    red[tid] = s; __syncthreads();
    for (int st = 128; st > 0; st >>= 1) { if (tid < st) red[tid] += red[tid + st]; __syncthreads(); }
    float mean = red[0] * (1.0f / DD); __syncthreads();
    float v = 0.f;
#pragma unroll
    for (int u = 0; u < 4; u++) {
        int d = tid + u * 256;
        float dz = zb[d] - mean; v += dz * dz;
    }
    red[tid] = v; __syncthreads();
    for (int st = 128; st > 0; st >>= 1) { if (tid < st) red[tid] += red[tid + st]; __syncthreads(); }
    float inv = rsqrtf(red[0] * (1.0f / DD) + 1e-5f);
#pragma unroll
    for (int u = 0; u < 4; u++) {
        int d = tid + u * 256;
        float o = (zb[d] - mean) * inv * g[d] + bta[d];
        out[(size_t)t * DD + d] = o;
        if (outb) outb[(size_t)t * DD + d] = __float2bfloat16_rn(o);
    }
}

__global__ void mode_kernel(const float* __restrict__ core, const float* __restrict__ mw,
                            const float* __restrict__ mb, float* __restrict__ msig)
{
    int t = blockIdx.x;
    int tid = threadIdx.x;
    int wid = tid >> 5, lane = tid & 31;
    float s = 0.f;
    for (int d = tid; d < DD; d += 256) s += core[(size_t)t * DD + d] * mw[d];
    s = warp_sum(s);
    __shared__ float red[8];
    if (lane == 0) red[wid] = s;
    __syncthreads();
    if (tid == 0) {
        float tot = red[0];
#pragma unroll
        for (int w = 1; w < 8; w++) tot += red[w];
        msig[t] = 1.0f / (1.0f + expf(-(tot + mb[0])));
    }
}

__global__ void zero_loss()
{
    g_lossacc[0] = 0.f;
    g_lossacc[1] = 0.f;
}

__global__ void loss_partial(const float* __restrict__ tgtlog, const float* __restrict__ rmax,
                             const float* __restrict__ rsum, const float* __restrict__ msig,
                             const float* __restrict__ IL, const int* __restrict__ input_ids,
                             const int* __restrict__ decode_target)
{
    int tid = threadIdx.x;
    int wid = tid >> 5, lane = tid & 31;
    int t = blockIdx.x * 8 + wid;
    float acc = 0.f, cnt = 0.f;
    int b = t & (BB - 1), sIdx = t >> 3;
    int tgt = decode_target[b * SS + sIdx];
    if (tgt != 0) {
        const int* ids = input_ids + b * EE;
        const float* il = IL + (size_t)t * EE;
        float cp = 0.f;
        for (int j = lane; j < EE; j += 32)
            if (ids[j] == tgt) cp += il[j];
        cp = warp_sum(cp);
        if (lane == 0) {
            float mg = msig[t];
            float p = expf(tgtlog[t] - rmax[t]) / rsum[t] * mg;
            p += (1.0f - mg) * cp;
            acc = -logf(p + 1e-6f);
            cnt = 1.0f;
        }
    }
    __shared__ float sa[8], sc[8];
    if (lane == 0) { sa[wid] = acc; sc[wid] = cnt; }
    __syncthreads();
    if (tid == 0) {
        float A = 0.f, C = 0.f;
#pragma unroll
        for (int w = 0; w < 8; w++) { A += sa[w]; C += sc[w]; }
        atomicAdd(&g_lossacc[0], A);
        atomicAdd(&g_lossacc[1], C);
    }
}

__global__ void loss_final(float* __restrict__ out)
{
    out[threadIdx.x] = g_lossacc[0] / g_lossacc[1];
}

// ---------------- host orchestration --------------------------------------------------
static void* symaddr(const void* sym)
{
    void* p = nullptr;
    cudaGetSymbolAddress(&p, sym);
    return p;
}

static void cvtS(const float* src, bf16* dst, size_t n, cudaStream_t st)
{
    int blocks = (int)((n / 4 + 255) / 256);
    cvt_bf16<<<blocks, 256, 0, st>>>(src, dst, (int)n);
}

extern "C" void kernel_launch(void* const* d_in, const int* in_sizes, int n_in,
                              void* d_out, int out_size)
{
    const int*   input_ids     = (const int*)d_in[0];
    const float* encoder_rep   = (const float*)d_in[1];
    const float* input_mask    = (const float*)d_in[2];
    const int*   decode_input  = (const int*)d_in[3];
    const int*   decode_target = (const int*)d_in[4];
    const float* word_emb      = (const float*)d_in[5];
    const float* qkv_w         = (const float*)d_in[6];
    const float* r_w           = (const float*)d_in[7];
    const float* o_w           = (const float*)d_in[8];
    const float* kv_w          = (const float*)d_in[9];
    const float* q_w           = (const float*)d_in[10];
    const float* io_w          = (const float*)d_in[11];
    const float* rr_bias       = (const float*)d_in[12];
    const float* rw_bias       = (const float*)d_in[13];
    const float* ln1_g         = (const float*)d_in[14];
    const float* ln1_b         = (const float*)d_in[15];
    const float* ln2_g         = (const float*)d_in[16];
    const float* ln2_b         = (const float*)d_in[17];
    const float* ffn_w1        = (const float*)d_in[18];
    const float* ffn_b1        = (const float*)d_in[19];
    const float* ffn_w2        = (const float*)d_in[20];
    const float* ffn_b2        = (const float*)d_in[21];
    const float* ln3_g         = (const float*)d_in[22];
    const float* ln3_b         = (const float*)d_in[23];
    const float* out_w         = (const float*)d_in[24];
    const float* out_b         = (const float*)d_in[25];
    const float* copy_w        = (const float*)d_in[26];
    const float* copy_b        = (const float*)d_in[27];
    const float* mode_w        = (const float*)d_in[28];
    const float* mode_b        = (const float*)d_in[29];

    float* p_core  = (float*)symaddr(g_core);
    float* p_r     = (float*)symaddr(g_r);
    float* p_x     = (float*)symaddr(g_x);
    float* p_y     = (float*)symaddr(g_y);
    float* p_tmpk  = (float*)symaddr(g_tmpk);
    float* p_enct  = (float*)symaddr(g_enct);
    float* p_IL    = (float*)symaddr(g_IL);
    float* p_pm    = (float*)symaddr(g_pm);
    float* p_ps    = (float*)symaddr(g_ps);
    float* p_tgt   = (float*)symaddr(g_tgtlog);
    float* p_rmax  = (float*)symaddr(g_rmax);
    float* p_rsum  = (float*)symaddr(g_rsum);
    float* p_msig  = (float*)symaddr(g_msig);

    bf16* pb_core = (bf16*)symaddr(b_core);
    bf16* pb_r    = (bf16*)symaddr(b_r);
    bf16* pb_rkall= (bf16*)symaddr(b_rkall);
    bf16* pb_x    = (bf16*)symaddr(b_x);
    bf16* pb_y    = (bf16*)symaddr(b_y);
    bf16* pb_vec  = (bf16*)symaddr(b_vec);
    bf16* pb_enct = (bf16*)symaddr(b_enct);
    bf16* pb_h    = (bf16*)symaddr(b_h);
    bf16* pb_outb = (bf16*)symaddr(b_outb);
    bf16* pb_cpyh = (bf16*)symaddr(b_copyhb);
    bf16* pb_heads= (bf16*)symaddr(b_heads);
    bf16* pb_kvall= (bf16*)symaddr(b_kvall);

    bf16* pw_qkv = (bf16*)symaddr(w_qkv);
    bf16* pw_r   = (bf16*)symaddr(w_r);
    bf16* pw_o   = (bf16*)symaddr(w_o);
    bf16* pw_kv  = (bf16*)symaddr(w_kv);
    bf16* pw_q   = (bf16*)symaddr(w_q);
    bf16* pw_io  = (bf16*)symaddr(w_io);
    bf16* pw_f1  = (bf16*)symaddr(w_f1);
    bf16* pw_f2  = (bf16*)symaddr(w_f2);
    bf16* pw_emb = (bf16*)symaddr(w_emb);
    bf16* pw_out = (bf16*)symaddr(w_out);
    bf16* pw_cp  = (bf16*)symaddr(w_copy);

    cudaFuncSetAttribute(sgemm_bf, cudaFuncAttributeMaxDynamicSharedMemorySize, SMEMSZ);
    cudaFuncSetAttribute(sgemm_vocab, cudaFuncAttributeMaxDynamicSharedMemorySize, SMEMSZ);
    cudaFuncSetAttribute(fused_self_attn, cudaFuncAttributeMaxDynamicSharedMemorySize, SMEM_ATT);
    cudaFuncSetAttribute(fused_cross_attn, cudaFuncAttributeMaxDynamicSharedMemorySize, SMEM_XATT);

    static cudaStream_t s2 = nullptr, s3 = nullptr;
    static cudaEvent_t evFork = nullptr, evJoin = nullptr, evTail = nullptr, evTail2 = nullptr,
                       evKV = nullptr;
    if (!s2) {
        cudaStreamCreateWithFlags(&s2, cudaStreamNonBlocking);
        cudaStreamCreateWithFlags(&s3, cudaStreamNonBlocking);
        cudaEventCreateWithFlags(&evFork, cudaEventDisableTiming);
        cudaEventCreateWithFlags(&evJoin, cudaEventDisableTiming);
        cudaEventCreateWithFlags(&evTail, cudaEventDisableTiming);
        cudaEventCreateWithFlags(&evTail2, cudaEventDisableTiming);
        cudaEventCreateWithFlags(&evKV, cudaEventDisableTiming);
    }

    // early weights on main stream (needed by layer-0 self-attn path)
    cvtS(r_w,    pw_r,   (size_t)LL*DD*DD, 0);
    cvtS(qkv_w,  pw_qkv, (size_t)LL*3*DD*DD, 0);

    // fork s2: late weights (needed from o-projection onward)
    cudaEventRecord(evFork, 0);
    cudaStreamWaitEvent(s2, evFork, 0);
    cvtS(o_w,    pw_o,   (size_t)LL*DD*DD, s2);
    cvtS(q_w,    pw_q,   (size_t)LL*DD*DD, s2);
    cvtS(io_w,   pw_io,  (size_t)LL*DD*DD, s2);
    cvtS(ffn_w1, pw_f1,  (size_t)LL*FF_*DD, s2);
    cvtS(ffn_w2, pw_f2,  (size_t)LL*DD*FF_, s2);
    cvtS(word_emb, pw_emb, (size_t)VV*DD, s2);
    cvtS(out_w,  pw_out, (size_t)DD*DD, s2);
    cvtS(copy_w, pw_cp,  (size_t)DD*DD, s2);
    cudaEventRecord(evJoin, s2);

    // fork s3: KV chain (cvt -> transpose -> hoisted KV GEMM), overlaps layer-0 self-attn
    cudaStreamWaitEvent(s3, evFork, 0);
    cvtS(kv_w, pw_kv, (size_t)LL*2*DD*DD, s3);
    transpose_enc<<<TE, 256, 0, s3>>>(encoder_rep, p_enct, pb_enct);
    sgemm_bf<<<dim3(LL*2*DD/128, TE/128), 256, SMEMSZ, s3>>>(pb_enct, pw_kv, nullptr, pb_kvall,
        nullptr, DD, DD, DD, LL*2*DD, 0, 1, 0, 0, 0, 0);
    cudaEventRecord(evKV, s3);

    pos_emb_kernel<<<SS, 256>>>(p_r, pb_r);
    embed_kernel<<<TT, 256>>>(decode_input, word_emb, p_core, pb_core);

    sgemm_bf<<<dim3(LL*DD/128, SS/128), 256, SMEMSZ>>>(pb_r, pw_r, nullptr, pb_rkall,
        nullptr, DD, DD, DD, LL*DD, 0, 1, 0, 0, 0, 0);

    bool joined = false, kvJoined = false;
    for (int l = 0; l < LL; l++) {
        sgemm_bf<<<dim3(3*DD/128, TT/128), 256, SMEMSZ>>>(pb_core, pw_qkv + (size_t)l*3*DD*DD,
            nullptr, pb_heads, nullptr, DD, DD, DD, 3*DD, 0, 1, 0, 0, 0, 0);
        fused_self_attn<<<BB*HH, 256, SMEM_ATT>>>(pb_heads, pb_rkall, pb_vec,
            rw_bias + (size_t)l*HH*DHH, rr_bias + (size_t)l*HH*DHH, l);
        if (!joined) { cudaStreamWaitEvent(0, evJoin, 0); joined = true; }
        sgemm_bf<<<dim3(DD/128, TT/128, 2), 256, SMEMSZ>>>(pb_vec, pw_o + (size_t)l*DD*DD,
            p_tmpk, nullptr, nullptr, DD, DD, DD, DD, 0, 2, (long long)TT*DD, 0, 0, 0);
        add_ln<<<TT, 256>>>(p_core, p_tmpk, 2, p_x, pb_x, ln1_g + l*DD, ln1_b + l*DD);

        // cross attention
        sgemm_bf<<<dim3(DD/128, TT/128, 2), 256, SMEMSZ>>>(pb_x, pw_q + (size_t)l*DD*DD,
            p_tmpk, nullptr, nullptr, DD, DD, DD, DD, 0, 2, (long long)TT*DD, 0, 0, 0);
        if (!kvJoined) { cudaStreamWaitEvent(0, evKV, 0); kvJoined = true; }
        fused_cross_attn<<<BB*HH, 256, SMEM_XATT>>>(p_tmpk, p_tmpk + (size_t)TT*DD,
            pb_kvall, input_mask, pb_vec, l);
        sgemm_bf<<<dim3(DD/128, TT/128, 2), 256, SMEMSZ>>>(pb_vec, pw_io + (size_t)l*DD*DD,
            p_tmpk, nullptr, nullptr, DD, DD, DD, DD, 0, 2, (long long)TT*DD, 0, 0, 0);
        add_ln<<<TT, 256>>>(p_x, p_tmpk, 2, p_y, pb_y, ln2_g + l*DD, ln2_b + l*DD);

        // FFN
        sgemm_bf<<<dim3(FF_/128, TT/128), 256, SMEMSZ>>>(pb_y, pw_f1 + (size_t)l*FF_*DD,
            nullptr, pb_h, ffn_b1 + (size_t)l*FF_, DD, DD, DD, FF_, 1, 1, 0, 0, 0, 0);
        sgemm_bf<<<dim3(DD/128, TT/128, 4), 256, SMEMSZ>>>(pb_h, pw_f2 + (size_t)l*DD*FF_,
            p_tmpk, nullptr, ffn_b2 + (size_t)l*DD, FF_, FF_, FF_, DD, 0, 4, (long long)TT*DD, 0, 0, 0);
        add_ln<<<TT, 256>>>(p_y, p_tmpk, 4, p_core, pb_core, ln3_g + l*DD, ln3_b + l*DD);
    }

    // ---- tail: two independent chains overlapped ----
    cudaEventRecord(evTail, 0);
    cudaStreamWaitEvent(s2, evTail, 0);
    sgemm_bf<<<dim3(DD/128, TT/128), 256, SMEMSZ, s2>>>(pb_core, pw_cp, nullptr, pb_cpyh, copy_b,
        DD, DD, DD, DD, 0, 1, 0, 0, 0, 0);
    sgemm_bf<<<dim3(EE/128, SS/128, BB), 256, SMEMSZ, s2>>>(pb_cpyh, pb_enct, p_IL, nullptr,
        nullptr, DD, BB*DD, BB*DD, BB*EE, 0, 1, 0,
        (long long)DD, (long long)DD, (long long)EE);
    softmax_il<<<TT, 512, 0, s2>>>(p_IL, input_mask);
    mode_kernel<<<TT, 256, 0, s2>>>(p_core, mode_w, mode_b, p_msig);
    cudaEventRecord(evTail2, s2);

    sgemm_bf<<<dim3(DD/128, TT/128), 256, SMEMSZ>>>(pb_core, pw_out, nullptr, pb_outb, out_b,
        DD, DD, DD, DD, 0, 1, 0, 0, 0, 0);
    sgemm_vocab<<<dim3(NTILE, TT/128), 256, SMEMSZ>>>(pb_outb, pw_emb, decode_target,
        p_pm, p_ps, p_tgt, DD, DD, DD);
    stats_final<<<TT, 32>>>(p_pm, p_ps, p_rmax, p_rsum);
    zero_loss<<<1, 1>>>();

    cudaStreamWaitEvent(0, evTail2, 0);
    loss_partial<<<TT/8, 256>>>(p_tgt, p_rmax, p_rsum, p_msig, p_IL, input_ids, decode_target);
    loss_final<<<1, BB>>>((float*)d_out);
}